// round 11
// baseline (speedup 1.0000x reference)
#include <cuda_runtime.h>
#include <cuda_bf16.h>
#include <cuda_fp16.h>
#include <cstdint>

// Problem constants (fixed shapes)
#define V_N 50000
#define E_N 800000

// Scratch (static device arrays — no runtime allocation)
__device__ __half g_S[(size_t)V_N * 128];           // Σ relu(A2@W2+b2) per node, fp16
__device__ int    g_deg[V_N];                       // in-degree
__device__ __nv_bfloat16 g_PQ[(size_t)V_N * 256];   // [P | Q] per node, bf16
__device__ float  g_R[(size_t)V_N * 128];           // h @ Wn1_top (near-fp32)
__device__ __half g_W3n[128 * 128];                 // W3 @ Wn1_bot, fp16
__device__ float  g_bn3[128];                       // b3 @ Wn1_bot

// ============================================================================
// Warp-level MMA helpers (base PTX: ldmatrix sm_75+, mma.sync sm_80+)
// ============================================================================
__device__ __forceinline__ uint32_t smem_u32(const void* p) {
    uint32_t a;
    asm("{ .reg .u64 t; cvta.to.shared.u64 t, %1; cvt.u32.u64 %0, t; }"
        : "=r"(a) : "l"(p));
    return a;
}
__device__ __forceinline__ void ldsm_x4(uint32_t* r, uint32_t addr) {
    asm volatile("ldmatrix.sync.aligned.m8n8.x4.shared.b16 {%0,%1,%2,%3}, [%4];"
                 : "=r"(r[0]), "=r"(r[1]), "=r"(r[2]), "=r"(r[3]) : "r"(addr));
}
__device__ __forceinline__ void ldsm_x4_t(uint32_t* r, uint32_t addr) {
    asm volatile("ldmatrix.sync.aligned.m8n8.x4.trans.shared.b16 {%0,%1,%2,%3}, [%4];"
                 : "=r"(r[0]), "=r"(r[1]), "=r"(r[2]), "=r"(r[3]) : "r"(addr));
}
__device__ __forceinline__ void mma_bf16(float* d, const uint32_t* a, const uint32_t* b) {
    asm volatile(
        "mma.sync.aligned.m16n8k16.row.col.f32.bf16.bf16.f32 "
        "{%0,%1,%2,%3}, {%4,%5,%6,%7}, {%8,%9}, {%0,%1,%2,%3};"
        : "+f"(d[0]), "+f"(d[1]), "+f"(d[2]), "+f"(d[3])
        : "r"(a[0]), "r"(a[1]), "r"(a[2]), "r"(a[3]), "r"(b[0]), "r"(b[1]));
}
__device__ __forceinline__ void mma_f16(float* d, const uint32_t* a, const uint32_t* b) {
    asm volatile(
        "mma.sync.aligned.m16n8k16.row.col.f32.f16.f16.f32 "
        "{%0,%1,%2,%3}, {%4,%5,%6,%7}, {%8,%9}, {%0,%1,%2,%3};"
        : "+f"(d[0]), "+f"(d[1]), "+f"(d[2]), "+f"(d[3])
        : "r"(a[0]), "r"(a[1]), "r"(a[2]), "r"(a[3]), "r"(b[0]), "r"(b[1]));
}
__device__ __forceinline__ uint32_t pack2(float a, float b) {
    __nv_bfloat162 p = __floats2bfloat162_rn(a, b);
    return *(uint32_t*)&p;
}
// 16-byte vector fp16 reduction (sm_90+): 8 halves per op
__device__ __forceinline__ void red_add_v4h2(__half* p, uint4 v) {
    asm volatile("red.global.add.noftz.v4.f16x2 [%0], {%1, %2, %3, %4};"
                 :: "l"(p), "r"(v.x), "r"(v.y), "r"(v.z), "r"(v.w) : "memory");
}
// relu(bf16x2(p) + bf16x2(q) + bf16x2(b)) in fp32, repacked bf16x2
__device__ __forceinline__ uint32_t addrelu2(uint32_t p, uint32_t q, uint32_t b) {
    float2 fp = __bfloat1622float2(*(__nv_bfloat162*)&p);
    float2 fq = __bfloat1622float2(*(__nv_bfloat162*)&q);
    float2 fb = __bfloat1622float2(*(__nv_bfloat162*)&b);
    return pack2(fmaxf(fp.x + fq.x + fb.x, 0.f), fmaxf(fp.y + fq.y + fb.y, 0.f));
}

#define WPITCH 272   // b16 tile pitch for 128-col matrices
#define BPITCH 528   // b16 tile pitch for 256-col matrices

// Warp-tile GEMM (ACCUMULATES into d; caller zeroes). WP = weight pitch.
template <int NK, int AP, int WP, int F16>
__device__ __forceinline__ void gemm_tile(uint32_t abase, uint32_t wbase,
                                          int wr, int wc, int lane,
                                          float d[2][4][4]) {
    const int l15 = lane & 15;
    const int kh  = (lane >> 4) << 3;
#pragma unroll
    for (int ks = 0; ks < NK; ks++) {
        uint32_t a[2][4], b[4][2];
#pragma unroll
        for (int mi = 0; mi < 2; mi++) {
            uint32_t addr = abase + (uint32_t)((wr * 32 + mi * 16 + l15) * AP +
                                               (ks * 16 + kh) * 2);
            ldsm_x4(a[mi], addr);
        }
#pragma unroll
        for (int nj = 0; nj < 2; nj++) {
            uint32_t addr = wbase + (uint32_t)((ks * 16 + l15) * WP +
                                               (wc * 32 + nj * 16 + kh) * 2);
            uint32_t t[4];
            ldsm_x4_t(t, addr);
            b[2 * nj][0] = t[0]; b[2 * nj][1] = t[1];
            b[2 * nj + 1][0] = t[2]; b[2 * nj + 1][1] = t[3];
        }
#pragma unroll
        for (int mi = 0; mi < 2; mi++)
#pragma unroll
            for (int ni = 0; ni < 4; ni++) {
                if (F16) mma_f16(d[mi][ni], a[mi], b[ni]);
                else     mma_bf16(d[mi][ni], a[mi], b[ni]);
            }
    }
}
__device__ __forceinline__ void zero_d(float d[2][4][4]) {
#pragma unroll
    for (int mi = 0; mi < 2; mi++)
#pragma unroll
        for (int ni = 0; ni < 4; ni++)
#pragma unroll
            for (int x = 0; x < 4; x++) d[mi][ni][x] = 0.f;
}

// ---------------------------------------------------------------------------
// k_zero: zero g_S and g_deg
// ---------------------------------------------------------------------------
__global__ void k_zero() {
    const uint4 z = make_uint4(0, 0, 0, 0);
    const int nS = V_N * 128 / 8;
    for (int i = blockIdx.x * blockDim.x + threadIdx.x; i < nS;
         i += gridDim.x * blockDim.x)
        ((uint4*)g_S)[i] = z;
    const int nD = V_N / 4;
    for (int i = blockIdx.x * blockDim.x + threadIdx.x; i < nD;
         i += gridDim.x * blockDim.x)
        ((uint4*)g_deg)[i] = z;
}

// k_deg: in-degree histogram
__global__ void k_deg(const int* __restrict__ ei) {
    for (int i = blockIdx.x * blockDim.x + threadIdx.x; i < E_N;
         i += gridDim.x * blockDim.x)
        atomicAdd(&g_deg[ei[E_N + i]], 1);
}

// k_w3n: W3n = W3 @ Wn1_bot (fp32 -> fp16), bn3 = b3 @ Wn1_bot (fp32)
__global__ void k_w3n(const float* __restrict__ W3, const float* __restrict__ b3,
                      const float* __restrict__ Wn1) {
    const int n = threadIdx.x, k = blockIdx.x;
    float s = 0.f;
    for (int j = 0; j < 128; j++)
        s += W3[k * 128 + j] * Wn1[(128 + j) * 128 + n];
    g_W3n[k * 128 + n] = __float2half(s);
    if (k == 0) {
        float s2 = 0.f;
        for (int j = 0; j < 128; j++)
            s2 += b3[j] * Wn1[(128 + j) * 128 + n];
        g_bn3[n] = s2;
    }
}

// ---------------------------------------------------------------------------
// k_prep (merged k_pq + k_r): one h staging (hi/lo) per 128-row tile feeds
//   PQ = h@[W1_top | W1_bot]    (bf16, hi only)   -> g_PQ bf16
//   R  = h@Wn1_top 3-term split                   -> g_R fp32
// 512 threads, 4x4 warp grid.
// ---------------------------------------------------------------------------
#define P_W1  0        // 128 x 528 = 67584 (bf16, 256 cols: [W1_top|W1_bot])
#define P_WH  67584    // 34816
#define P_WL  102400   // 34816
#define P_HH  137216   // 128 x 272 = 34816
#define P_HL  172032   // 34816
#define SM_PREP_TOTAL 206848

__global__ __launch_bounds__(512, 1) void k_prep(
    const float* __restrict__ h, const float* __restrict__ W1,
    const float* __restrict__ Wn1)
{
    extern __shared__ __align__(16) char sm[];
    const uint32_t sbase = smem_u32(sm);
    const int tid = threadIdx.x, wid = tid >> 5, lane = tid & 31;
    const int wr = wid & 3, wc = wid >> 2;
    const int g = lane >> 2, q = lane & 3;

    // Stage weights: W1 as 256-col tile; Wn1_top split hi/lo
    for (int i = tid; i < 128 * 256; i += 512) {
        int k = i >> 8, n = i & 255;
        float w = (n < 128) ? W1[k * 128 + n] : W1[(128 + k) * 128 + (n - 128)];
        *(__nv_bfloat16*)(sm + P_W1 + k * BPITCH + n * 2) = __float2bfloat16(w);
    }
    for (int i = tid; i < 128 * 128; i += 512) {
        int k = i >> 7, n = i & 127;
        float w = Wn1[k * 128 + n];
        __nv_bfloat16 whi = __float2bfloat16(w);
        *(__nv_bfloat16*)(sm + P_WH + k * WPITCH + n * 2) = whi;
        *(__nv_bfloat16*)(sm + P_WL + k * WPITCH + n * 2) =
            __float2bfloat16(w - __bfloat162float(whi));
    }
    __syncthreads();

    const float4* h4 = (const float4*)h;
    const int numTiles = (V_N + 127) / 128;   // 391
    float d[2][4][4];

    for (int tile = blockIdx.x; tile < numTiles; tile += gridDim.x) {
        const int n0 = tile * 128;
        __syncthreads();   // previous tile's GEMMs done reading h tiles
        for (int i = tid; i < 128 * 32; i += 512) {
            int r = i >> 5, j = i & 31;
            int node = n0 + r;
            float4 v = (node < V_N) ? h4[(size_t)node * 32 + j]
                                    : make_float4(0.f, 0.f, 0.f, 0.f);
            __nv_bfloat16 h0 = __float2bfloat16(v.x), h1 = __float2bfloat16(v.y);
            __nv_bfloat16 h2 = __float2bfloat16(v.z), h3 = __float2bfloat16(v.w);
            uint2 uh, ul;
            uh.x = pack2(__bfloat162float(h0), __bfloat162float(h1));
            uh.y = pack2(__bfloat162float(h2), __bfloat162float(h3));
            ul.x = pack2(v.x - __bfloat162float(h0), v.y - __bfloat162float(h1));
            ul.y = pack2(v.z - __bfloat162float(h2), v.w - __bfloat162float(h3));
            *(uint2*)(sm + P_HH + r * WPITCH + j * 8) = uh;
            *(uint2*)(sm + P_HL + r * WPITCH + j * 8) = ul;
        }
        __syncthreads();

        // ---- PQ (two 128-col halves), bf16 hi only ----
#pragma unroll
        for (int half = 0; half < 2; half++) {
            zero_d(d);
            gemm_tile<8, WPITCH, BPITCH, 0>(sbase + P_HH,
                                            sbase + P_W1 + half * 256,
                                            wr, wc, lane, d);
#pragma unroll
            for (int mi = 0; mi < 2; mi++) {
                const int rA = wr * 32 + mi * 16 + g;
                const int nodeA = n0 + rA, nodeB = nodeA + 8;
#pragma unroll
                for (int ni = 0; ni < 4; ni++) {
                    const int c = half * 128 + wc * 32 + ni * 8 + 2 * q;
                    if (nodeA < V_N)
                        *(uint32_t*)&g_PQ[(size_t)nodeA * 256 + c] =
                            pack2(d[mi][ni][0], d[mi][ni][1]);
                    if (nodeB < V_N)
                        *(uint32_t*)&g_PQ[(size_t)nodeB * 256 + c] =
                            pack2(d[mi][ni][2], d[mi][ni][3]);
                }
            }
        }

        // ---- R: 3-term split ----
        zero_d(d);
        gemm_tile<8, WPITCH, WPITCH, 0>(sbase + P_HH, sbase + P_WH, wr, wc, lane, d);
        gemm_tile<8, WPITCH, WPITCH, 0>(sbase + P_HH, sbase + P_WL, wr, wc, lane, d);
        gemm_tile<8, WPITCH, WPITCH, 0>(sbase + P_HL, sbase + P_WH, wr, wc, lane, d);
#pragma unroll
        for (int mi = 0; mi < 2; mi++) {
            const int rA = wr * 32 + mi * 16 + g;
            const int nodeA = n0 + rA, nodeB = nodeA + 8;
#pragma unroll
            for (int ni = 0; ni < 4; ni++) {
                const int c = wc * 32 + ni * 8 + 2 * q;
                if (nodeA < V_N)
                    *(float2*)&g_R[(size_t)nodeA * 128 + c] =
                        make_float2(d[mi][ni][0], d[mi][ni][1]);
                if (nodeB < V_N)
                    *(float2*)&g_R[(size_t)nodeB * 128 + c] =
                        make_float2(d[mi][ni][2], d[mi][ni][3]);
            }
        }
    }
}

// ---------------------------------------------------------------------------
// k_edge: 128-edge tiles, 512 threads, 2 syncs/tile.
//   A2 = relu(P[src]+Q[dst]+b1);  Sstage = relu(A2@W2+b2) fp16 (smem);
//   scatter Sstage rows with 16B red.v4.f16x2 (overlapped with next gather).
// ---------------------------------------------------------------------------
#define SM_B1BF 0        // 128 bf16 = 256B
#define SM_B2S  256      // 128 f32 = 512B
#define SM_W2   768      // 128 x 272 = 34816
#define SM_A2A  35584
#define SM_A2B  70400
#define SM_SST  105216   // fp16 S staging, 128 x 272 = 34816
#define SM_EDGE_TOTAL 140032

__global__ __launch_bounds__(512, 1) void k_edge(
    const int* __restrict__ ei,
    const float* __restrict__ b1,
    const float* __restrict__ W2, const float* __restrict__ b2)
{
    extern __shared__ __align__(16) char sm[];
    float* b2s = (float*)(sm + SM_B2S);
    const uint32_t sbase = smem_u32(sm);
    const uint32_t sW2 = sbase + SM_W2;

    const int tid = threadIdx.x, wid = tid >> 5, lane = tid & 31;
    const int wr = wid & 3, wc = wid >> 2;
    const int g = lane >> 2, q = lane & 3;

    for (int i = tid; i < 128 * 128; i += 512) {
        int k = i >> 7, n = i & 127;
        *(__nv_bfloat16*)(sm + SM_W2 + k * WPITCH + n * 2) = __float2bfloat16(W2[i]);
    }
    if (tid < 128) {
        b2s[tid] = b2[tid];
        *(__nv_bfloat16*)(sm + SM_B1BF + tid * 2) = __float2bfloat16(b1[tid]);
    }
    __syncthreads();

    const int jg = tid & 15;                  // gather: 16B col group
    const int r0 = tid >> 4;                  // gather: base row (0..31)
    const uint4 Bv = *(const uint4*)(sm + SM_B1BF + jg * 16);
    const int sr = tid >> 2;                  // scatter: row (0..127)
    const int scg = (tid & 3) * 32;           // scatter: col group (32 fp16 = 64B)

    const int numTiles = E_N / 128;   // 6250
    float d[2][4][4];
    int buf = 0;

    // Prologue: gather first tile into buffer A
    int tile = blockIdx.x;
    if (tile < numTiles) {
        const int e0 = tile * 128;
        char* a2p = sm + SM_A2A;
#pragma unroll
        for (int k = 0; k < 4; k++) {
            int r = r0 + 32 * k;
            int s = ei[e0 + r], t = ei[E_N + e0 + r];
            uint4 P = *(const uint4*)&g_PQ[(size_t)s * 256 + jg * 8];
            uint4 Q = *(const uint4*)&g_PQ[(size_t)t * 256 + 128 + jg * 8];
            uint4 o;
            o.x = addrelu2(P.x, Q.x, Bv.x);
            o.y = addrelu2(P.y, Q.y, Bv.y);
            o.z = addrelu2(P.z, Q.z, Bv.z);
            o.w = addrelu2(P.w, Q.w, Bv.w);
            *(uint4*)(a2p + r * WPITCH + jg * 16) = o;
        }
    }

    for (; tile < numTiles; tile += gridDim.x) {
        const int e0 = tile * 128;
        __syncthreads();   // A2[buf] ready; Sstage free (scattered last iter)

        // ---- GEMM2 + epi -> fp16 Sstage ----
        zero_d(d);
        gemm_tile<8, WPITCH, WPITCH, 0>(sbase + (buf ? SM_A2B : SM_A2A), sW2,
                                        wr, wc, lane, d);
        {
#pragma unroll
            for (int mi = 0; mi < 2; mi++) {
                const int rA = wr * 32 + mi * 16 + g;
#pragma unroll
                for (int ni = 0; ni < 4; ni++) {
                    const int c = wc * 32 + ni * 8 + 2 * q;
                    float2 bb = *(const float2*)&b2s[c];
                    __half2 v0 = __floats2half2_rn(
                        fmaxf(d[mi][ni][0] + bb.x, 0.f),
                        fmaxf(d[mi][ni][1] + bb.y, 0.f));
                    __half2 v1 = __floats2half2_rn(
                        fmaxf(d[mi][ni][2] + bb.x, 0.f),
                        fmaxf(d[mi][ni][3] + bb.y, 0.f));
                    *(uint32_t*)(sm + SM_SST + rA * WPITCH + c * 2) = *(uint32_t*)&v0;
                    *(uint32_t*)(sm + SM_SST + (rA + 8) * WPITCH + c * 2) = *(uint32_t*)&v1;
                }
            }
        }
        __syncthreads();   // Sstage ready; A2[buf] free

        // ---- scatter (16B vector reds) + gather next tile ----
        {
            const int dst = ei[E_N + e0 + sr];
            __half* base = &g_S[(size_t)dst * 128 + scg];
            const char* srow = sm + SM_SST + sr * WPITCH + scg * 2;
#pragma unroll
            for (int k = 0; k < 4; k++) {
                uint4 v = *(const uint4*)(srow + k * 16);
                red_add_v4h2(base + k * 8, v);
            }
        }
        const int nt = tile + gridDim.x;
        if (nt < numTiles) {
            const int ne0 = nt * 128;
            char* a2p = sm + (buf ? SM_A2A : SM_A2B);
#pragma unroll
            for (int k = 0; k < 4; k++) {
                int r = r0 + 32 * k;
                int s = ei[ne0 + r], t = ei[E_N + ne0 + r];
                uint4 P = *(const uint4*)&g_PQ[(size_t)s * 256 + jg * 8];
                uint4 Q = *(const uint4*)&g_PQ[(size_t)t * 256 + 128 + jg * 8];
                uint4 o;
                o.x = addrelu2(P.x, Q.x, Bv.x);
                o.y = addrelu2(P.y, Q.y, Bv.y);
                o.z = addrelu2(P.z, Q.z, Bv.z);
                o.w = addrelu2(P.w, Q.w, Bv.w);
                *(uint4*)(a2p + r * WPITCH + jg * 16) = o;
            }
        }
        buf ^= 1;
    }
}

// ---------------------------------------------------------------------------
// k_node: T = relu(R + S@W3n + deg*bn3 + bn1); out = T@Wn2 (3-term split).
// ---------------------------------------------------------------------------
#define N_B1  0         // bn1 512B
#define N_B2  512       // bn2 512B
#define N_B3  1024      // bn3 512B
#define N_W3N 1536      // fp16 W3n, 128 x 272 = 34816
#define N_W2H 36352
#define N_W2L 71168
#define N_XS  105984    // S staged fp16, 128 x 272
#define N_THI 140800
#define N_TLO 175616
#define SM_NODE_TOTAL 210432

__global__ __launch_bounds__(512, 1) void k_node(
    const float* __restrict__ bn1,
    const float* __restrict__ Wn2, const float* __restrict__ bn2,
    float* __restrict__ out)
{
    extern __shared__ __align__(16) char sm[];
    float* bn1s = (float*)(sm + N_B1);
    float* bn2s = (float*)(sm + N_B2);
    float* bn3s = (float*)(sm + N_B3);
    const uint32_t sbase = smem_u32(sm);
    const int tid = threadIdx.x, wid = tid >> 5, lane = tid & 31;
    const int wr = wid & 3, wc = wid >> 2;
    const int g = lane >> 2, q = lane & 3;

    for (int i = tid; i < 128 * 128; i += 512) {
        int k = i >> 7, n = i & 127;
        *(__half*)(sm + N_W3N + k * WPITCH + n * 2) = g_W3n[i];
        float w2 = Wn2[i];
        __nv_bfloat16 whi = __float2bfloat16(w2);
        *(__nv_bfloat16*)(sm + N_W2H + k * WPITCH + n * 2) = whi;
        *(__nv_bfloat16*)(sm + N_W2L + k * WPITCH + n * 2) =
            __float2bfloat16(w2 - __bfloat162float(whi));
    }
    if (tid < 128) { bn1s[tid] = bn1[tid]; bn2s[tid] = bn2[tid]; bn3s[tid] = g_bn3[tid]; }
    __syncthreads();

    float d[2][4][4];
    const int numTiles = (V_N + 127) / 128;   // 391

    for (int tile = blockIdx.x; tile < numTiles; tile += gridDim.x) {
        const int n0 = tile * 128;
        __syncthreads();
        for (int i = tid; i < 128 * 16; i += 512) {
            int r = i >> 4, j = i & 15;
            int node = n0 + r;
            uint4 v = (node < V_N) ? *(const uint4*)&g_S[(size_t)node * 128 + j * 8]
                                   : make_uint4(0, 0, 0, 0);
            *(uint4*)(sm + N_XS + r * WPITCH + j * 16) = v;
        }
        __syncthreads();

        // GEMM A: S @ W3n (fp16)
        zero_d(d);
        gemm_tile<8, WPITCH, WPITCH, 1>(sbase + N_XS, sbase + N_W3N, wr, wc, lane, d);

        // T = relu(d + R + deg*bn3 + bn1), split -> Thi/Tlo
#pragma unroll
        for (int mi = 0; mi < 2; mi++) {
            const int rA = wr * 32 + mi * 16 + g;
            const int nodeA = n0 + rA, nodeB = nodeA + 8;
            const float degA = (nodeA < V_N) ? (float)g_deg[nodeA] : 0.f;
            const float degB = (nodeB < V_N) ? (float)g_deg[nodeB] : 0.f;
#pragma unroll
            for (int ni = 0; ni < 4; ni++) {
                const int c = wc * 32 + ni * 8 + 2 * q;
                float2 bb = *(const float2*)&bn1s[c];
                float2 b3v = *(const float2*)&bn3s[c];
                float2 r0 = (nodeA < V_N) ? *(const float2*)&g_R[(size_t)nodeA * 128 + c]
                                          : make_float2(0.f, 0.f);
                float2 r1 = (nodeB < V_N) ? *(const float2*)&g_R[(size_t)nodeB * 128 + c]
                                          : make_float2(0.f, 0.f);
                float t0 = fmaxf(d[mi][ni][0] + r0.x + degA * b3v.x + bb.x, 0.f);
                float t1 = fmaxf(d[mi][ni][1] + r0.y + degA * b3v.y + bb.y, 0.f);
                float t2 = fmaxf(d[mi][ni][2] + r1.x + degB * b3v.x + bb.x, 0.f);
                float t3 = fmaxf(d[mi][ni][3] + r1.y + degB * b3v.y + bb.y, 0.f);
                __nv_bfloat16 h0 = __float2bfloat16(t0), h1 = __float2bfloat16(t1);
                __nv_bfloat16 h2 = __float2bfloat16(t2), h3 = __float2bfloat16(t3);
                *(uint32_t*)(sm + N_THI + rA * WPITCH + c * 2) =
                    pack2(__bfloat162float(h0), __bfloat162float(h1));
                *(uint32_t*)(sm + N_THI + (rA + 8) * WPITCH + c * 2) =
                    pack2(__bfloat162float(h2), __bfloat162float(h3));
                *(uint32_t*)(sm + N_TLO + rA * WPITCH + c * 2) =
                    pack2(t0 - __bfloat162float(h0), t1 - __bfloat162float(h1));
                *(uint32_t*)(sm + N_TLO + (rA + 8) * WPITCH + c * 2) =
                    pack2(t2 - __bfloat162float(h2), t3 - __bfloat162float(h3));
            }
        }
        __syncthreads();

        // GEMM B: out = Thi@W2hi + Thi@W2lo + Tlo@W2hi + bn2
        zero_d(d);
        gemm_tile<8, WPITCH, WPITCH, 0>(sbase + N_THI, sbase + N_W2H, wr, wc, lane, d);
        gemm_tile<8, WPITCH, WPITCH, 0>(sbase + N_THI, sbase + N_W2L, wr, wc, lane, d);
        gemm_tile<8, WPITCH, WPITCH, 0>(sbase + N_TLO, sbase + N_W2H, wr, wc, lane, d);

#pragma unroll
        for (int mi = 0; mi < 2; mi++) {
            const int rA = wr * 32 + mi * 16 + g;
            const int nodeA = n0 + rA, nodeB = nodeA + 8;
#pragma unroll
            for (int ni = 0; ni < 4; ni++) {
                const int c = wc * 32 + ni * 8 + 2 * q;
                float2 bb = *(const float2*)&bn2s[c];
                if (nodeA < V_N)
                    *(float2*)&out[(size_t)nodeA * 128 + c] =
                        make_float2(d[mi][ni][0] + bb.x, d[mi][ni][1] + bb.y);
                if (nodeB < V_N)
                    *(float2*)&out[(size_t)nodeB * 128 + c] =
                        make_float2(d[mi][ni][2] + bb.x, d[mi][ni][3] + bb.y);
            }
        }
    }
}

// ---------------------------------------------------------------------------
extern "C" void kernel_launch(void* const* d_in, const int* in_sizes, int n_in,
                              void* d_out, int out_size) {
    const float* h   = (const float*)d_in[0];
    const int*   ei  = (const int*)d_in[1];   // int32 (JAX x64 disabled)
    const float* W1  = (const float*)d_in[2];
    const float* b1  = (const float*)d_in[3];
    const float* W2  = (const float*)d_in[4];
    const float* b2  = (const float*)d_in[5];
    const float* W3  = (const float*)d_in[6];
    const float* b3  = (const float*)d_in[7];
    const float* Wn1 = (const float*)d_in[8];
    const float* bn1 = (const float*)d_in[9];
    const float* Wn2 = (const float*)d_in[10];
    const float* bn2 = (const float*)d_in[11];
    float*       out = (float*)d_out;

    cudaFuncSetAttribute(k_prep, cudaFuncAttributeMaxDynamicSharedMemorySize, SM_PREP_TOTAL);
    cudaFuncSetAttribute(k_edge, cudaFuncAttributeMaxDynamicSharedMemorySize, SM_EDGE_TOTAL);
    cudaFuncSetAttribute(k_node, cudaFuncAttributeMaxDynamicSharedMemorySize, SM_NODE_TOTAL);

    k_zero<<<512, 256>>>();
    k_deg<<<1024, 256>>>(ei);
    k_w3n<<<128, 128>>>(W3, b3, Wn1);
    k_prep<<<148, 512, SM_PREP_TOTAL>>>(h, W1, Wn1);
    k_edge<<<148, 512, SM_EDGE_TOTAL>>>(ei, b1, W2, b2);
    k_node<<<148, 512, SM_NODE_TOTAL>>>(bn1, Wn2, bn2, out);
}

// round 12
// speedup vs baseline: 1.1881x; 1.1881x over previous
#include <cuda_runtime.h>
#include <cuda_bf16.h>
#include <cuda_fp16.h>
#include <cstdint>

// Problem constants (fixed shapes)
#define V_N 50000
#define E_N 800000

// Scratch (static device arrays — no runtime allocation)
__device__ __half g_S[(size_t)V_N * 128];           // Σ relu(A2@W2+b2) per node, fp16
__device__ int    g_deg[V_N];                       // in-degree
__device__ __nv_bfloat16 g_PQ[(size_t)V_N * 256];   // [P | Q] per node, bf16
__device__ float  g_R[(size_t)V_N * 128];           // h @ Wn1_top (near-fp32)
__device__ __half g_W3n[128 * 128];                 // W3 @ Wn1_bot, fp16
__device__ float  g_bn3[128];                       // b3 @ Wn1_bot

// ============================================================================
// Warp-level MMA helpers (base PTX: ldmatrix sm_75+, mma.sync sm_80+)
// ============================================================================
__device__ __forceinline__ uint32_t smem_u32(const void* p) {
    uint32_t a;
    asm("{ .reg .u64 t; cvta.to.shared.u64 t, %1; cvt.u32.u64 %0, t; }"
        : "=r"(a) : "l"(p));
    return a;
}
__device__ __forceinline__ void ldsm_x4(uint32_t* r, uint32_t addr) {
    asm volatile("ldmatrix.sync.aligned.m8n8.x4.shared.b16 {%0,%1,%2,%3}, [%4];"
                 : "=r"(r[0]), "=r"(r[1]), "=r"(r[2]), "=r"(r[3]) : "r"(addr));
}
__device__ __forceinline__ void ldsm_x4_t(uint32_t* r, uint32_t addr) {
    asm volatile("ldmatrix.sync.aligned.m8n8.x4.trans.shared.b16 {%0,%1,%2,%3}, [%4];"
                 : "=r"(r[0]), "=r"(r[1]), "=r"(r[2]), "=r"(r[3]) : "r"(addr));
}
__device__ __forceinline__ void mma_bf16(float* d, const uint32_t* a, const uint32_t* b) {
    asm volatile(
        "mma.sync.aligned.m16n8k16.row.col.f32.bf16.bf16.f32 "
        "{%0,%1,%2,%3}, {%4,%5,%6,%7}, {%8,%9}, {%0,%1,%2,%3};"
        : "+f"(d[0]), "+f"(d[1]), "+f"(d[2]), "+f"(d[3])
        : "r"(a[0]), "r"(a[1]), "r"(a[2]), "r"(a[3]), "r"(b[0]), "r"(b[1]));
}
__device__ __forceinline__ void mma_f16(float* d, const uint32_t* a, const uint32_t* b) {
    asm volatile(
        "mma.sync.aligned.m16n8k16.row.col.f32.f16.f16.f32 "
        "{%0,%1,%2,%3}, {%4,%5,%6,%7}, {%8,%9}, {%0,%1,%2,%3};"
        : "+f"(d[0]), "+f"(d[1]), "+f"(d[2]), "+f"(d[3])
        : "r"(a[0]), "r"(a[1]), "r"(a[2]), "r"(a[3]), "r"(b[0]), "r"(b[1]));
}
__device__ __forceinline__ uint32_t pack2(float a, float b) {
    __nv_bfloat162 p = __floats2bfloat162_rn(a, b);
    return *(uint32_t*)&p;
}
// 16-byte vector fp16 reduction (sm_90+): 8 halves per op
__device__ __forceinline__ void red_add_v4h2(__half* p, uint4 v) {
    asm volatile("red.global.add.noftz.v4.f16x2 [%0], {%1, %2, %3, %4};"
                 :: "l"(p), "r"(v.x), "r"(v.y), "r"(v.z), "r"(v.w) : "memory");
}
// relu(bf16x2(p) + bf16x2(q) + bf16x2(b)) in fp32, repacked bf16x2
__device__ __forceinline__ uint32_t addrelu2(uint32_t p, uint32_t q, uint32_t b) {
    float2 fp = __bfloat1622float2(*(__nv_bfloat162*)&p);
    float2 fq = __bfloat1622float2(*(__nv_bfloat162*)&q);
    float2 fb = __bfloat1622float2(*(__nv_bfloat162*)&b);
    return pack2(fmaxf(fp.x + fq.x + fb.x, 0.f), fmaxf(fp.y + fq.y + fb.y, 0.f));
}

#define WPITCH 272   // b16 tile pitch for 128-col matrices
#define BPITCH 528   // b16 tile pitch for 256-col matrices

// Warp-tile GEMM (ACCUMULATES into d; caller zeroes). WP = weight pitch.
template <int NK, int AP, int WP, int F16>
__device__ __forceinline__ void gemm_tile(uint32_t abase, uint32_t wbase,
                                          int wr, int wc, int lane,
                                          float d[2][4][4]) {
    const int l15 = lane & 15;
    const int kh  = (lane >> 4) << 3;
#pragma unroll
    for (int ks = 0; ks < NK; ks++) {
        uint32_t a[2][4], b[4][2];
#pragma unroll
        for (int mi = 0; mi < 2; mi++) {
            uint32_t addr = abase + (uint32_t)((wr * 32 + mi * 16 + l15) * AP +
                                               (ks * 16 + kh) * 2);
            ldsm_x4(a[mi], addr);
        }
#pragma unroll
        for (int nj = 0; nj < 2; nj++) {
            uint32_t addr = wbase + (uint32_t)((ks * 16 + l15) * WP +
                                               (wc * 32 + nj * 16 + kh) * 2);
            uint32_t t[4];
            ldsm_x4_t(t, addr);
            b[2 * nj][0] = t[0]; b[2 * nj][1] = t[1];
            b[2 * nj + 1][0] = t[2]; b[2 * nj + 1][1] = t[3];
        }
#pragma unroll
        for (int mi = 0; mi < 2; mi++)
#pragma unroll
            for (int ni = 0; ni < 4; ni++) {
                if (F16) mma_f16(d[mi][ni], a[mi], b[ni]);
                else     mma_bf16(d[mi][ni], a[mi], b[ni]);
            }
    }
}
__device__ __forceinline__ void zero_d(float d[2][4][4]) {
#pragma unroll
    for (int mi = 0; mi < 2; mi++)
#pragma unroll
        for (int ni = 0; ni < 4; ni++)
#pragma unroll
            for (int x = 0; x < 4; x++) d[mi][ni][x] = 0.f;
}

// ---------------------------------------------------------------------------
// k_zero: zero g_S and g_deg
// ---------------------------------------------------------------------------
__global__ void k_zero() {
    const uint4 z = make_uint4(0, 0, 0, 0);
    const int nS = V_N * 128 / 8;
    for (int i = blockIdx.x * blockDim.x + threadIdx.x; i < nS;
         i += gridDim.x * blockDim.x)
        ((uint4*)g_S)[i] = z;
    const int nD = V_N / 4;
    for (int i = blockIdx.x * blockDim.x + threadIdx.x; i < nD;
         i += gridDim.x * blockDim.x)
        ((uint4*)g_deg)[i] = z;
}

// k_deg: in-degree histogram
__global__ void k_deg(const int* __restrict__ ei) {
    for (int i = blockIdx.x * blockDim.x + threadIdx.x; i < E_N;
         i += gridDim.x * blockDim.x)
        atomicAdd(&g_deg[ei[E_N + i]], 1);
}

// k_w3n: W3n = W3 @ Wn1_bot (fp32 -> fp16), bn3 = b3 @ Wn1_bot (fp32)
__global__ void k_w3n(const float* __restrict__ W3, const float* __restrict__ b3,
                      const float* __restrict__ Wn1) {
    const int n = threadIdx.x, k = blockIdx.x;
    float s = 0.f;
    for (int j = 0; j < 128; j++)
        s += W3[k * 128 + j] * Wn1[(128 + j) * 128 + n];
    g_W3n[k * 128 + n] = __float2half(s);
    if (k == 0) {
        float s2 = 0.f;
        for (int j = 0; j < 128; j++)
            s2 += b3[j] * Wn1[(128 + j) * 128 + n];
        g_bn3[n] = s2;
    }
}

// ---------------------------------------------------------------------------
// k_prep (merged): one h staging (hi/lo) per 128-row tile feeds
//   PQ = h@[W1_top | W1_bot]  (bf16, hi only)  -> g_PQ bf16
//   R  = h@Wn1_top 3-term split                -> g_R fp32
// ---------------------------------------------------------------------------
#define P_W1  0        // 128 x 528 = 67584 (bf16, 256 cols)
#define P_WH  67584
#define P_WL  102400
#define P_HH  137216
#define P_HL  172032
#define SM_PREP_TOTAL 206848

__global__ __launch_bounds__(512, 1) void k_prep(
    const float* __restrict__ h, const float* __restrict__ W1,
    const float* __restrict__ Wn1)
{
    extern __shared__ __align__(16) char sm[];
    const uint32_t sbase = smem_u32(sm);
    const int tid = threadIdx.x, wid = tid >> 5, lane = tid & 31;
    const int wr = wid & 3, wc = wid >> 2;
    const int g = lane >> 2, q = lane & 3;

    for (int i = tid; i < 128 * 256; i += 512) {
        int k = i >> 8, n = i & 255;
        float w = (n < 128) ? W1[k * 128 + n] : W1[(128 + k) * 128 + (n - 128)];
        *(__nv_bfloat16*)(sm + P_W1 + k * BPITCH + n * 2) = __float2bfloat16(w);
    }
    for (int i = tid; i < 128 * 128; i += 512) {
        int k = i >> 7, n = i & 127;
        float w = Wn1[k * 128 + n];
        __nv_bfloat16 whi = __float2bfloat16(w);
        *(__nv_bfloat16*)(sm + P_WH + k * WPITCH + n * 2) = whi;
        *(__nv_bfloat16*)(sm + P_WL + k * WPITCH + n * 2) =
            __float2bfloat16(w - __bfloat162float(whi));
    }
    __syncthreads();

    const float4* h4 = (const float4*)h;
    const int numTiles = (V_N + 127) / 128;   // 391
    float d[2][4][4];

    for (int tile = blockIdx.x; tile < numTiles; tile += gridDim.x) {
        const int n0 = tile * 128;
        __syncthreads();
        for (int i = tid; i < 128 * 32; i += 512) {
            int r = i >> 5, j = i & 31;
            int node = n0 + r;
            float4 v = (node < V_N) ? h4[(size_t)node * 32 + j]
                                    : make_float4(0.f, 0.f, 0.f, 0.f);
            __nv_bfloat16 h0 = __float2bfloat16(v.x), h1 = __float2bfloat16(v.y);
            __nv_bfloat16 h2 = __float2bfloat16(v.z), h3 = __float2bfloat16(v.w);
            uint2 uh, ul;
            uh.x = pack2(__bfloat162float(h0), __bfloat162float(h1));
            uh.y = pack2(__bfloat162float(h2), __bfloat162float(h3));
            ul.x = pack2(v.x - __bfloat162float(h0), v.y - __bfloat162float(h1));
            ul.y = pack2(v.z - __bfloat162float(h2), v.w - __bfloat162float(h3));
            *(uint2*)(sm + P_HH + r * WPITCH + j * 8) = uh;
            *(uint2*)(sm + P_HL + r * WPITCH + j * 8) = ul;
        }
        __syncthreads();

        // ---- PQ (two 128-col halves), bf16 hi only ----
#pragma unroll
        for (int half = 0; half < 2; half++) {
            zero_d(d);
            gemm_tile<8, WPITCH, BPITCH, 0>(sbase + P_HH,
                                            sbase + P_W1 + half * 256,
                                            wr, wc, lane, d);
#pragma unroll
            for (int mi = 0; mi < 2; mi++) {
                const int rA = wr * 32 + mi * 16 + g;
                const int nodeA = n0 + rA, nodeB = nodeA + 8;
#pragma unroll
                for (int ni = 0; ni < 4; ni++) {
                    const int c = half * 128 + wc * 32 + ni * 8 + 2 * q;
                    if (nodeA < V_N)
                        *(uint32_t*)&g_PQ[(size_t)nodeA * 256 + c] =
                            pack2(d[mi][ni][0], d[mi][ni][1]);
                    if (nodeB < V_N)
                        *(uint32_t*)&g_PQ[(size_t)nodeB * 256 + c] =
                            pack2(d[mi][ni][2], d[mi][ni][3]);
                }
            }
        }

        // ---- R: 3-term split ----
        zero_d(d);
        gemm_tile<8, WPITCH, WPITCH, 0>(sbase + P_HH, sbase + P_WH, wr, wc, lane, d);
        gemm_tile<8, WPITCH, WPITCH, 0>(sbase + P_HH, sbase + P_WL, wr, wc, lane, d);
        gemm_tile<8, WPITCH, WPITCH, 0>(sbase + P_HL, sbase + P_WH, wr, wc, lane, d);
#pragma unroll
        for (int mi = 0; mi < 2; mi++) {
            const int rA = wr * 32 + mi * 16 + g;
            const int nodeA = n0 + rA, nodeB = nodeA + 8;
#pragma unroll
            for (int ni = 0; ni < 4; ni++) {
                const int c = wc * 32 + ni * 8 + 2 * q;
                if (nodeA < V_N)
                    *(float2*)&g_R[(size_t)nodeA * 128 + c] =
                        make_float2(d[mi][ni][0], d[mi][ni][1]);
                if (nodeB < V_N)
                    *(float2*)&g_R[(size_t)nodeB * 128 + c] =
                        make_float2(d[mi][ni][2], d[mi][ni][3]);
            }
        }
    }
}

// ---------------------------------------------------------------------------
// k_edge: 128-edge tiles, 512 threads, 1 sync/tile (round-10 structure).
//   A2 = relu(P[src]+Q[dst]+b1);  S[dst] += relu(A2@W2+b2)
// W2 columns stored PERMUTED (tau: within each 32-col tile,
// stored ni*8+2q+j <- logical 8q+2ni+j) so each thread's fragment row spans
// logical cols [ws+8q, ws+8q+8) -> ONE red.v4.f16x2 (16B) per row.
// g_S remains in LOGICAL column order -> k_node unchanged.
// ---------------------------------------------------------------------------
#define SM_B1BF 0        // 128 bf16 = 256B
#define SM_B2S  256      // 128 f32 = 512B (logical order)
#define SM_W2   768      // 128 x 272 = 34816 (permuted cols)
#define SM_A2A  35584
#define SM_A2B  70400
#define SM_EDGE_TOTAL 105216

__global__ __launch_bounds__(512, 1) void k_edge(
    const int* __restrict__ ei,
    const float* __restrict__ b1,
    const float* __restrict__ W2, const float* __restrict__ b2)
{
    extern __shared__ __align__(16) char sm[];
    float* b2s = (float*)(sm + SM_B2S);
    const uint32_t sbase = smem_u32(sm);
    const uint32_t sW2 = sbase + SM_W2;

    const int tid = threadIdx.x, wid = tid >> 5, lane = tid & 31;
    const int wr = wid & 3, wc = wid >> 2;
    const int g = lane >> 2, q = lane & 3;

    // Stage W2 with column permutation tau
    for (int i = tid; i < 128 * 128; i += 512) {
        int k = i >> 7, n = i & 127;
        int t = n & 31, base = n & ~31;
        int q2 = t >> 3, rem = t & 7, ni2 = rem >> 1, jj = rem & 1;
        int tcol = base + ni2 * 8 + 2 * q2 + jj;   // stored position of logical n
        *(__nv_bfloat16*)(sm + SM_W2 + k * WPITCH + tcol * 2) = __float2bfloat16(W2[i]);
    }
    if (tid < 128) {
        b2s[tid] = b2[tid];   // logical order
        *(__nv_bfloat16*)(sm + SM_B1BF + tid * 2) = __float2bfloat16(b1[tid]);
    }
    __syncthreads();

    const int jg = tid & 15;                  // gather: 16B col group
    const int r0 = tid >> 4;                  // gather: base row (0..31)
    const uint4 Bv = *(const uint4*)(sm + SM_B1BF + jg * 16);
    const int cb = wc * 32 + 8 * q;           // scatter: logical col base (8 cols)

    const int numTiles = E_N / 128;   // 6250
    float d[2][4][4];
    int buf = 0;

    // Prologue: gather first tile into buffer A
    int tile = blockIdx.x;
    if (tile < numTiles) {
        const int e0 = tile * 128;
        char* a2p = sm + SM_A2A;
#pragma unroll
        for (int k = 0; k < 4; k++) {
            int r = r0 + 32 * k;
            int s = ei[e0 + r], t = ei[E_N + e0 + r];
            uint4 P = *(const uint4*)&g_PQ[(size_t)s * 256 + jg * 8];
            uint4 Q = *(const uint4*)&g_PQ[(size_t)t * 256 + 128 + jg * 8];
            uint4 o;
            o.x = addrelu2(P.x, Q.x, Bv.x);
            o.y = addrelu2(P.y, Q.y, Bv.y);
            o.z = addrelu2(P.z, Q.z, Bv.z);
            o.w = addrelu2(P.w, Q.w, Bv.w);
            *(uint4*)(a2p + r * WPITCH + jg * 16) = o;
        }
    }

    for (; tile < numTiles; tile += gridDim.x) {
        const int e0 = tile * 128;
        __syncthreads();   // A2[buf] ready; other buffer free

        // ---- GEMM2 on A2[buf] (output cols permuted) ----
        zero_d(d);
        gemm_tile<8, WPITCH, WPITCH, 0>(sbase + (buf ? SM_A2B : SM_A2A), sW2,
                                        wr, wc, lane, d);

        // ---- scatter: one 16B red per row per mi ----
        // fragment (ni, j) holds logical col cb + 2*ni + j
        {
            const int rA = wr * 32 + g;
            float2 bb0 = *(const float2*)&b2s[cb + 0];
            float2 bb1 = *(const float2*)&b2s[cb + 2];
            float2 bb2 = *(const float2*)&b2s[cb + 4];
            float2 bb3 = *(const float2*)&b2s[cb + 6];
#pragma unroll
            for (int mi = 0; mi < 2; mi++) {
                const int rr = rA + mi * 16;
                const int d0 = ei[E_N + e0 + rr], d1 = ei[E_N + e0 + rr + 8];
                __half2 a0 = __floats2half2_rn(fmaxf(d[mi][0][0] + bb0.x, 0.f),
                                               fmaxf(d[mi][0][1] + bb0.y, 0.f));
                __half2 a1 = __floats2half2_rn(fmaxf(d[mi][1][0] + bb1.x, 0.f),
                                               fmaxf(d[mi][1][1] + bb1.y, 0.f));
                __half2 a2 = __floats2half2_rn(fmaxf(d[mi][2][0] + bb2.x, 0.f),
                                               fmaxf(d[mi][2][1] + bb2.y, 0.f));
                __half2 a3 = __floats2half2_rn(fmaxf(d[mi][3][0] + bb3.x, 0.f),
                                               fmaxf(d[mi][3][1] + bb3.y, 0.f));
                uint4 v0 = make_uint4(*(uint32_t*)&a0, *(uint32_t*)&a1,
                                      *(uint32_t*)&a2, *(uint32_t*)&a3);
                red_add_v4h2(&g_S[(size_t)d0 * 128 + cb], v0);

                __half2 c0 = __floats2half2_rn(fmaxf(d[mi][0][2] + bb0.x, 0.f),
                                               fmaxf(d[mi][0][3] + bb0.y, 0.f));
                __half2 c1 = __floats2half2_rn(fmaxf(d[mi][1][2] + bb1.x, 0.f),
                                               fmaxf(d[mi][1][3] + bb1.y, 0.f));
                __half2 c2 = __floats2half2_rn(fmaxf(d[mi][2][2] + bb2.x, 0.f),
                                               fmaxf(d[mi][2][3] + bb2.y, 0.f));
                __half2 c3 = __floats2half2_rn(fmaxf(d[mi][3][2] + bb3.x, 0.f),
                                               fmaxf(d[mi][3][3] + bb3.y, 0.f));
                uint4 v1 = make_uint4(*(uint32_t*)&c0, *(uint32_t*)&c1,
                                      *(uint32_t*)&c2, *(uint32_t*)&c3);
                red_add_v4h2(&g_S[(size_t)d1 * 128 + cb], v1);
            }
        }

        // ---- gather next tile into the other buffer ----
        const int nt = tile + gridDim.x;
        if (nt < numTiles) {
            const int ne0 = nt * 128;
            char* a2p = sm + (buf ? SM_A2A : SM_A2B);
#pragma unroll
            for (int k = 0; k < 4; k++) {
                int r = r0 + 32 * k;
                int s = ei[ne0 + r], t = ei[E_N + ne0 + r];
                uint4 P = *(const uint4*)&g_PQ[(size_t)s * 256 + jg * 8];
                uint4 Q = *(const uint4*)&g_PQ[(size_t)t * 256 + 128 + jg * 8];
                uint4 o;
                o.x = addrelu2(P.x, Q.x, Bv.x);
                o.y = addrelu2(P.y, Q.y, Bv.y);
                o.z = addrelu2(P.z, Q.z, Bv.z);
                o.w = addrelu2(P.w, Q.w, Bv.w);
                *(uint4*)(a2p + r * WPITCH + jg * 16) = o;
            }
        }
        buf ^= 1;
    }
}

// ---------------------------------------------------------------------------
// k_node: T = relu(R + S@W3n + deg*bn3 + bn1); out = T@Wn2 (3-term split).
// ---------------------------------------------------------------------------
#define N_B1  0         // bn1 512B
#define N_B2  512       // bn2 512B
#define N_B3  1024      // bn3 512B
#define N_W3N 1536      // fp16 W3n, 128 x 272 = 34816
#define N_W2H 36352
#define N_W2L 71168
#define N_XS  105984    // S staged fp16, 128 x 272
#define N_THI 140800
#define N_TLO 175616
#define SM_NODE_TOTAL 210432

__global__ __launch_bounds__(512, 1) void k_node(
    const float* __restrict__ bn1,
    const float* __restrict__ Wn2, const float* __restrict__ bn2,
    float* __restrict__ out)
{
    extern __shared__ __align__(16) char sm[];
    float* bn1s = (float*)(sm + N_B1);
    float* bn2s = (float*)(sm + N_B2);
    float* bn3s = (float*)(sm + N_B3);
    const uint32_t sbase = smem_u32(sm);
    const int tid = threadIdx.x, wid = tid >> 5, lane = tid & 31;
    const int wr = wid & 3, wc = wid >> 2;
    const int g = lane >> 2, q = lane & 3;

    for (int i = tid; i < 128 * 128; i += 512) {
        int k = i >> 7, n = i & 127;
        *(__half*)(sm + N_W3N + k * WPITCH + n * 2) = g_W3n[i];
        float w2 = Wn2[i];
        __nv_bfloat16 whi = __float2bfloat16(w2);
        *(__nv_bfloat16*)(sm + N_W2H + k * WPITCH + n * 2) = whi;
        *(__nv_bfloat16*)(sm + N_W2L + k * WPITCH + n * 2) =
            __float2bfloat16(w2 - __bfloat162float(whi));
    }
    if (tid < 128) { bn1s[tid] = bn1[tid]; bn2s[tid] = bn2[tid]; bn3s[tid] = g_bn3[tid]; }
    __syncthreads();

    float d[2][4][4];
    const int numTiles = (V_N + 127) / 128;   // 391

    for (int tile = blockIdx.x; tile < numTiles; tile += gridDim.x) {
        const int n0 = tile * 128;
        __syncthreads();
        for (int i = tid; i < 128 * 16; i += 512) {
            int r = i >> 4, j = i & 15;
            int node = n0 + r;
            uint4 v = (node < V_N) ? *(const uint4*)&g_S[(size_t)node * 128 + j * 8]
                                   : make_uint4(0, 0, 0, 0);
            *(uint4*)(sm + N_XS + r * WPITCH + j * 16) = v;
        }
        __syncthreads();

        // GEMM A: S @ W3n (fp16)
        zero_d(d);
        gemm_tile<8, WPITCH, WPITCH, 1>(sbase + N_XS, sbase + N_W3N, wr, wc, lane, d);

        // T = relu(d + R + deg*bn3 + bn1), split -> Thi/Tlo
#pragma unroll
        for (int mi = 0; mi < 2; mi++) {
            const int rA = wr * 32 + mi * 16 + g;
            const int nodeA = n0 + rA, nodeB = nodeA + 8;
            const float degA = (nodeA < V_N) ? (float)g_deg[nodeA] : 0.f;
            const float degB = (nodeB < V_N) ? (float)g_deg[nodeB] : 0.f;
#pragma unroll
            for (int ni = 0; ni < 4; ni++) {
                const int c = wc * 32 + ni * 8 + 2 * q;
                float2 bb = *(const float2*)&bn1s[c];
                float2 b3v = *(const float2*)&bn3s[c];
                float2 r0 = (nodeA < V_N) ? *(const float2*)&g_R[(size_t)nodeA * 128 + c]
                                          : make_float2(0.f, 0.f);
                float2 r1 = (nodeB < V_N) ? *(const float2*)&g_R[(size_t)nodeB * 128 + c]
                                          : make_float2(0.f, 0.f);
                float t0 = fmaxf(d[mi][ni][0] + r0.x + degA * b3v.x + bb.x, 0.f);
                float t1 = fmaxf(d[mi][ni][1] + r0.y + degA * b3v.y + bb.y, 0.f);
                float t2 = fmaxf(d[mi][ni][2] + r1.x + degB * b3v.x + bb.x, 0.f);
                float t3 = fmaxf(d[mi][ni][3] + r1.y + degB * b3v.y + bb.y, 0.f);
                __nv_bfloat16 h0 = __float2bfloat16(t0), h1 = __float2bfloat16(t1);
                __nv_bfloat16 h2 = __float2bfloat16(t2), h3 = __float2bfloat16(t3);
                *(uint32_t*)(sm + N_THI + rA * WPITCH + c * 2) =
                    pack2(__bfloat162float(h0), __bfloat162float(h1));
                *(uint32_t*)(sm + N_THI + (rA + 8) * WPITCH + c * 2) =
                    pack2(__bfloat162float(h2), __bfloat162float(h3));
                *(uint32_t*)(sm + N_TLO + rA * WPITCH + c * 2) =
                    pack2(t0 - __bfloat162float(h0), t1 - __bfloat162float(h1));
                *(uint32_t*)(sm + N_TLO + (rA + 8) * WPITCH + c * 2) =
                    pack2(t2 - __bfloat162float(h2), t3 - __bfloat162float(h3));
            }
        }
        __syncthreads();

        // GEMM B: out = Thi@W2hi + Thi@W2lo + Tlo@W2hi + bn2
        zero_d(d);
        gemm_tile<8, WPITCH, WPITCH, 0>(sbase + N_THI, sbase + N_W2H, wr, wc, lane, d);
        gemm_tile<8, WPITCH, WPITCH, 0>(sbase + N_THI, sbase + N_W2L, wr, wc, lane, d);
        gemm_tile<8, WPITCH, WPITCH, 0>(sbase + N_TLO, sbase + N_W2H, wr, wc, lane, d);

#pragma unroll
        for (int mi = 0; mi < 2; mi++) {
            const int rA = wr * 32 + mi * 16 + g;
            const int nodeA = n0 + rA, nodeB = nodeA + 8;
#pragma unroll
            for (int ni = 0; ni < 4; ni++) {
                const int c = wc * 32 + ni * 8 + 2 * q;
                float2 bb = *(const float2*)&bn2s[c];
                if (nodeA < V_N)
                    *(float2*)&out[(size_t)nodeA * 128 + c] =
                        make_float2(d[mi][ni][0] + bb.x, d[mi][ni][1] + bb.y);
                if (nodeB < V_N)
                    *(float2*)&out[(size_t)nodeB * 128 + c] =
                        make_float2(d[mi][ni][2] + bb.x, d[mi][ni][3] + bb.y);
            }
        }
    }
}

// ---------------------------------------------------------------------------
extern "C" void kernel_launch(void* const* d_in, const int* in_sizes, int n_in,
                              void* d_out, int out_size) {
    const float* h   = (const float*)d_in[0];
    const int*   ei  = (const int*)d_in[1];   // int32 (JAX x64 disabled)
    const float* W1  = (const float*)d_in[2];
    const float* b1  = (const float*)d_in[3];
    const float* W2  = (const float*)d_in[4];
    const float* b2  = (const float*)d_in[5];
    const float* W3  = (const float*)d_in[6];
    const float* b3  = (const float*)d_in[7];
    const float* Wn1 = (const float*)d_in[8];
    const float* bn1 = (const float*)d_in[9];
    const float* Wn2 = (const float*)d_in[10];
    const float* bn2 = (const float*)d_in[11];
    float*       out = (float*)d_out;

    cudaFuncSetAttribute(k_prep, cudaFuncAttributeMaxDynamicSharedMemorySize, SM_PREP_TOTAL);
    cudaFuncSetAttribute(k_edge, cudaFuncAttributeMaxDynamicSharedMemorySize, SM_EDGE_TOTAL);
    cudaFuncSetAttribute(k_node, cudaFuncAttributeMaxDynamicSharedMemorySize, SM_NODE_TOTAL);

    k_zero<<<512, 256>>>();
    k_deg<<<1024, 256>>>(ei);
    k_w3n<<<128, 128>>>(W3, b3, Wn1);
    k_prep<<<148, 512, SM_PREP_TOTAL>>>(h, W1, Wn1);
    k_edge<<<148, 512, SM_EDGE_TOTAL>>>(ei, b1, W2, b2);
    k_node<<<148, 512, SM_NODE_TOTAL>>>(bn1, Wn2, bn2, out);
}

// round 13
// speedup vs baseline: 1.2357x; 1.0400x over previous
#include <cuda_runtime.h>
#include <cuda_bf16.h>
#include <cuda_fp16.h>
#include <cstdint>

// Problem constants (fixed shapes)
#define V_N 50000
#define E_N 800000

// Scratch (static device arrays — no runtime allocation)
__device__ __half g_S[(size_t)V_N * 128];           // Σ relu(A2@W2+b2) per node, fp16
__device__ int    g_deg[V_N];                       // in-degree
__device__ __nv_bfloat16 g_PQ[(size_t)V_N * 256];   // [P | Q] per node, bf16
__device__ float  g_R[(size_t)V_N * 128];           // h @ Wn1_top (near-fp32)
__device__ __half g_W3n[128 * 128];                 // W3 @ Wn1_bot, fp16
__device__ float  g_bn3[128];                       // b3 @ Wn1_bot

// ============================================================================
// Warp-level MMA helpers (base PTX: ldmatrix sm_75+, mma.sync sm_80+)
// ============================================================================
__device__ __forceinline__ uint32_t smem_u32(const void* p) {
    uint32_t a;
    asm("{ .reg .u64 t; cvta.to.shared.u64 t, %1; cvt.u32.u64 %0, t; }"
        : "=r"(a) : "l"(p));
    return a;
}
__device__ __forceinline__ void ldsm_x4(uint32_t* r, uint32_t addr) {
    asm volatile("ldmatrix.sync.aligned.m8n8.x4.shared.b16 {%0,%1,%2,%3}, [%4];"
                 : "=r"(r[0]), "=r"(r[1]), "=r"(r[2]), "=r"(r[3]) : "r"(addr));
}
__device__ __forceinline__ void ldsm_x4_t(uint32_t* r, uint32_t addr) {
    asm volatile("ldmatrix.sync.aligned.m8n8.x4.trans.shared.b16 {%0,%1,%2,%3}, [%4];"
                 : "=r"(r[0]), "=r"(r[1]), "=r"(r[2]), "=r"(r[3]) : "r"(addr));
}
__device__ __forceinline__ void mma_bf16(float* d, const uint32_t* a, const uint32_t* b) {
    asm volatile(
        "mma.sync.aligned.m16n8k16.row.col.f32.bf16.bf16.f32 "
        "{%0,%1,%2,%3}, {%4,%5,%6,%7}, {%8,%9}, {%0,%1,%2,%3};"
        : "+f"(d[0]), "+f"(d[1]), "+f"(d[2]), "+f"(d[3])
        : "r"(a[0]), "r"(a[1]), "r"(a[2]), "r"(a[3]), "r"(b[0]), "r"(b[1]));
}
__device__ __forceinline__ void mma_f16(float* d, const uint32_t* a, const uint32_t* b) {
    asm volatile(
        "mma.sync.aligned.m16n8k16.row.col.f32.f16.f16.f32 "
        "{%0,%1,%2,%3}, {%4,%5,%6,%7}, {%8,%9}, {%0,%1,%2,%3};"
        : "+f"(d[0]), "+f"(d[1]), "+f"(d[2]), "+f"(d[3])
        : "r"(a[0]), "r"(a[1]), "r"(a[2]), "r"(a[3]), "r"(b[0]), "r"(b[1]));
}
__device__ __forceinline__ uint32_t pack2(float a, float b) {
    __nv_bfloat162 p = __floats2bfloat162_rn(a, b);
    return *(uint32_t*)&p;
}
// 16-byte vector fp16 reduction (sm_90+): 8 halves per op
__device__ __forceinline__ void red_add_v4h2(__half* p, uint4 v) {
    asm volatile("red.global.add.noftz.v4.f16x2 [%0], {%1, %2, %3, %4};"
                 :: "l"(p), "r"(v.x), "r"(v.y), "r"(v.z), "r"(v.w) : "memory");
}
// relu(bf16x2(p) + bf16x2(q) + bf16x2(b)) in fp32, repacked bf16x2
__device__ __forceinline__ uint32_t addrelu2(uint32_t p, uint32_t q, uint32_t b) {
    float2 fp = __bfloat1622float2(*(__nv_bfloat162*)&p);
    float2 fq = __bfloat1622float2(*(__nv_bfloat162*)&q);
    float2 fb = __bfloat1622float2(*(__nv_bfloat162*)&b);
    return pack2(fmaxf(fp.x + fq.x + fb.x, 0.f), fmaxf(fp.y + fq.y + fb.y, 0.f));
}

#define WPITCH 272   // b16 tile pitch for 128-col matrices
#define BPITCH 528   // b16 tile pitch for 256-col matrices

// Warp-tile GEMM (ACCUMULATES into d; caller zeroes). WP = weight pitch.
template <int NK, int AP, int WP, int F16>
__device__ __forceinline__ void gemm_tile(uint32_t abase, uint32_t wbase,
                                          int wr, int wc, int lane,
                                          float d[2][4][4]) {
    const int l15 = lane & 15;
    const int kh  = (lane >> 4) << 3;
#pragma unroll
    for (int ks = 0; ks < NK; ks++) {
        uint32_t a[2][4], b[4][2];
#pragma unroll
        for (int mi = 0; mi < 2; mi++) {
            uint32_t addr = abase + (uint32_t)((wr * 32 + mi * 16 + l15) * AP +
                                               (ks * 16 + kh) * 2);
            ldsm_x4(a[mi], addr);
        }
#pragma unroll
        for (int nj = 0; nj < 2; nj++) {
            uint32_t addr = wbase + (uint32_t)((ks * 16 + l15) * WP +
                                               (wc * 32 + nj * 16 + kh) * 2);
            uint32_t t[4];
            ldsm_x4_t(t, addr);
            b[2 * nj][0] = t[0]; b[2 * nj][1] = t[1];
            b[2 * nj + 1][0] = t[2]; b[2 * nj + 1][1] = t[3];
        }
#pragma unroll
        for (int mi = 0; mi < 2; mi++)
#pragma unroll
            for (int ni = 0; ni < 4; ni++) {
                if (F16) mma_f16(d[mi][ni], a[mi], b[ni]);
                else     mma_bf16(d[mi][ni], a[mi], b[ni]);
            }
    }
}
__device__ __forceinline__ void zero_d(float d[2][4][4]) {
#pragma unroll
    for (int mi = 0; mi < 2; mi++)
#pragma unroll
        for (int ni = 0; ni < 4; ni++)
#pragma unroll
            for (int x = 0; x < 4; x++) d[mi][ni][x] = 0.f;
}

// ---------------------------------------------------------------------------
// k_zero: zero g_S and g_deg
// ---------------------------------------------------------------------------
__global__ void k_zero() {
    const uint4 z = make_uint4(0, 0, 0, 0);
    const int nS = V_N * 128 / 8;
    for (int i = blockIdx.x * blockDim.x + threadIdx.x; i < nS;
         i += gridDim.x * blockDim.x)
        ((uint4*)g_S)[i] = z;
    const int nD = V_N / 4;
    for (int i = blockIdx.x * blockDim.x + threadIdx.x; i < nD;
         i += gridDim.x * blockDim.x)
        ((uint4*)g_deg)[i] = z;
}

// k_deg: in-degree histogram
__global__ void k_deg(const int* __restrict__ ei) {
    for (int i = blockIdx.x * blockDim.x + threadIdx.x; i < E_N;
         i += gridDim.x * blockDim.x)
        atomicAdd(&g_deg[ei[E_N + i]], 1);
}

// k_w3n: W3n = W3 @ Wn1_bot (fp32 -> fp16), bn3 = b3 @ Wn1_bot (fp32)
__global__ void k_w3n(const float* __restrict__ W3, const float* __restrict__ b3,
                      const float* __restrict__ Wn1) {
    const int n = threadIdx.x, k = blockIdx.x;
    float s = 0.f;
    for (int j = 0; j < 128; j++)
        s += W3[k * 128 + j] * Wn1[(128 + j) * 128 + n];
    g_W3n[k * 128 + n] = __float2half(s);
    if (k == 0) {
        float s2 = 0.f;
        for (int j = 0; j < 128; j++)
            s2 += b3[j] * Wn1[(128 + j) * 128 + n];
        g_bn3[n] = s2;
    }
}

// ---------------------------------------------------------------------------
// k_prep (merged): one h staging (hi/lo) per 128-row tile feeds
//   PQ = h@[W1_top | W1_bot]  (bf16, hi only)  -> g_PQ bf16
//   R  = h@Wn1_top 3-term split                -> g_R fp32
// ---------------------------------------------------------------------------
#define P_W1  0        // 128 x 528 = 67584 (bf16, 256 cols)
#define P_WH  67584
#define P_WL  102400
#define P_HH  137216
#define P_HL  172032
#define SM_PREP_TOTAL 206848

__global__ __launch_bounds__(512, 1) void k_prep(
    const float* __restrict__ h, const float* __restrict__ W1,
    const float* __restrict__ Wn1)
{
    extern __shared__ __align__(16) char sm[];
    const uint32_t sbase = smem_u32(sm);
    const int tid = threadIdx.x, wid = tid >> 5, lane = tid & 31;
    const int wr = wid & 3, wc = wid >> 2;
    const int g = lane >> 2, q = lane & 3;

    for (int i = tid; i < 128 * 256; i += 512) {
        int k = i >> 8, n = i & 255;
        float w = (n < 128) ? W1[k * 128 + n] : W1[(128 + k) * 128 + (n - 128)];
        *(__nv_bfloat16*)(sm + P_W1 + k * BPITCH + n * 2) = __float2bfloat16(w);
    }
    for (int i = tid; i < 128 * 128; i += 512) {
        int k = i >> 7, n = i & 127;
        float w = Wn1[k * 128 + n];
        __nv_bfloat16 whi = __float2bfloat16(w);
        *(__nv_bfloat16*)(sm + P_WH + k * WPITCH + n * 2) = whi;
        *(__nv_bfloat16*)(sm + P_WL + k * WPITCH + n * 2) =
            __float2bfloat16(w - __bfloat162float(whi));
    }
    __syncthreads();

    const float4* h4 = (const float4*)h;
    const int numTiles = (V_N + 127) / 128;   // 391
    float d[2][4][4];

    for (int tile = blockIdx.x; tile < numTiles; tile += gridDim.x) {
        const int n0 = tile * 128;
        __syncthreads();
        for (int i = tid; i < 128 * 32; i += 512) {
            int r = i >> 5, j = i & 31;
            int node = n0 + r;
            float4 v = (node < V_N) ? h4[(size_t)node * 32 + j]
                                    : make_float4(0.f, 0.f, 0.f, 0.f);
            __nv_bfloat16 h0 = __float2bfloat16(v.x), h1 = __float2bfloat16(v.y);
            __nv_bfloat16 h2 = __float2bfloat16(v.z), h3 = __float2bfloat16(v.w);
            uint2 uh, ul;
            uh.x = pack2(__bfloat162float(h0), __bfloat162float(h1));
            uh.y = pack2(__bfloat162float(h2), __bfloat162float(h3));
            ul.x = pack2(v.x - __bfloat162float(h0), v.y - __bfloat162float(h1));
            ul.y = pack2(v.z - __bfloat162float(h2), v.w - __bfloat162float(h3));
            *(uint2*)(sm + P_HH + r * WPITCH + j * 8) = uh;
            *(uint2*)(sm + P_HL + r * WPITCH + j * 8) = ul;
        }
        __syncthreads();

        // ---- PQ (two 128-col halves), bf16 hi only ----
#pragma unroll
        for (int half = 0; half < 2; half++) {
            zero_d(d);
            gemm_tile<8, WPITCH, BPITCH, 0>(sbase + P_HH,
                                            sbase + P_W1 + half * 256,
                                            wr, wc, lane, d);
#pragma unroll
            for (int mi = 0; mi < 2; mi++) {
                const int rA = wr * 32 + mi * 16 + g;
                const int nodeA = n0 + rA, nodeB = nodeA + 8;
#pragma unroll
                for (int ni = 0; ni < 4; ni++) {
                    const int c = half * 128 + wc * 32 + ni * 8 + 2 * q;
                    if (nodeA < V_N)
                        *(uint32_t*)&g_PQ[(size_t)nodeA * 256 + c] =
                            pack2(d[mi][ni][0], d[mi][ni][1]);
                    if (nodeB < V_N)
                        *(uint32_t*)&g_PQ[(size_t)nodeB * 256 + c] =
                            pack2(d[mi][ni][2], d[mi][ni][3]);
                }
            }
        }

        // ---- R: 3-term split ----
        zero_d(d);
        gemm_tile<8, WPITCH, WPITCH, 0>(sbase + P_HH, sbase + P_WH, wr, wc, lane, d);
        gemm_tile<8, WPITCH, WPITCH, 0>(sbase + P_HH, sbase + P_WL, wr, wc, lane, d);
        gemm_tile<8, WPITCH, WPITCH, 0>(sbase + P_HL, sbase + P_WH, wr, wc, lane, d);
#pragma unroll
        for (int mi = 0; mi < 2; mi++) {
            const int rA = wr * 32 + mi * 16 + g;
            const int nodeA = n0 + rA, nodeB = nodeA + 8;
#pragma unroll
            for (int ni = 0; ni < 4; ni++) {
                const int c = wc * 32 + ni * 8 + 2 * q;
                if (nodeA < V_N)
                    *(float2*)&g_R[(size_t)nodeA * 128 + c] =
                        make_float2(d[mi][ni][0], d[mi][ni][1]);
                if (nodeB < V_N)
                    *(float2*)&g_R[(size_t)nodeB * 128 + c] =
                        make_float2(d[mi][ni][2], d[mi][ni][3]);
            }
        }
    }
}

// ---------------------------------------------------------------------------
// k_edge: 64-edge tiles, 256 threads, TWO CTAs per SM (independent barriers
// hide gather latency + barrier stalls). 8 warps: 2(row) x 4(col) grid.
//   A2 = relu(P[src]+Q[dst]+b1);  S[dst] += relu(A2@W2+b2)
// W2 columns stored PERMUTED (tau) -> one red.v4.f16x2 (16B) per row per mi.
// ---------------------------------------------------------------------------
#define SM_B1BF 0        // 128 bf16 = 256B
#define SM_B2S  256      // 128 f32 = 512B (logical order)
#define SM_W2   768      // 128 x 272 = 34816 (permuted cols)
#define SM_A2A  35584    // 64 x 272 = 17408
#define SM_A2B  52992    // 17408
#define SM_EDGE_TOTAL 70400

__global__ __launch_bounds__(256, 2) void k_edge(
    const int* __restrict__ ei,
    const float* __restrict__ b1,
    const float* __restrict__ W2, const float* __restrict__ b2)
{
    extern __shared__ __align__(16) char sm[];
    float* b2s = (float*)(sm + SM_B2S);
    const uint32_t sbase = smem_u32(sm);
    const uint32_t sW2 = sbase + SM_W2;

    const int tid = threadIdx.x, wid = tid >> 5, lane = tid & 31;
    const int wr = wid & 1, wc = wid >> 1;   // 2x4 warp grid
    const int g = lane >> 2, q = lane & 3;

    // Stage W2 with column permutation tau
    for (int i = tid; i < 128 * 128; i += 256) {
        int k = i >> 7, n = i & 127;
        int t = n & 31, base = n & ~31;
        int q2 = t >> 3, rem = t & 7, ni2 = rem >> 1, jj = rem & 1;
        int tcol = base + ni2 * 8 + 2 * q2 + jj;   // stored position of logical n
        *(__nv_bfloat16*)(sm + SM_W2 + k * WPITCH + tcol * 2) = __float2bfloat16(W2[i]);
    }
    if (tid < 128) {
        b2s[tid] = b2[tid];   // logical order
        *(__nv_bfloat16*)(sm + SM_B1BF + tid * 2) = __float2bfloat16(b1[tid]);
    }
    __syncthreads();

    const int jg = tid & 15;                  // gather: 16B col group
    const int r0 = tid >> 4;                  // gather: base row (0..15)
    const uint4 Bv = *(const uint4*)(sm + SM_B1BF + jg * 16);
    const int cb = wc * 32 + 8 * q;           // scatter: logical col base (8 cols)

    const int numTiles = E_N / 64;   // 12500
    float d[2][4][4];
    int buf = 0;

    // Prologue: gather first tile into buffer A
    int tile = blockIdx.x;
    if (tile < numTiles) {
        const int e0 = tile * 64;
        char* a2p = sm + SM_A2A;
#pragma unroll
        for (int k = 0; k < 4; k++) {
            int r = r0 + 16 * k;
            int s = ei[e0 + r], t = ei[E_N + e0 + r];
            uint4 P = *(const uint4*)&g_PQ[(size_t)s * 256 + jg * 8];
            uint4 Q = *(const uint4*)&g_PQ[(size_t)t * 256 + 128 + jg * 8];
            uint4 o;
            o.x = addrelu2(P.x, Q.x, Bv.x);
            o.y = addrelu2(P.y, Q.y, Bv.y);
            o.z = addrelu2(P.z, Q.z, Bv.z);
            o.w = addrelu2(P.w, Q.w, Bv.w);
            *(uint4*)(a2p + r * WPITCH + jg * 16) = o;
        }
    }

    for (; tile < numTiles; tile += gridDim.x) {
        const int e0 = tile * 64;
        __syncthreads();   // A2[buf] ready; other buffer free

        // ---- GEMM2 on A2[buf] (output cols permuted) ----
        zero_d(d);
        gemm_tile<8, WPITCH, WPITCH, 0>(sbase + (buf ? SM_A2B : SM_A2A), sW2,
                                        wr, wc, lane, d);

        // ---- scatter: one 16B red per row per mi ----
        // fragment (ni, j) holds logical col cb + 2*ni + j
        {
            const int rA = wr * 32 + g;
            float2 bb0 = *(const float2*)&b2s[cb + 0];
            float2 bb1 = *(const float2*)&b2s[cb + 2];
            float2 bb2 = *(const float2*)&b2s[cb + 4];
            float2 bb3 = *(const float2*)&b2s[cb + 6];
#pragma unroll
            for (int mi = 0; mi < 2; mi++) {
                const int rr = rA + mi * 16;
                const int d0 = ei[E_N + e0 + rr], d1 = ei[E_N + e0 + rr + 8];
                __half2 a0 = __floats2half2_rn(fmaxf(d[mi][0][0] + bb0.x, 0.f),
                                               fmaxf(d[mi][0][1] + bb0.y, 0.f));
                __half2 a1 = __floats2half2_rn(fmaxf(d[mi][1][0] + bb1.x, 0.f),
                                               fmaxf(d[mi][1][1] + bb1.y, 0.f));
                __half2 a2 = __floats2half2_rn(fmaxf(d[mi][2][0] + bb2.x, 0.f),
                                               fmaxf(d[mi][2][1] + bb2.y, 0.f));
                __half2 a3 = __floats2half2_rn(fmaxf(d[mi][3][0] + bb3.x, 0.f),
                                               fmaxf(d[mi][3][1] + bb3.y, 0.f));
                uint4 v0 = make_uint4(*(uint32_t*)&a0, *(uint32_t*)&a1,
                                      *(uint32_t*)&a2, *(uint32_t*)&a3);
                red_add_v4h2(&g_S[(size_t)d0 * 128 + cb], v0);

                __half2 c0 = __floats2half2_rn(fmaxf(d[mi][0][2] + bb0.x, 0.f),
                                               fmaxf(d[mi][0][3] + bb0.y, 0.f));
                __half2 c1 = __floats2half2_rn(fmaxf(d[mi][1][2] + bb1.x, 0.f),
                                               fmaxf(d[mi][1][3] + bb1.y, 0.f));
                __half2 c2 = __floats2half2_rn(fmaxf(d[mi][2][2] + bb2.x, 0.f),
                                               fmaxf(d[mi][2][3] + bb2.y, 0.f));
                __half2 c3 = __floats2half2_rn(fmaxf(d[mi][3][2] + bb3.x, 0.f),
                                               fmaxf(d[mi][3][3] + bb3.y, 0.f));
                uint4 v1 = make_uint4(*(uint32_t*)&c0, *(uint32_t*)&c1,
                                      *(uint32_t*)&c2, *(uint32_t*)&c3);
                red_add_v4h2(&g_S[(size_t)d1 * 128 + cb], v1);
            }
        }

        // ---- gather next tile into the other buffer ----
        const int nt = tile + gridDim.x;
        if (nt < numTiles) {
            const int ne0 = nt * 64;
            char* a2p = sm + (buf ? SM_A2A : SM_A2B);
#pragma unroll
            for (int k = 0; k < 4; k++) {
                int r = r0 + 16 * k;
                int s = ei[ne0 + r], t = ei[E_N + ne0 + r];
                uint4 P = *(const uint4*)&g_PQ[(size_t)s * 256 + jg * 8];
                uint4 Q = *(const uint4*)&g_PQ[(size_t)t * 256 + 128 + jg * 8];
                uint4 o;
                o.x = addrelu2(P.x, Q.x, Bv.x);
                o.y = addrelu2(P.y, Q.y, Bv.y);
                o.z = addrelu2(P.z, Q.z, Bv.z);
                o.w = addrelu2(P.w, Q.w, Bv.w);
                *(uint4*)(a2p + r * WPITCH + jg * 16) = o;
            }
        }
        buf ^= 1;
    }
}

// ---------------------------------------------------------------------------
// k_node: T = relu(R + S@W3n + deg*bn3 + bn1); out = T@Wn2 (3-term split).
// ---------------------------------------------------------------------------
#define N_B1  0         // bn1 512B
#define N_B2  512       // bn2 512B
#define N_B3  1024      // bn3 512B
#define N_W3N 1536      // fp16 W3n, 128 x 272 = 34816
#define N_W2H 36352
#define N_W2L 71168
#define N_XS  105984    // S staged fp16, 128 x 272
#define N_THI 140800
#define N_TLO 175616
#define SM_NODE_TOTAL 210432

__global__ __launch_bounds__(512, 1) void k_node(
    const float* __restrict__ bn1,
    const float* __restrict__ Wn2, const float* __restrict__ bn2,
    float* __restrict__ out)
{
    extern __shared__ __align__(16) char sm[];
    float* bn1s = (float*)(sm + N_B1);
    float* bn2s = (float*)(sm + N_B2);
    float* bn3s = (float*)(sm + N_B3);
    const uint32_t sbase = smem_u32(sm);
    const int tid = threadIdx.x, wid = tid >> 5, lane = tid & 31;
    const int wr = wid & 3, wc = wid >> 2;
    const int g = lane >> 2, q = lane & 3;

    for (int i = tid; i < 128 * 128; i += 512) {
        int k = i >> 7, n = i & 127;
        *(__half*)(sm + N_W3N + k * WPITCH + n * 2) = g_W3n[i];
        float w2 = Wn2[i];
        __nv_bfloat16 whi = __float2bfloat16(w2);
        *(__nv_bfloat16*)(sm + N_W2H + k * WPITCH + n * 2) = whi;
        *(__nv_bfloat16*)(sm + N_W2L + k * WPITCH + n * 2) =
            __float2bfloat16(w2 - __bfloat162float(whi));
    }
    if (tid < 128) { bn1s[tid] = bn1[tid]; bn2s[tid] = bn2[tid]; bn3s[tid] = g_bn3[tid]; }
    __syncthreads();

    float d[2][4][4];
    const int numTiles = (V_N + 127) / 128;   // 391

    for (int tile = blockIdx.x; tile < numTiles; tile += gridDim.x) {
        const int n0 = tile * 128;
        __syncthreads();
        for (int i = tid; i < 128 * 16; i += 512) {
            int r = i >> 4, j = i & 15;
            int node = n0 + r;
            uint4 v = (node < V_N) ? *(const uint4*)&g_S[(size_t)node * 128 + j * 8]
                                   : make_uint4(0, 0, 0, 0);
            *(uint4*)(sm + N_XS + r * WPITCH + j * 16) = v;
        }
        __syncthreads();

        // GEMM A: S @ W3n (fp16)
        zero_d(d);
        gemm_tile<8, WPITCH, WPITCH, 1>(sbase + N_XS, sbase + N_W3N, wr, wc, lane, d);

        // T = relu(d + R + deg*bn3 + bn1), split -> Thi/Tlo
#pragma unroll
        for (int mi = 0; mi < 2; mi++) {
            const int rA = wr * 32 + mi * 16 + g;
            const int nodeA = n0 + rA, nodeB = nodeA + 8;
            const float degA = (nodeA < V_N) ? (float)g_deg[nodeA] : 0.f;
            const float degB = (nodeB < V_N) ? (float)g_deg[nodeB] : 0.f;
#pragma unroll
            for (int ni = 0; ni < 4; ni++) {
                const int c = wc * 32 + ni * 8 + 2 * q;
                float2 bb = *(const float2*)&bn1s[c];
                float2 b3v = *(const float2*)&bn3s[c];
                float2 r0 = (nodeA < V_N) ? *(const float2*)&g_R[(size_t)nodeA * 128 + c]
                                          : make_float2(0.f, 0.f);
                float2 r1 = (nodeB < V_N) ? *(const float2*)&g_R[(size_t)nodeB * 128 + c]
                                          : make_float2(0.f, 0.f);
                float t0 = fmaxf(d[mi][ni][0] + r0.x + degA * b3v.x + bb.x, 0.f);
                float t1 = fmaxf(d[mi][ni][1] + r0.y + degA * b3v.y + bb.y, 0.f);
                float t2 = fmaxf(d[mi][ni][2] + r1.x + degB * b3v.x + bb.x, 0.f);
                float t3 = fmaxf(d[mi][ni][3] + r1.y + degB * b3v.y + bb.y, 0.f);
                __nv_bfloat16 h0 = __float2bfloat16(t0), h1 = __float2bfloat16(t1);
                __nv_bfloat16 h2 = __float2bfloat16(t2), h3 = __float2bfloat16(t3);
                *(uint32_t*)(sm + N_THI + rA * WPITCH + c * 2) =
                    pack2(__bfloat162float(h0), __bfloat162float(h1));
                *(uint32_t*)(sm + N_THI + (rA + 8) * WPITCH + c * 2) =
                    pack2(__bfloat162float(h2), __bfloat162float(h3));
                *(uint32_t*)(sm + N_TLO + rA * WPITCH + c * 2) =
                    pack2(t0 - __bfloat162float(h0), t1 - __bfloat162float(h1));
                *(uint32_t*)(sm + N_TLO + (rA + 8) * WPITCH + c * 2) =
                    pack2(t2 - __bfloat162float(h2), t3 - __bfloat162float(h3));
            }
        }
        __syncthreads();

        // GEMM B: out = Thi@W2hi + Thi@W2lo + Tlo@W2hi + bn2
        zero_d(d);
        gemm_tile<8, WPITCH, WPITCH, 0>(sbase + N_THI, sbase + N_W2H, wr, wc, lane, d);
        gemm_tile<8, WPITCH, WPITCH, 0>(sbase + N_THI, sbase + N_W2L, wr, wc, lane, d);
        gemm_tile<8, WPITCH, WPITCH, 0>(sbase + N_TLO, sbase + N_W2H, wr, wc, lane, d);

#pragma unroll
        for (int mi = 0; mi < 2; mi++) {
            const int rA = wr * 32 + mi * 16 + g;
            const int nodeA = n0 + rA, nodeB = nodeA + 8;
#pragma unroll
            for (int ni = 0; ni < 4; ni++) {
                const int c = wc * 32 + ni * 8 + 2 * q;
                float2 bb = *(const float2*)&bn2s[c];
                if (nodeA < V_N)
                    *(float2*)&out[(size_t)nodeA * 128 + c] =
                        make_float2(d[mi][ni][0] + bb.x, d[mi][ni][1] + bb.y);
                if (nodeB < V_N)
                    *(float2*)&out[(size_t)nodeB * 128 + c] =
                        make_float2(d[mi][ni][2] + bb.x, d[mi][ni][3] + bb.y);
            }
        }
    }
}

// ---------------------------------------------------------------------------
extern "C" void kernel_launch(void* const* d_in, const int* in_sizes, int n_in,
                              void* d_out, int out_size) {
    const float* h   = (const float*)d_in[0];
    const int*   ei  = (const int*)d_in[1];   // int32 (JAX x64 disabled)
    const float* W1  = (const float*)d_in[2];
    const float* b1  = (const float*)d_in[3];
    const float* W2  = (const float*)d_in[4];
    const float* b2  = (const float*)d_in[5];
    const float* W3  = (const float*)d_in[6];
    const float* b3  = (const float*)d_in[7];
    const float* Wn1 = (const float*)d_in[8];
    const float* bn1 = (const float*)d_in[9];
    const float* Wn2 = (const float*)d_in[10];
    const float* bn2 = (const float*)d_in[11];
    float*       out = (float*)d_out;

    cudaFuncSetAttribute(k_prep, cudaFuncAttributeMaxDynamicSharedMemorySize, SM_PREP_TOTAL);
    cudaFuncSetAttribute(k_edge, cudaFuncAttributeMaxDynamicSharedMemorySize, SM_EDGE_TOTAL);
    cudaFuncSetAttribute(k_node, cudaFuncAttributeMaxDynamicSharedMemorySize, SM_NODE_TOTAL);

    k_zero<<<512, 256>>>();
    k_deg<<<1024, 256>>>(ei);
    k_w3n<<<128, 128>>>(W3, b3, Wn1);
    k_prep<<<148, 512, SM_PREP_TOTAL>>>(h, W1, Wn1);
    k_edge<<<296, 256, SM_EDGE_TOTAL>>>(ei, b1, W2, b2);
    k_node<<<148, 512, SM_NODE_TOTAL>>>(bn1, Wn2, bn2, out);
}

// round 14
// speedup vs baseline: 1.2805x; 1.0362x over previous
#include <cuda_runtime.h>
#include <cuda_bf16.h>
#include <cuda_fp16.h>
#include <cstdint>

// Problem constants (fixed shapes)
#define V_N 50000
#define E_N 800000

// Scratch (static device arrays — no runtime allocation)
__device__ __half g_S[(size_t)V_N * 128];           // Σ relu(A2@W2+b2) per node, fp16
__device__ int    g_deg[V_N];                       // in-degree
__device__ __nv_bfloat16 g_PQ[(size_t)V_N * 256];   // [P | Q] per node, bf16
__device__ float  g_R[(size_t)V_N * 128];           // h @ Wn1_top (near-fp32)
__device__ __half g_W3n[128 * 128];                 // W3 @ Wn1_bot, fp16
__device__ float  g_bn3[128];                       // b3 @ Wn1_bot

// ============================================================================
// Warp-level MMA helpers (base PTX: ldmatrix sm_75+, mma.sync sm_80+)
// ============================================================================
__device__ __forceinline__ uint32_t smem_u32(const void* p) {
    uint32_t a;
    asm("{ .reg .u64 t; cvta.to.shared.u64 t, %1; cvt.u32.u64 %0, t; }"
        : "=r"(a) : "l"(p));
    return a;
}
__device__ __forceinline__ void ldsm_x4(uint32_t* r, uint32_t addr) {
    asm volatile("ldmatrix.sync.aligned.m8n8.x4.shared.b16 {%0,%1,%2,%3}, [%4];"
                 : "=r"(r[0]), "=r"(r[1]), "=r"(r[2]), "=r"(r[3]) : "r"(addr));
}
__device__ __forceinline__ void ldsm_x4_t(uint32_t* r, uint32_t addr) {
    asm volatile("ldmatrix.sync.aligned.m8n8.x4.trans.shared.b16 {%0,%1,%2,%3}, [%4];"
                 : "=r"(r[0]), "=r"(r[1]), "=r"(r[2]), "=r"(r[3]) : "r"(addr));
}
__device__ __forceinline__ void mma_bf16(float* d, const uint32_t* a, const uint32_t* b) {
    asm volatile(
        "mma.sync.aligned.m16n8k16.row.col.f32.bf16.bf16.f32 "
        "{%0,%1,%2,%3}, {%4,%5,%6,%7}, {%8,%9}, {%0,%1,%2,%3};"
        : "+f"(d[0]), "+f"(d[1]), "+f"(d[2]), "+f"(d[3])
        : "r"(a[0]), "r"(a[1]), "r"(a[2]), "r"(a[3]), "r"(b[0]), "r"(b[1]));
}
__device__ __forceinline__ void mma_f16(float* d, const uint32_t* a, const uint32_t* b) {
    asm volatile(
        "mma.sync.aligned.m16n8k16.row.col.f32.f16.f16.f32 "
        "{%0,%1,%2,%3}, {%4,%5,%6,%7}, {%8,%9}, {%0,%1,%2,%3};"
        : "+f"(d[0]), "+f"(d[1]), "+f"(d[2]), "+f"(d[3])
        : "r"(a[0]), "r"(a[1]), "r"(a[2]), "r"(a[3]), "r"(b[0]), "r"(b[1]));
}
__device__ __forceinline__ uint32_t pack2(float a, float b) {
    __nv_bfloat162 p = __floats2bfloat162_rn(a, b);
    return *(uint32_t*)&p;
}
// 16-byte vector fp16 reduction (sm_90+): 8 halves per op
__device__ __forceinline__ void red_add_v4h2(__half* p, uint4 v) {
    asm volatile("red.global.add.noftz.v4.f16x2 [%0], {%1, %2, %3, %4};"
                 :: "l"(p), "r"(v.x), "r"(v.y), "r"(v.z), "r"(v.w) : "memory");
}
// relu(bf16x2(p) + bf16x2(q) + bf16x2(b)) in fp32, repacked bf16x2
__device__ __forceinline__ uint32_t addrelu2(uint32_t p, uint32_t q, uint32_t b) {
    float2 fp = __bfloat1622float2(*(__nv_bfloat162*)&p);
    float2 fq = __bfloat1622float2(*(__nv_bfloat162*)&q);
    float2 fb = __bfloat1622float2(*(__nv_bfloat162*)&b);
    return pack2(fmaxf(fp.x + fq.x + fb.x, 0.f), fmaxf(fp.y + fq.y + fb.y, 0.f));
}

#define WPITCH 272   // b16 tile pitch for 128-col matrices
#define BPITCH 528   // b16 tile pitch for 256-col matrices

// Warp-tile GEMM (ACCUMULATES into d; caller zeroes). WP = weight pitch.
template <int NK, int AP, int WP, int F16>
__device__ __forceinline__ void gemm_tile(uint32_t abase, uint32_t wbase,
                                          int wr, int wc, int lane,
                                          float d[2][4][4]) {
    const int l15 = lane & 15;
    const int kh  = (lane >> 4) << 3;
#pragma unroll
    for (int ks = 0; ks < NK; ks++) {
        uint32_t a[2][4], b[4][2];
#pragma unroll
        for (int mi = 0; mi < 2; mi++) {
            uint32_t addr = abase + (uint32_t)((wr * 32 + mi * 16 + l15) * AP +
                                               (ks * 16 + kh) * 2);
            ldsm_x4(a[mi], addr);
        }
#pragma unroll
        for (int nj = 0; nj < 2; nj++) {
            uint32_t addr = wbase + (uint32_t)((ks * 16 + l15) * WP +
                                               (wc * 32 + nj * 16 + kh) * 2);
            uint32_t t[4];
            ldsm_x4_t(t, addr);
            b[2 * nj][0] = t[0]; b[2 * nj][1] = t[1];
            b[2 * nj + 1][0] = t[2]; b[2 * nj + 1][1] = t[3];
        }
#pragma unroll
        for (int mi = 0; mi < 2; mi++)
#pragma unroll
            for (int ni = 0; ni < 4; ni++) {
                if (F16) mma_f16(d[mi][ni], a[mi], b[ni]);
                else     mma_bf16(d[mi][ni], a[mi], b[ni]);
            }
    }
}
__device__ __forceinline__ void zero_d(float d[2][4][4]) {
#pragma unroll
    for (int mi = 0; mi < 2; mi++)
#pragma unroll
        for (int ni = 0; ni < 4; ni++)
#pragma unroll
            for (int x = 0; x < 4; x++) d[mi][ni][x] = 0.f;
}

// ---------------------------------------------------------------------------
// k_zero: zero g_S and g_deg
// ---------------------------------------------------------------------------
__global__ void k_zero() {
    const uint4 z = make_uint4(0, 0, 0, 0);
    const int nS = V_N * 128 / 8;
    for (int i = blockIdx.x * blockDim.x + threadIdx.x; i < nS;
         i += gridDim.x * blockDim.x)
        ((uint4*)g_S)[i] = z;
    const int nD = V_N / 4;
    for (int i = blockIdx.x * blockDim.x + threadIdx.x; i < nD;
         i += gridDim.x * blockDim.x)
        ((uint4*)g_deg)[i] = z;
}

// k_deg: in-degree histogram
__global__ void k_deg(const int* __restrict__ ei) {
    for (int i = blockIdx.x * blockDim.x + threadIdx.x; i < E_N;
         i += gridDim.x * blockDim.x)
        atomicAdd(&g_deg[ei[E_N + i]], 1);
}

// k_w3n: W3n = W3 @ Wn1_bot (fp32 -> fp16), bn3 = b3 @ Wn1_bot (fp32)
__global__ void k_w3n(const float* __restrict__ W3, const float* __restrict__ b3,
                      const float* __restrict__ Wn1) {
    const int n = threadIdx.x, k = blockIdx.x;
    float s = 0.f;
    for (int j = 0; j < 128; j++)
        s += W3[k * 128 + j] * Wn1[(128 + j) * 128 + n];
    g_W3n[k * 128 + n] = __float2half(s);
    if (k == 0) {
        float s2 = 0.f;
        for (int j = 0; j < 128; j++)
            s2 += b3[j] * Wn1[(128 + j) * 128 + n];
        g_bn3[n] = s2;
    }
}

// ---------------------------------------------------------------------------
// k_prep (merged): one h staging (hi/lo) per 128-row tile feeds
//   PQ = h@[W1_top | W1_bot]  (bf16 hi, ONE pass, 32x64 warp tiles) -> g_PQ
//   R  = h@Wn1_top 3-term split (HH a-frags loaded once for WH+WL)  -> g_R
// ---------------------------------------------------------------------------
#define P_W1  0        // 128 x 528 = 67584 (bf16, 256 cols)
#define P_WH  67584
#define P_WL  102400
#define P_HH  137216
#define P_HL  172032
#define SM_PREP_TOTAL 206848

__global__ __launch_bounds__(512, 1) void k_prep(
    const float* __restrict__ h, const float* __restrict__ W1,
    const float* __restrict__ Wn1)
{
    extern __shared__ __align__(16) char sm[];
    const uint32_t sbase = smem_u32(sm);
    const int tid = threadIdx.x, wid = tid >> 5, lane = tid & 31;
    const int wr = wid & 3, wc = wid >> 2;   // 4x4 warp grid
    const int l15 = lane & 15, kh = (lane >> 4) << 3;
    const int g = lane >> 2, q = lane & 3;

    for (int i = tid; i < 128 * 256; i += 512) {
        int k = i >> 8, n = i & 255;
        float w = (n < 128) ? W1[k * 128 + n] : W1[(128 + k) * 128 + (n - 128)];
        *(__nv_bfloat16*)(sm + P_W1 + k * BPITCH + n * 2) = __float2bfloat16(w);
    }
    for (int i = tid; i < 128 * 128; i += 512) {
        int k = i >> 7, n = i & 127;
        float w = Wn1[k * 128 + n];
        __nv_bfloat16 whi = __float2bfloat16(w);
        *(__nv_bfloat16*)(sm + P_WH + k * WPITCH + n * 2) = whi;
        *(__nv_bfloat16*)(sm + P_WL + k * WPITCH + n * 2) =
            __float2bfloat16(w - __bfloat162float(whi));
    }
    __syncthreads();

    const float4* h4 = (const float4*)h;
    const int numTiles = (V_N + 127) / 128;   // 391

    for (int tile = blockIdx.x; tile < numTiles; tile += gridDim.x) {
        const int n0 = tile * 128;
        __syncthreads();
        for (int i = tid; i < 128 * 32; i += 512) {
            int r = i >> 5, j = i & 31;
            int node = n0 + r;
            float4 v = (node < V_N) ? h4[(size_t)node * 32 + j]
                                    : make_float4(0.f, 0.f, 0.f, 0.f);
            __nv_bfloat16 h0 = __float2bfloat16(v.x), h1 = __float2bfloat16(v.y);
            __nv_bfloat16 h2 = __float2bfloat16(v.z), h3 = __float2bfloat16(v.w);
            uint2 uh, ul;
            uh.x = pack2(__bfloat162float(h0), __bfloat162float(h1));
            uh.y = pack2(__bfloat162float(h2), __bfloat162float(h3));
            ul.x = pack2(v.x - __bfloat162float(h0), v.y - __bfloat162float(h1));
            ul.y = pack2(v.z - __bfloat162float(h2), v.w - __bfloat162float(h3));
            *(uint2*)(sm + P_HH + r * WPITCH + j * 8) = uh;
            *(uint2*)(sm + P_HL + r * WPITCH + j * 8) = ul;
        }
        __syncthreads();

        // ---- PQ: single pass, warp tile 32 rows x 64 cols ----
        {
            float dq[2][8][4];
#pragma unroll
            for (int mi = 0; mi < 2; mi++)
#pragma unroll
                for (int ni = 0; ni < 8; ni++)
#pragma unroll
                    for (int x = 0; x < 4; x++) dq[mi][ni][x] = 0.f;

#pragma unroll
            for (int ks = 0; ks < 8; ks++) {
                uint32_t a[2][4], b[8][2];
#pragma unroll
                for (int mi = 0; mi < 2; mi++) {
                    uint32_t addr = sbase + P_HH +
                        (uint32_t)((wr * 32 + mi * 16 + l15) * WPITCH +
                                   (ks * 16 + kh) * 2);
                    ldsm_x4(a[mi], addr);
                }
#pragma unroll
                for (int nj = 0; nj < 4; nj++) {
                    uint32_t addr = sbase + P_W1 +
                        (uint32_t)((ks * 16 + l15) * BPITCH +
                                   (wc * 64 + nj * 16 + kh) * 2);
                    uint32_t t[4];
                    ldsm_x4_t(t, addr);
                    b[2 * nj][0] = t[0]; b[2 * nj][1] = t[1];
                    b[2 * nj + 1][0] = t[2]; b[2 * nj + 1][1] = t[3];
                }
#pragma unroll
                for (int mi = 0; mi < 2; mi++)
#pragma unroll
                    for (int ni = 0; ni < 8; ni++)
                        mma_bf16(dq[mi][ni], a[mi], b[ni]);
            }

#pragma unroll
            for (int mi = 0; mi < 2; mi++) {
                const int rA = wr * 32 + mi * 16 + g;
                const int nodeA = n0 + rA, nodeB = nodeA + 8;
#pragma unroll
                for (int ni = 0; ni < 8; ni++) {
                    const int c = wc * 64 + ni * 8 + 2 * q;
                    if (nodeA < V_N)
                        *(uint32_t*)&g_PQ[(size_t)nodeA * 256 + c] =
                            pack2(dq[mi][ni][0], dq[mi][ni][1]);
                    if (nodeB < V_N)
                        *(uint32_t*)&g_PQ[(size_t)nodeB * 256 + c] =
                            pack2(dq[mi][ni][2], dq[mi][ni][3]);
                }
            }
        }

        // ---- R: 3-term split; HH a-frags shared between WH and WL ----
        {
            float d[2][4][4];
            zero_d(d);
#pragma unroll
            for (int ks = 0; ks < 8; ks++) {
                uint32_t a[2][4], b[4][2];
#pragma unroll
                for (int mi = 0; mi < 2; mi++) {
                    uint32_t addr = sbase + P_HH +
                        (uint32_t)((wr * 32 + mi * 16 + l15) * WPITCH +
                                   (ks * 16 + kh) * 2);
                    ldsm_x4(a[mi], addr);
                }
                // WH
#pragma unroll
                for (int nj = 0; nj < 2; nj++) {
                    uint32_t addr = sbase + P_WH +
                        (uint32_t)((ks * 16 + l15) * WPITCH +
                                   (wc * 32 + nj * 16 + kh) * 2);
                    uint32_t t[4];
                    ldsm_x4_t(t, addr);
                    b[2 * nj][0] = t[0]; b[2 * nj][1] = t[1];
                    b[2 * nj + 1][0] = t[2]; b[2 * nj + 1][1] = t[3];
                }
#pragma unroll
                for (int mi = 0; mi < 2; mi++)
#pragma unroll
                    for (int ni = 0; ni < 4; ni++)
                        mma_bf16(d[mi][ni], a[mi], b[ni]);
                // WL (same a-frags)
#pragma unroll
                for (int nj = 0; nj < 2; nj++) {
                    uint32_t addr = sbase + P_WL +
                        (uint32_t)((ks * 16 + l15) * WPITCH +
                                   (wc * 32 + nj * 16 + kh) * 2);
                    uint32_t t[4];
                    ldsm_x4_t(t, addr);
                    b[2 * nj][0] = t[0]; b[2 * nj][1] = t[1];
                    b[2 * nj + 1][0] = t[2]; b[2 * nj + 1][1] = t[3];
                }
#pragma unroll
                for (int mi = 0; mi < 2; mi++)
#pragma unroll
                    for (int ni = 0; ni < 4; ni++)
                        mma_bf16(d[mi][ni], a[mi], b[ni]);
            }
            // HL @ WH
            gemm_tile<8, WPITCH, WPITCH, 0>(sbase + P_HL, sbase + P_WH,
                                            wr, wc, lane, d);

#pragma unroll
            for (int mi = 0; mi < 2; mi++) {
                const int rA = wr * 32 + mi * 16 + g;
                const int nodeA = n0 + rA, nodeB = nodeA + 8;
#pragma unroll
                for (int ni = 0; ni < 4; ni++) {
                    const int c = wc * 32 + ni * 8 + 2 * q;
                    if (nodeA < V_N)
                        *(float2*)&g_R[(size_t)nodeA * 128 + c] =
                            make_float2(d[mi][ni][0], d[mi][ni][1]);
                    if (nodeB < V_N)
                        *(float2*)&g_R[(size_t)nodeB * 128 + c] =
                            make_float2(d[mi][ni][2], d[mi][ni][3]);
                }
            }
        }
    }
}

// ---------------------------------------------------------------------------
// k_edge: 64-edge tiles, 256 threads, TWO CTAs per SM.
//   A2 = relu(P[src]+Q[dst]+b1);  S[dst] += relu(A2@W2+b2)
// W2 columns stored PERMUTED (tau) -> one red.v4.f16x2 (16B) per row per mi.
// dst indices prefetched before GEMM2.
// ---------------------------------------------------------------------------
#define SM_B1BF 0        // 128 bf16 = 256B
#define SM_B2S  256      // 128 f32 = 512B (logical order)
#define SM_W2   768      // 128 x 272 = 34816 (permuted cols)
#define SM_A2A  35584    // 64 x 272 = 17408
#define SM_A2B  52992    // 17408
#define SM_EDGE_TOTAL 70400

__global__ __launch_bounds__(256, 2) void k_edge(
    const int* __restrict__ ei,
    const float* __restrict__ b1,
    const float* __restrict__ W2, const float* __restrict__ b2)
{
    extern __shared__ __align__(16) char sm[];
    float* b2s = (float*)(sm + SM_B2S);
    const uint32_t sbase = smem_u32(sm);
    const uint32_t sW2 = sbase + SM_W2;

    const int tid = threadIdx.x, wid = tid >> 5, lane = tid & 31;
    const int wr = wid & 1, wc = wid >> 1;   // 2x4 warp grid
    const int g = lane >> 2, q = lane & 3;

    // Stage W2 with column permutation tau
    for (int i = tid; i < 128 * 128; i += 256) {
        int k = i >> 7, n = i & 127;
        int t = n & 31, base = n & ~31;
        int q2 = t >> 3, rem = t & 7, ni2 = rem >> 1, jj = rem & 1;
        int tcol = base + ni2 * 8 + 2 * q2 + jj;   // stored position of logical n
        *(__nv_bfloat16*)(sm + SM_W2 + k * WPITCH + tcol * 2) = __float2bfloat16(W2[i]);
    }
    if (tid < 128) {
        b2s[tid] = b2[tid];   // logical order
        *(__nv_bfloat16*)(sm + SM_B1BF + tid * 2) = __float2bfloat16(b1[tid]);
    }
    __syncthreads();

    const int jg = tid & 15;                  // gather: 16B col group
    const int r0 = tid >> 4;                  // gather: base row (0..15)
    const uint4 Bv = *(const uint4*)(sm + SM_B1BF + jg * 16);
    const int cb = wc * 32 + 8 * q;           // scatter: logical col base (8 cols)

    const int numTiles = E_N / 64;   // 12500
    float d[2][4][4];
    int buf = 0;

    // Prologue: gather first tile into buffer A
    int tile = blockIdx.x;
    if (tile < numTiles) {
        const int e0 = tile * 64;
        char* a2p = sm + SM_A2A;
#pragma unroll
        for (int k = 0; k < 4; k++) {
            int r = r0 + 16 * k;
            int s = ei[e0 + r], t = ei[E_N + e0 + r];
            uint4 P = *(const uint4*)&g_PQ[(size_t)s * 256 + jg * 8];
            uint4 Q = *(const uint4*)&g_PQ[(size_t)t * 256 + 128 + jg * 8];
            uint4 o;
            o.x = addrelu2(P.x, Q.x, Bv.x);
            o.y = addrelu2(P.y, Q.y, Bv.y);
            o.z = addrelu2(P.z, Q.z, Bv.z);
            o.w = addrelu2(P.w, Q.w, Bv.w);
            *(uint4*)(a2p + r * WPITCH + jg * 16) = o;
        }
    }

    for (; tile < numTiles; tile += gridDim.x) {
        const int e0 = tile * 64;
        const int rA = wr * 32 + g;

        // Prefetch scatter destinations (hide LDG latency behind GEMM2)
        int pd0 = ei[E_N + e0 + rA];
        int pd1 = ei[E_N + e0 + rA + 8];
        int pd2 = ei[E_N + e0 + rA + 16];
        int pd3 = ei[E_N + e0 + rA + 24];

        __syncthreads();   // A2[buf] ready; other buffer free

        // ---- GEMM2 on A2[buf] (output cols permuted) ----
        zero_d(d);
        gemm_tile<8, WPITCH, WPITCH, 0>(sbase + (buf ? SM_A2B : SM_A2A), sW2,
                                        wr, wc, lane, d);

        // ---- scatter: one 16B red per row per mi ----
        {
            float2 bb0 = *(const float2*)&b2s[cb + 0];
            float2 bb1 = *(const float2*)&b2s[cb + 2];
            float2 bb2 = *(const float2*)&b2s[cb + 4];
            float2 bb3 = *(const float2*)&b2s[cb + 6];
#pragma unroll
            for (int mi = 0; mi < 2; mi++) {
                const int d0 = mi ? pd2 : pd0, d1 = mi ? pd3 : pd1;
                __half2 a0 = __floats2half2_rn(fmaxf(d[mi][0][0] + bb0.x, 0.f),
                                               fmaxf(d[mi][0][1] + bb0.y, 0.f));
                __half2 a1 = __floats2half2_rn(fmaxf(d[mi][1][0] + bb1.x, 0.f),
                                               fmaxf(d[mi][1][1] + bb1.y, 0.f));
                __half2 a2 = __floats2half2_rn(fmaxf(d[mi][2][0] + bb2.x, 0.f),
                                               fmaxf(d[mi][2][1] + bb2.y, 0.f));
                __half2 a3 = __floats2half2_rn(fmaxf(d[mi][3][0] + bb3.x, 0.f),
                                               fmaxf(d[mi][3][1] + bb3.y, 0.f));
                uint4 v0 = make_uint4(*(uint32_t*)&a0, *(uint32_t*)&a1,
                                      *(uint32_t*)&a2, *(uint32_t*)&a3);
                red_add_v4h2(&g_S[(size_t)d0 * 128 + cb], v0);

                __half2 c0 = __floats2half2_rn(fmaxf(d[mi][0][2] + bb0.x, 0.f),
                                               fmaxf(d[mi][0][3] + bb0.y, 0.f));
                __half2 c1 = __floats2half2_rn(fmaxf(d[mi][1][2] + bb1.x, 0.f),
                                               fmaxf(d[mi][1][3] + bb1.y, 0.f));
                __half2 c2 = __floats2half2_rn(fmaxf(d[mi][2][2] + bb2.x, 0.f),
                                               fmaxf(d[mi][2][3] + bb2.y, 0.f));
                __half2 c3 = __floats2half2_rn(fmaxf(d[mi][3][2] + bb3.x, 0.f),
                                               fmaxf(d[mi][3][3] + bb3.y, 0.f));
                uint4 v1 = make_uint4(*(uint32_t*)&c0, *(uint32_t*)&c1,
                                      *(uint32_t*)&c2, *(uint32_t*)&c3);
                red_add_v4h2(&g_S[(size_t)d1 * 128 + cb], v1);
            }
        }

        // ---- gather next tile into the other buffer ----
        const int nt = tile + gridDim.x;
        if (nt < numTiles) {
            const int ne0 = nt * 64;
            char* a2p = sm + (buf ? SM_A2A : SM_A2B);
#pragma unroll
            for (int k = 0; k < 4; k++) {
                int r = r0 + 16 * k;
                int s = ei[ne0 + r], t = ei[E_N + ne0 + r];
                uint4 P = *(const uint4*)&g_PQ[(size_t)s * 256 + jg * 8];
                uint4 Q = *(const uint4*)&g_PQ[(size_t)t * 256 + 128 + jg * 8];
                uint4 o;
                o.x = addrelu2(P.x, Q.x, Bv.x);
                o.y = addrelu2(P.y, Q.y, Bv.y);
                o.z = addrelu2(P.z, Q.z, Bv.z);
                o.w = addrelu2(P.w, Q.w, Bv.w);
                *(uint4*)(a2p + r * WPITCH + jg * 16) = o;
            }
        }
        buf ^= 1;
    }
}

// ---------------------------------------------------------------------------
// k_node: T = relu(R + S@W3n + deg*bn3 + bn1); out = T@Wn2 (3-term split).
// ---------------------------------------------------------------------------
#define N_B1  0         // bn1 512B
#define N_B2  512       // bn2 512B
#define N_B3  1024      // bn3 512B
#define N_W3N 1536      // fp16 W3n, 128 x 272 = 34816
#define N_W2H 36352
#define N_W2L 71168
#define N_XS  105984    // S staged fp16, 128 x 272
#define N_THI 140800
#define N_TLO 175616
#define SM_NODE_TOTAL 210432

__global__ __launch_bounds__(512, 1) void k_node(
    const float* __restrict__ bn1,
    const float* __restrict__ Wn2, const float* __restrict__ bn2,
    float* __restrict__ out)
{
    extern __shared__ __align__(16) char sm[];
    float* bn1s = (float*)(sm + N_B1);
    float* bn2s = (float*)(sm + N_B2);
    float* bn3s = (float*)(sm + N_B3);
    const uint32_t sbase = smem_u32(sm);
    const int tid = threadIdx.x, wid = tid >> 5, lane = tid & 31;
    const int wr = wid & 3, wc = wid >> 2;
    const int g = lane >> 2, q = lane & 3;

    for (int i = tid; i < 128 * 128; i += 512) {
        int k = i >> 7, n = i & 127;
        *(__half*)(sm + N_W3N + k * WPITCH + n * 2) = g_W3n[i];
        float w2 = Wn2[i];
        __nv_bfloat16 whi = __float2bfloat16(w2);
        *(__nv_bfloat16*)(sm + N_W2H + k * WPITCH + n * 2) = whi;
        *(__nv_bfloat16*)(sm + N_W2L + k * WPITCH + n * 2) =
            __float2bfloat16(w2 - __bfloat162float(whi));
    }
    if (tid < 128) { bn1s[tid] = bn1[tid]; bn2s[tid] = bn2[tid]; bn3s[tid] = g_bn3[tid]; }
    __syncthreads();

    float d[2][4][4];
    const int numTiles = (V_N + 127) / 128;   // 391

    for (int tile = blockIdx.x; tile < numTiles; tile += gridDim.x) {
        const int n0 = tile * 128;
        __syncthreads();
        for (int i = tid; i < 128 * 16; i += 512) {
            int r = i >> 4, j = i & 15;
            int node = n0 + r;
            uint4 v = (node < V_N) ? *(const uint4*)&g_S[(size_t)node * 128 + j * 8]
                                   : make_uint4(0, 0, 0, 0);
            *(uint4*)(sm + N_XS + r * WPITCH + j * 16) = v;
        }
        __syncthreads();

        // GEMM A: S @ W3n (fp16)
        zero_d(d);
        gemm_tile<8, WPITCH, WPITCH, 1>(sbase + N_XS, sbase + N_W3N, wr, wc, lane, d);

        // T = relu(d + R + deg*bn3 + bn1), split -> Thi/Tlo
#pragma unroll
        for (int mi = 0; mi < 2; mi++) {
            const int rA = wr * 32 + mi * 16 + g;
            const int nodeA = n0 + rA, nodeB = nodeA + 8;
            const float degA = (nodeA < V_N) ? (float)g_deg[nodeA] : 0.f;
            const float degB = (nodeB < V_N) ? (float)g_deg[nodeB] : 0.f;
#pragma unroll
            for (int ni = 0; ni < 4; ni++) {
                const int c = wc * 32 + ni * 8 + 2 * q;
                float2 bb = *(const float2*)&bn1s[c];
                float2 b3v = *(const float2*)&bn3s[c];
                float2 r0 = (nodeA < V_N) ? *(const float2*)&g_R[(size_t)nodeA * 128 + c]
                                          : make_float2(0.f, 0.f);
                float2 r1 = (nodeB < V_N) ? *(const float2*)&g_R[(size_t)nodeB * 128 + c]
                                          : make_float2(0.f, 0.f);
                float t0 = fmaxf(d[mi][ni][0] + r0.x + degA * b3v.x + bb.x, 0.f);
                float t1 = fmaxf(d[mi][ni][1] + r0.y + degA * b3v.y + bb.y, 0.f);
                float t2 = fmaxf(d[mi][ni][2] + r1.x + degB * b3v.x + bb.x, 0.f);
                float t3 = fmaxf(d[mi][ni][3] + r1.y + degB * b3v.y + bb.y, 0.f);
                __nv_bfloat16 h0 = __float2bfloat16(t0), h1 = __float2bfloat16(t1);
                __nv_bfloat16 h2 = __float2bfloat16(t2), h3 = __float2bfloat16(t3);
                *(uint32_t*)(sm + N_THI + rA * WPITCH + c * 2) =
                    pack2(__bfloat162float(h0), __bfloat162float(h1));
                *(uint32_t*)(sm + N_THI + (rA + 8) * WPITCH + c * 2) =
                    pack2(__bfloat162float(h2), __bfloat162float(h3));
                *(uint32_t*)(sm + N_TLO + rA * WPITCH + c * 2) =
                    pack2(t0 - __bfloat162float(h0), t1 - __bfloat162float(h1));
                *(uint32_t*)(sm + N_TLO + (rA + 8) * WPITCH + c * 2) =
                    pack2(t2 - __bfloat162float(h2), t3 - __bfloat162float(h3));
            }
        }
        __syncthreads();

        // GEMM B: out = Thi@W2hi + Thi@W2lo + Tlo@W2hi + bn2
        zero_d(d);
        gemm_tile<8, WPITCH, WPITCH, 0>(sbase + N_THI, sbase + N_W2H, wr, wc, lane, d);
        gemm_tile<8, WPITCH, WPITCH, 0>(sbase + N_THI, sbase + N_W2L, wr, wc, lane, d);
        gemm_tile<8, WPITCH, WPITCH, 0>(sbase + N_TLO, sbase + N_W2H, wr, wc, lane, d);

#pragma unroll
        for (int mi = 0; mi < 2; mi++) {
            const int rA = wr * 32 + mi * 16 + g;
            const int nodeA = n0 + rA, nodeB = nodeA + 8;
#pragma unroll
            for (int ni = 0; ni < 4; ni++) {
                const int c = wc * 32 + ni * 8 + 2 * q;
                float2 bb = *(const float2*)&bn2s[c];
                if (nodeA < V_N)
                    *(float2*)&out[(size_t)nodeA * 128 + c] =
                        make_float2(d[mi][ni][0] + bb.x, d[mi][ni][1] + bb.y);
                if (nodeB < V_N)
                    *(float2*)&out[(size_t)nodeB * 128 + c] =
                        make_float2(d[mi][ni][2] + bb.x, d[mi][ni][3] + bb.y);
            }
        }
    }
}

// ---------------------------------------------------------------------------
extern "C" void kernel_launch(void* const* d_in, const int* in_sizes, int n_in,
                              void* d_out, int out_size) {
    const float* h   = (const float*)d_in[0];
    const int*   ei  = (const int*)d_in[1];   // int32 (JAX x64 disabled)
    const float* W1  = (const float*)d_in[2];
    const float* b1  = (const float*)d_in[3];
    const float* W2  = (const float*)d_in[4];
    const float* b2  = (const float*)d_in[5];
    const float* W3  = (const float*)d_in[6];
    const float* b3  = (const float*)d_in[7];
    const float* Wn1 = (const float*)d_in[8];
    const float* bn1 = (const float*)d_in[9];
    const float* Wn2 = (const float*)d_in[10];
    const float* bn2 = (const float*)d_in[11];
    float*       out = (float*)d_out;

    cudaFuncSetAttribute(k_prep, cudaFuncAttributeMaxDynamicSharedMemorySize, SM_PREP_TOTAL);
    cudaFuncSetAttribute(k_edge, cudaFuncAttributeMaxDynamicSharedMemorySize, SM_EDGE_TOTAL);
    cudaFuncSetAttribute(k_node, cudaFuncAttributeMaxDynamicSharedMemorySize, SM_NODE_TOTAL);

    k_zero<<<512, 256>>>();
    k_deg<<<1024, 256>>>(ei);
    k_w3n<<<128, 128>>>(W3, b3, Wn1);
    k_prep<<<148, 512, SM_PREP_TOTAL>>>(h, W1, Wn1);
    k_edge<<<296, 256, SM_EDGE_TOTAL>>>(ei, b1, W2, b2);
    k_node<<<148, 512, SM_NODE_TOTAL>>>(bn1, Wn2, bn2, out);
}

// round 15
// speedup vs baseline: 1.3900x; 1.0855x over previous
#include <cuda_runtime.h>
#include <cuda_bf16.h>
#include <cuda_fp16.h>
#include <cstdint>

// Problem constants (fixed shapes)
#define V_N 50000
#define E_N 800000

// Scratch (static device arrays — no runtime allocation)
__device__ __half g_S[(size_t)V_N * 128];           // Σ relu(A2@W2+b2) per node, fp16
__device__ int    g_deg[V_N];                       // in-degree
__device__ __nv_bfloat16 g_PQ[(size_t)V_N * 256];   // [P+b1 | Q] per node, bf16
__device__ float  g_R[(size_t)V_N * 128];           // h @ Wn1_top (near-fp32)
__device__ __half g_W3n[128 * 128];                 // W3 @ Wn1_bot, fp16
__device__ float  g_bn3[128];                       // b3 @ Wn1_bot

// ============================================================================
// Warp-level MMA helpers (base PTX: ldmatrix sm_75+, mma.sync sm_80+)
// ============================================================================
__device__ __forceinline__ uint32_t smem_u32(const void* p) {
    uint32_t a;
    asm("{ .reg .u64 t; cvta.to.shared.u64 t, %1; cvt.u32.u64 %0, t; }"
        : "=r"(a) : "l"(p));
    return a;
}
__device__ __forceinline__ void ldsm_x4(uint32_t* r, uint32_t addr) {
    asm volatile("ldmatrix.sync.aligned.m8n8.x4.shared.b16 {%0,%1,%2,%3}, [%4];"
                 : "=r"(r[0]), "=r"(r[1]), "=r"(r[2]), "=r"(r[3]) : "r"(addr));
}
__device__ __forceinline__ void ldsm_x4_t(uint32_t* r, uint32_t addr) {
    asm volatile("ldmatrix.sync.aligned.m8n8.x4.trans.shared.b16 {%0,%1,%2,%3}, [%4];"
                 : "=r"(r[0]), "=r"(r[1]), "=r"(r[2]), "=r"(r[3]) : "r"(addr));
}
__device__ __forceinline__ void mma_bf16(float* d, const uint32_t* a, const uint32_t* b) {
    asm volatile(
        "mma.sync.aligned.m16n8k16.row.col.f32.bf16.bf16.f32 "
        "{%0,%1,%2,%3}, {%4,%5,%6,%7}, {%8,%9}, {%0,%1,%2,%3};"
        : "+f"(d[0]), "+f"(d[1]), "+f"(d[2]), "+f"(d[3])
        : "r"(a[0]), "r"(a[1]), "r"(a[2]), "r"(a[3]), "r"(b[0]), "r"(b[1]));
}
__device__ __forceinline__ void mma_f16(float* d, const uint32_t* a, const uint32_t* b) {
    asm volatile(
        "mma.sync.aligned.m16n8k16.row.col.f32.f16.f16.f32 "
        "{%0,%1,%2,%3}, {%4,%5,%6,%7}, {%8,%9}, {%0,%1,%2,%3};"
        : "+f"(d[0]), "+f"(d[1]), "+f"(d[2]), "+f"(d[3])
        : "r"(a[0]), "r"(a[1]), "r"(a[2]), "r"(a[3]), "r"(b[0]), "r"(b[1]));
}
__device__ __forceinline__ uint32_t pack2(float a, float b) {
    __nv_bfloat162 p = __floats2bfloat162_rn(a, b);
    return *(uint32_t*)&p;
}
// 16-byte vector fp16 reduction (sm_90+): 8 halves per op
__device__ __forceinline__ void red_add_v4h2(__half* p, uint4 v) {
    asm volatile("red.global.add.noftz.v4.f16x2 [%0], {%1, %2, %3, %4};"
                 :: "l"(p), "r"(v.x), "r"(v.y), "r"(v.z), "r"(v.w) : "memory");
}
// relu(bf16x2(p) + bf16x2(q)) in fp32, repacked bf16x2 (b1 pre-folded into P)
__device__ __forceinline__ uint32_t addrelu2(uint32_t p, uint32_t q) {
    float2 fp = __bfloat1622float2(*(__nv_bfloat162*)&p);
    float2 fq = __bfloat1622float2(*(__nv_bfloat162*)&q);
    return pack2(fmaxf(fp.x + fq.x, 0.f), fmaxf(fp.y + fq.y, 0.f));
}

#define WPITCH 272   // b16 tile pitch for 128-col matrices
#define BPITCH 528   // b16 tile pitch for 256-col matrices

// Warp-tile GEMM (ACCUMULATES into d; caller zeroes). WP = weight pitch.
template <int NK, int AP, int WP, int F16>
__device__ __forceinline__ void gemm_tile(uint32_t abase, uint32_t wbase,
                                          int wr, int wc, int lane,
                                          float d[2][4][4]) {
    const int l15 = lane & 15;
    const int kh  = (lane >> 4) << 3;
#pragma unroll
    for (int ks = 0; ks < NK; ks++) {
        uint32_t a[2][4], b[4][2];
#pragma unroll
        for (int mi = 0; mi < 2; mi++) {
            uint32_t addr = abase + (uint32_t)((wr * 32 + mi * 16 + l15) * AP +
                                               (ks * 16 + kh) * 2);
            ldsm_x4(a[mi], addr);
        }
#pragma unroll
        for (int nj = 0; nj < 2; nj++) {
            uint32_t addr = wbase + (uint32_t)((ks * 16 + l15) * WP +
                                               (wc * 32 + nj * 16 + kh) * 2);
            uint32_t t[4];
            ldsm_x4_t(t, addr);
            b[2 * nj][0] = t[0]; b[2 * nj][1] = t[1];
            b[2 * nj + 1][0] = t[2]; b[2 * nj + 1][1] = t[3];
        }
#pragma unroll
        for (int mi = 0; mi < 2; mi++)
#pragma unroll
            for (int ni = 0; ni < 4; ni++) {
                if (F16) mma_f16(d[mi][ni], a[mi], b[ni]);
                else     mma_bf16(d[mi][ni], a[mi], b[ni]);
            }
    }
}
// Fused two-B-matrix GEMM: A-fragments loaded once, both B matrices streamed.
template <int NK, int AP, int WP, int F16>
__device__ __forceinline__ void gemm_tile2(uint32_t abase, uint32_t wbase0,
                                           uint32_t wbase1,
                                           int wr, int wc, int lane,
                                           float d[2][4][4]) {
    const int l15 = lane & 15;
    const int kh  = (lane >> 4) << 3;
#pragma unroll
    for (int ks = 0; ks < NK; ks++) {
        uint32_t a[2][4], b[4][2];
#pragma unroll
        for (int mi = 0; mi < 2; mi++) {
            uint32_t addr = abase + (uint32_t)((wr * 32 + mi * 16 + l15) * AP +
                                               (ks * 16 + kh) * 2);
            ldsm_x4(a[mi], addr);
        }
#pragma unroll
        for (int w2 = 0; w2 < 2; w2++) {
            uint32_t wb = w2 ? wbase1 : wbase0;
#pragma unroll
            for (int nj = 0; nj < 2; nj++) {
                uint32_t addr = wb + (uint32_t)((ks * 16 + l15) * WP +
                                                (wc * 32 + nj * 16 + kh) * 2);
                uint32_t t[4];
                ldsm_x4_t(t, addr);
                b[2 * nj][0] = t[0]; b[2 * nj][1] = t[1];
                b[2 * nj + 1][0] = t[2]; b[2 * nj + 1][1] = t[3];
            }
#pragma unroll
            for (int mi = 0; mi < 2; mi++)
#pragma unroll
                for (int ni = 0; ni < 4; ni++) {
                    if (F16) mma_f16(d[mi][ni], a[mi], b[ni]);
                    else     mma_bf16(d[mi][ni], a[mi], b[ni]);
                }
        }
    }
}
__device__ __forceinline__ void zero_d(float d[2][4][4]) {
#pragma unroll
    for (int mi = 0; mi < 2; mi++)
#pragma unroll
        for (int ni = 0; ni < 4; ni++)
#pragma unroll
            for (int x = 0; x < 4; x++) d[mi][ni][x] = 0.f;
}

// ---------------------------------------------------------------------------
// k_setup: blocks 0-63 compute W3n = W3 @ Wn1_bot (+ bn3); blocks 64+ zero
// g_S and g_deg.
// ---------------------------------------------------------------------------
__global__ void k_setup(const float* __restrict__ W3, const float* __restrict__ b3,
                        const float* __restrict__ Wn1) {
    const int blk = blockIdx.x, tid = threadIdx.x;
    if (blk < 64) {
        const int k = blk * 2 + (tid >> 7), n = tid & 127;
        float s = 0.f;
        for (int j = 0; j < 128; j++)
            s += W3[k * 128 + j] * Wn1[(128 + j) * 128 + n];
        g_W3n[k * 128 + n] = __float2half(s);
        if (blk == 0 && tid < 128) {
            float s2 = 0.f;
            for (int j = 0; j < 128; j++)
                s2 += b3[j] * Wn1[(128 + j) * 128 + n];
            g_bn3[n] = s2;
        }
    } else {
        const uint4 z = make_uint4(0, 0, 0, 0);
        const int nS = V_N * 128 / 8;
        const int stride = (gridDim.x - 64) * blockDim.x;
        for (int i = (blk - 64) * blockDim.x + tid; i < nS; i += stride)
            ((uint4*)g_S)[i] = z;
        const int nD = V_N / 4;
        for (int i = (blk - 64) * blockDim.x + tid; i < nD; i += stride)
            ((uint4*)g_deg)[i] = z;
    }
}

// ---------------------------------------------------------------------------
// k_prep (merged): one h staging (hi/lo) per 128-row tile feeds
//   PQ = h@[W1_top | W1_bot] + [b1 | 0]  (bf16 hi, ONE pass) -> g_PQ
//   R  = h@Wn1_top 3-term split (HH a-frags shared WH+WL)    -> g_R
// ---------------------------------------------------------------------------
#define P_W1  0        // 128 x 528 = 67584 (bf16, 256 cols)
#define P_WH  67584
#define P_WL  102400
#define P_HH  137216
#define P_HL  172032
#define SM_PREP_TOTAL 206848

__global__ __launch_bounds__(512, 1) void k_prep(
    const float* __restrict__ h, const float* __restrict__ W1,
    const float* __restrict__ Wn1, const float* __restrict__ b1)
{
    extern __shared__ __align__(16) char sm[];
    const uint32_t sbase = smem_u32(sm);
    const int tid = threadIdx.x, wid = tid >> 5, lane = tid & 31;
    const int wr = wid & 3, wc = wid >> 2;   // 4x4 warp grid
    const int l15 = lane & 15, kh = (lane >> 4) << 3;
    const int g = lane >> 2, q = lane & 3;

    for (int i = tid; i < 128 * 256; i += 512) {
        int k = i >> 8, n = i & 255;
        float w = (n < 128) ? W1[k * 128 + n] : W1[(128 + k) * 128 + (n - 128)];
        *(__nv_bfloat16*)(sm + P_W1 + k * BPITCH + n * 2) = __float2bfloat16(w);
    }
    for (int i = tid; i < 128 * 128; i += 512) {
        int k = i >> 7, n = i & 127;
        float w = Wn1[k * 128 + n];
        __nv_bfloat16 whi = __float2bfloat16(w);
        *(__nv_bfloat16*)(sm + P_WH + k * WPITCH + n * 2) = whi;
        *(__nv_bfloat16*)(sm + P_WL + k * WPITCH + n * 2) =
            __float2bfloat16(w - __bfloat162float(whi));
    }
    __syncthreads();

    const float4* h4 = (const float4*)h;
    const int numTiles = (V_N + 127) / 128;   // 391

    for (int tile = blockIdx.x; tile < numTiles; tile += gridDim.x) {
        const int n0 = tile * 128;
        __syncthreads();
        for (int i = tid; i < 128 * 32; i += 512) {
            int r = i >> 5, j = i & 31;
            int node = n0 + r;
            float4 v = (node < V_N) ? h4[(size_t)node * 32 + j]
                                    : make_float4(0.f, 0.f, 0.f, 0.f);
            __nv_bfloat16 h0 = __float2bfloat16(v.x), h1 = __float2bfloat16(v.y);
            __nv_bfloat16 h2 = __float2bfloat16(v.z), h3 = __float2bfloat16(v.w);
            uint2 uh, ul;
            uh.x = pack2(__bfloat162float(h0), __bfloat162float(h1));
            uh.y = pack2(__bfloat162float(h2), __bfloat162float(h3));
            ul.x = pack2(v.x - __bfloat162float(h0), v.y - __bfloat162float(h1));
            ul.y = pack2(v.z - __bfloat162float(h2), v.w - __bfloat162float(h3));
            *(uint2*)(sm + P_HH + r * WPITCH + j * 8) = uh;
            *(uint2*)(sm + P_HL + r * WPITCH + j * 8) = ul;
        }
        __syncthreads();

        // ---- PQ: single pass, warp tile 32 rows x 64 cols; +b1 on P half ----
        {
            float dq[2][8][4];
#pragma unroll
            for (int mi = 0; mi < 2; mi++)
#pragma unroll
                for (int ni = 0; ni < 8; ni++)
#pragma unroll
                    for (int x = 0; x < 4; x++) dq[mi][ni][x] = 0.f;

#pragma unroll
            for (int ks = 0; ks < 8; ks++) {
                uint32_t a[2][4], b[8][2];
#pragma unroll
                for (int mi = 0; mi < 2; mi++) {
                    uint32_t addr = sbase + P_HH +
                        (uint32_t)((wr * 32 + mi * 16 + l15) * WPITCH +
                                   (ks * 16 + kh) * 2);
                    ldsm_x4(a[mi], addr);
                }
#pragma unroll
                for (int nj = 0; nj < 4; nj++) {
                    uint32_t addr = sbase + P_W1 +
                        (uint32_t)((ks * 16 + l15) * BPITCH +
                                   (wc * 64 + nj * 16 + kh) * 2);
                    uint32_t t[4];
                    ldsm_x4_t(t, addr);
                    b[2 * nj][0] = t[0]; b[2 * nj][1] = t[1];
                    b[2 * nj + 1][0] = t[2]; b[2 * nj + 1][1] = t[3];
                }
#pragma unroll
                for (int mi = 0; mi < 2; mi++)
#pragma unroll
                    for (int ni = 0; ni < 8; ni++)
                        mma_bf16(dq[mi][ni], a[mi], b[ni]);
            }

            const bool isP = (wc < 2);   // cols < 128 -> P half
#pragma unroll
            for (int mi = 0; mi < 2; mi++) {
                const int rA = wr * 32 + mi * 16 + g;
                const int nodeA = n0 + rA, nodeB = nodeA + 8;
#pragma unroll
                for (int ni = 0; ni < 8; ni++) {
                    const int c = wc * 64 + ni * 8 + 2 * q;
                    float bx = 0.f, by = 0.f;
                    if (isP) { float2 bv = *(const float2*)&b1[c]; bx = bv.x; by = bv.y; }
                    if (nodeA < V_N)
                        *(uint32_t*)&g_PQ[(size_t)nodeA * 256 + c] =
                            pack2(dq[mi][ni][0] + bx, dq[mi][ni][1] + by);
                    if (nodeB < V_N)
                        *(uint32_t*)&g_PQ[(size_t)nodeB * 256 + c] =
                            pack2(dq[mi][ni][2] + bx, dq[mi][ni][3] + by);
                }
            }
        }

        // ---- R: 3-term split; HH a-frags shared between WH and WL ----
        {
            float d[2][4][4];
            zero_d(d);
            gemm_tile2<8, WPITCH, WPITCH, 0>(sbase + P_HH, sbase + P_WH,
                                             sbase + P_WL, wr, wc, lane, d);
            gemm_tile<8, WPITCH, WPITCH, 0>(sbase + P_HL, sbase + P_WH,
                                            wr, wc, lane, d);

#pragma unroll
            for (int mi = 0; mi < 2; mi++) {
                const int rA = wr * 32 + mi * 16 + g;
                const int nodeA = n0 + rA, nodeB = nodeA + 8;
#pragma unroll
                for (int ni = 0; ni < 4; ni++) {
                    const int c = wc * 32 + ni * 8 + 2 * q;
                    if (nodeA < V_N)
                        *(float2*)&g_R[(size_t)nodeA * 128 + c] =
                            make_float2(d[mi][ni][0], d[mi][ni][1]);
                    if (nodeB < V_N)
                        *(float2*)&g_R[(size_t)nodeB * 128 + c] =
                            make_float2(d[mi][ni][2], d[mi][ni][3]);
                }
            }
        }
    }
}

// ---------------------------------------------------------------------------
// k_edge: 64-edge tiles, 256 threads, TWO CTAs per SM.
//   A2 = relu(P'[src]+Q[dst]);  S[dst] += relu(A2@W2+b2);  deg[dst] += 1
// W2 columns stored PERMUTED (tau) -> one red.v4.f16x2 (16B) per row per mi.
// ---------------------------------------------------------------------------
#define SM_B2S  0        // 128 f32 = 512B (logical order)
#define SM_W2   512      // 128 x 272 = 34816 (permuted cols)
#define SM_A2A  35328    // 64 x 272 = 17408
#define SM_A2B  52736    // 17408
#define SM_EDGE_TOTAL 70144

__global__ __launch_bounds__(256, 2) void k_edge(
    const int* __restrict__ ei,
    const float* __restrict__ W2, const float* __restrict__ b2)
{
    extern __shared__ __align__(16) char sm[];
    float* b2s = (float*)(sm + SM_B2S);
    const uint32_t sbase = smem_u32(sm);
    const uint32_t sW2 = sbase + SM_W2;

    const int tid = threadIdx.x, wid = tid >> 5, lane = tid & 31;
    const int wr = wid & 1, wc = wid >> 1;   // 2x4 warp grid
    const int g = lane >> 2, q = lane & 3;

    // Stage W2 with column permutation tau
    for (int i = tid; i < 128 * 128; i += 256) {
        int k = i >> 7, n = i & 127;
        int t = n & 31, base = n & ~31;
        int q2 = t >> 3, rem = t & 7, ni2 = rem >> 1, jj = rem & 1;
        int tcol = base + ni2 * 8 + 2 * q2 + jj;   // stored position of logical n
        *(__nv_bfloat16*)(sm + SM_W2 + k * WPITCH + tcol * 2) = __float2bfloat16(W2[i]);
    }
    if (tid < 128) b2s[tid] = b2[tid];   // logical order
    __syncthreads();

    const int jg = tid & 15;                  // gather: 16B col group
    const int r0 = tid >> 4;                  // gather: base row (0..15)
    const int cb = wc * 32 + 8 * q;           // scatter: logical col base (8 cols)

    const int numTiles = E_N / 64;   // 12500
    float d[2][4][4];
    int buf = 0;

    // Prologue: gather first tile into buffer A
    int tile = blockIdx.x;
    if (tile < numTiles) {
        const int e0 = tile * 64;
        char* a2p = sm + SM_A2A;
#pragma unroll
        for (int k = 0; k < 4; k++) {
            int r = r0 + 16 * k;
            int s = ei[e0 + r], t = ei[E_N + e0 + r];
            uint4 P = *(const uint4*)&g_PQ[(size_t)s * 256 + jg * 8];
            uint4 Q = *(const uint4*)&g_PQ[(size_t)t * 256 + 128 + jg * 8];
            uint4 o;
            o.x = addrelu2(P.x, Q.x);
            o.y = addrelu2(P.y, Q.y);
            o.z = addrelu2(P.z, Q.z);
            o.w = addrelu2(P.w, Q.w);
            *(uint4*)(a2p + r * WPITCH + jg * 16) = o;
        }
    }

    for (; tile < numTiles; tile += gridDim.x) {
        const int e0 = tile * 64;
        const int rA = wr * 32 + g;

        // Prefetch scatter destinations (hide LDG latency behind GEMM2)
        int pd0 = ei[E_N + e0 + rA];
        int pd1 = ei[E_N + e0 + rA + 8];
        int pd2 = ei[E_N + e0 + rA + 16];
        int pd3 = ei[E_N + e0 + rA + 24];

        __syncthreads();   // A2[buf] ready; other buffer free

        // ---- GEMM2 on A2[buf] (output cols permuted) ----
        zero_d(d);
        gemm_tile<8, WPITCH, WPITCH, 0>(sbase + (buf ? SM_A2B : SM_A2A), sW2,
                                        wr, wc, lane, d);

        // ---- scatter: one 16B red per row per mi (+deg from col-group 0) ----
        {
            float2 bb0 = *(const float2*)&b2s[cb + 0];
            float2 bb1 = *(const float2*)&b2s[cb + 2];
            float2 bb2 = *(const float2*)&b2s[cb + 4];
            float2 bb3 = *(const float2*)&b2s[cb + 6];
            if (wc == 0 && q == 0) {
                atomicAdd(&g_deg[pd0], 1);
                atomicAdd(&g_deg[pd1], 1);
                atomicAdd(&g_deg[pd2], 1);
                atomicAdd(&g_deg[pd3], 1);
            }
#pragma unroll
            for (int mi = 0; mi < 2; mi++) {
                const int d0 = mi ? pd2 : pd0, d1 = mi ? pd3 : pd1;
                __half2 a0 = __floats2half2_rn(fmaxf(d[mi][0][0] + bb0.x, 0.f),
                                               fmaxf(d[mi][0][1] + bb0.y, 0.f));
                __half2 a1 = __floats2half2_rn(fmaxf(d[mi][1][0] + bb1.x, 0.f),
                                               fmaxf(d[mi][1][1] + bb1.y, 0.f));
                __half2 a2 = __floats2half2_rn(fmaxf(d[mi][2][0] + bb2.x, 0.f),
                                               fmaxf(d[mi][2][1] + bb2.y, 0.f));
                __half2 a3 = __floats2half2_rn(fmaxf(d[mi][3][0] + bb3.x, 0.f),
                                               fmaxf(d[mi][3][1] + bb3.y, 0.f));
                uint4 v0 = make_uint4(*(uint32_t*)&a0, *(uint32_t*)&a1,
                                      *(uint32_t*)&a2, *(uint32_t*)&a3);
                red_add_v4h2(&g_S[(size_t)d0 * 128 + cb], v0);

                __half2 c0 = __floats2half2_rn(fmaxf(d[mi][0][2] + bb0.x, 0.f),
                                               fmaxf(d[mi][0][3] + bb0.y, 0.f));
                __half2 c1 = __floats2half2_rn(fmaxf(d[mi][1][2] + bb1.x, 0.f),
                                               fmaxf(d[mi][1][3] + bb1.y, 0.f));
                __half2 c2 = __floats2half2_rn(fmaxf(d[mi][2][2] + bb2.x, 0.f),
                                               fmaxf(d[mi][2][3] + bb2.y, 0.f));
                __half2 c3 = __floats2half2_rn(fmaxf(d[mi][3][2] + bb3.x, 0.f),
                                               fmaxf(d[mi][3][3] + bb3.y, 0.f));
                uint4 v1 = make_uint4(*(uint32_t*)&c0, *(uint32_t*)&c1,
                                      *(uint32_t*)&c2, *(uint32_t*)&c3);
                red_add_v4h2(&g_S[(size_t)d1 * 128 + cb], v1);
            }
        }

        // ---- gather next tile into the other buffer ----
        const int nt = tile + gridDim.x;
        if (nt < numTiles) {
            const int ne0 = nt * 64;
            char* a2p = sm + (buf ? SM_A2A : SM_A2B);
#pragma unroll
            for (int k = 0; k < 4; k++) {
                int r = r0 + 16 * k;
                int s = ei[ne0 + r], t = ei[E_N + ne0 + r];
                uint4 P = *(const uint4*)&g_PQ[(size_t)s * 256 + jg * 8];
                uint4 Q = *(const uint4*)&g_PQ[(size_t)t * 256 + 128 + jg * 8];
                uint4 o;
                o.x = addrelu2(P.x, Q.x);
                o.y = addrelu2(P.y, Q.y);
                o.z = addrelu2(P.z, Q.z);
                o.w = addrelu2(P.w, Q.w);
                *(uint4*)(a2p + r * WPITCH + jg * 16) = o;
            }
        }
        buf ^= 1;
    }
}

// ---------------------------------------------------------------------------
// k_node: T = relu(R + S@W3n + deg*bn3 + bn1); out = T@Wn2 (3-term split,
// Thi a-frags shared across W2H/W2L).
// ---------------------------------------------------------------------------
#define N_B1  0         // bn1 512B
#define N_B2  512       // bn2 512B
#define N_B3  1024      // bn3 512B
#define N_W3N 1536      // fp16 W3n, 128 x 272 = 34816
#define N_W2H 36352
#define N_W2L 71168
#define N_XS  105984    // S staged fp16, 128 x 272
#define N_THI 140800
#define N_TLO 175616
#define SM_NODE_TOTAL 210432

__global__ __launch_bounds__(512, 1) void k_node(
    const float* __restrict__ bn1,
    const float* __restrict__ Wn2, const float* __restrict__ bn2,
    float* __restrict__ out)
{
    extern __shared__ __align__(16) char sm[];
    float* bn1s = (float*)(sm + N_B1);
    float* bn2s = (float*)(sm + N_B2);
    float* bn3s = (float*)(sm + N_B3);
    const uint32_t sbase = smem_u32(sm);
    const int tid = threadIdx.x, wid = tid >> 5, lane = tid & 31;
    const int wr = wid & 3, wc = wid >> 2;
    const int g = lane >> 2, q = lane & 3;

    for (int i = tid; i < 128 * 128; i += 512) {
        int k = i >> 7, n = i & 127;
        *(__half*)(sm + N_W3N + k * WPITCH + n * 2) = g_W3n[i];
        float w2 = Wn2[i];
        __nv_bfloat16 whi = __float2bfloat16(w2);
        *(__nv_bfloat16*)(sm + N_W2H + k * WPITCH + n * 2) = whi;
        *(__nv_bfloat16*)(sm + N_W2L + k * WPITCH + n * 2) =
            __float2bfloat16(w2 - __bfloat162float(whi));
    }
    if (tid < 128) { bn1s[tid] = bn1[tid]; bn2s[tid] = bn2[tid]; bn3s[tid] = g_bn3[tid]; }
    __syncthreads();

    float d[2][4][4];
    const int numTiles = (V_N + 127) / 128;   // 391

    for (int tile = blockIdx.x; tile < numTiles; tile += gridDim.x) {
        const int n0 = tile * 128;
        __syncthreads();
        for (int i = tid; i < 128 * 16; i += 512) {
            int r = i >> 4, j = i & 15;
            int node = n0 + r;
            uint4 v = (node < V_N) ? *(const uint4*)&g_S[(size_t)node * 128 + j * 8]
                                   : make_uint4(0, 0, 0, 0);
            *(uint4*)(sm + N_XS + r * WPITCH + j * 16) = v;
        }
        __syncthreads();

        // GEMM A: S @ W3n (fp16)
        zero_d(d);
        gemm_tile<8, WPITCH, WPITCH, 1>(sbase + N_XS, sbase + N_W3N, wr, wc, lane, d);

        // T = relu(d + R + deg*bn3 + bn1), split -> Thi/Tlo
#pragma unroll
        for (int mi = 0; mi < 2; mi++) {
            const int rA = wr * 32 + mi * 16 + g;
            const int nodeA = n0 + rA, nodeB = nodeA + 8;
            const float degA = (nodeA < V_N) ? (float)g_deg[nodeA] : 0.f;
            const float degB = (nodeB < V_N) ? (float)g_deg[nodeB] : 0.f;
#pragma unroll
            for (int ni = 0; ni < 4; ni++) {
                const int c = wc * 32 + ni * 8 + 2 * q;
                float2 bb = *(const float2*)&bn1s[c];
                float2 b3v = *(const float2*)&bn3s[c];
                float2 r0 = (nodeA < V_N) ? *(const float2*)&g_R[(size_t)nodeA * 128 + c]
                                          : make_float2(0.f, 0.f);
                float2 r1 = (nodeB < V_N) ? *(const float2*)&g_R[(size_t)nodeB * 128 + c]
                                          : make_float2(0.f, 0.f);
                float t0 = fmaxf(d[mi][ni][0] + r0.x + degA * b3v.x + bb.x, 0.f);
                float t1 = fmaxf(d[mi][ni][1] + r0.y + degA * b3v.y + bb.y, 0.f);
                float t2 = fmaxf(d[mi][ni][2] + r1.x + degB * b3v.x + bb.x, 0.f);
                float t3 = fmaxf(d[mi][ni][3] + r1.y + degB * b3v.y + bb.y, 0.f);
                __nv_bfloat16 h0 = __float2bfloat16(t0), h1 = __float2bfloat16(t1);
                __nv_bfloat16 h2 = __float2bfloat16(t2), h3 = __float2bfloat16(t3);
                *(uint32_t*)(sm + N_THI + rA * WPITCH + c * 2) =
                    pack2(__bfloat162float(h0), __bfloat162float(h1));
                *(uint32_t*)(sm + N_THI + (rA + 8) * WPITCH + c * 2) =
                    pack2(__bfloat162float(h2), __bfloat162float(h3));
                *(uint32_t*)(sm + N_TLO + rA * WPITCH + c * 2) =
                    pack2(t0 - __bfloat162float(h0), t1 - __bfloat162float(h1));
                *(uint32_t*)(sm + N_TLO + (rA + 8) * WPITCH + c * 2) =
                    pack2(t2 - __bfloat162float(h2), t3 - __bfloat162float(h3));
            }
        }
        __syncthreads();

        // GEMM B: out = Thi@(W2hi+W2lo) + Tlo@W2hi + bn2 (Thi a-frags shared)
        zero_d(d);
        gemm_tile2<8, WPITCH, WPITCH, 0>(sbase + N_THI, sbase + N_W2H,
                                         sbase + N_W2L, wr, wc, lane, d);
        gemm_tile<8, WPITCH, WPITCH, 0>(sbase + N_TLO, sbase + N_W2H, wr, wc, lane, d);

#pragma unroll
        for (int mi = 0; mi < 2; mi++) {
            const int rA = wr * 32 + mi * 16 + g;
            const int nodeA = n0 + rA, nodeB = nodeA + 8;
#pragma unroll
            for (int ni = 0; ni < 4; ni++) {
                const int c = wc * 32 + ni * 8 + 2 * q;
                float2 bb = *(const float2*)&bn2s[c];
                if (nodeA < V_N)
                    *(float2*)&out[(size_t)nodeA * 128 + c] =
                        make_float2(d[mi][ni][0] + bb.x, d[mi][ni][1] + bb.y);
                if (nodeB < V_N)
                    *(float2*)&out[(size_t)nodeB * 128 + c] =
                        make_float2(d[mi][ni][2] + bb.x, d[mi][ni][3] + bb.y);
            }
        }
    }
}

// ---------------------------------------------------------------------------
extern "C" void kernel_launch(void* const* d_in, const int* in_sizes, int n_in,
                              void* d_out, int out_size) {
    const float* h   = (const float*)d_in[0];
    const int*   ei  = (const int*)d_in[1];   // int32 (JAX x64 disabled)
    const float* W1  = (const float*)d_in[2];
    const float* b1  = (const float*)d_in[3];
    const float* W2  = (const float*)d_in[4];
    const float* b2  = (const float*)d_in[5];
    const float* W3  = (const float*)d_in[6];
    const float* b3  = (const float*)d_in[7];
    const float* Wn1 = (const float*)d_in[8];
    const float* bn1 = (const float*)d_in[9];
    const float* Wn2 = (const float*)d_in[10];
    const float* bn2 = (const float*)d_in[11];
    float*       out = (float*)d_out;

    cudaFuncSetAttribute(k_prep, cudaFuncAttributeMaxDynamicSharedMemorySize, SM_PREP_TOTAL);
    cudaFuncSetAttribute(k_edge, cudaFuncAttributeMaxDynamicSharedMemorySize, SM_EDGE_TOTAL);
    cudaFuncSetAttribute(k_node, cudaFuncAttributeMaxDynamicSharedMemorySize, SM_NODE_TOTAL);

    k_setup<<<512, 256>>>(W3, b3, Wn1);
    k_prep<<<148, 512, SM_PREP_TOTAL>>>(h, W1, Wn1, b1);
    k_edge<<<296, 256, SM_EDGE_TOTAL>>>(ei, W2, b2);
    k_node<<<148, 512, SM_NODE_TOTAL>>>(bn1, Wn2, bn2, out);
}

// round 16
// speedup vs baseline: 1.4545x; 1.0464x over previous
#include <cuda_runtime.h>
#include <cuda_bf16.h>
#include <cuda_fp16.h>
#include <cstdint>

// Problem constants (fixed shapes)
#define V_N 50000
#define E_N 800000

// Scratch (static device arrays — no runtime allocation)
__device__ __half g_S[(size_t)V_N * 128];           // Σ relu(A2@W2+b2) per node, fp16
__device__ int    g_deg[V_N];                       // in-degree
__device__ __nv_bfloat16 g_PQ[(size_t)V_N * 256];   // [P+b1 | Q] per node, bf16
__device__ float  g_R[(size_t)V_N * 128];           // h @ Wn1_top (near-fp32)
__device__ __half g_W3n[128 * 128];                 // W3 @ Wn1_bot, fp16
__device__ float  g_bn3[128];                       // b3 @ Wn1_bot

// ============================================================================
// Warp-level MMA helpers (base PTX: ldmatrix sm_75+, mma.sync sm_80+)
// ============================================================================
__device__ __forceinline__ uint32_t smem_u32(const void* p) {
    uint32_t a;
    asm("{ .reg .u64 t; cvta.to.shared.u64 t, %1; cvt.u32.u64 %0, t; }"
        : "=r"(a) : "l"(p));
    return a;
}
__device__ __forceinline__ void ldsm_x4(uint32_t* r, uint32_t addr) {
    asm volatile("ldmatrix.sync.aligned.m8n8.x4.shared.b16 {%0,%1,%2,%3}, [%4];"
                 : "=r"(r[0]), "=r"(r[1]), "=r"(r[2]), "=r"(r[3]) : "r"(addr));
}
__device__ __forceinline__ void ldsm_x4_t(uint32_t* r, uint32_t addr) {
    asm volatile("ldmatrix.sync.aligned.m8n8.x4.trans.shared.b16 {%0,%1,%2,%3}, [%4];"
                 : "=r"(r[0]), "=r"(r[1]), "=r"(r[2]), "=r"(r[3]) : "r"(addr));
}
__device__ __forceinline__ void mma_bf16(float* d, const uint32_t* a, const uint32_t* b) {
    asm volatile(
        "mma.sync.aligned.m16n8k16.row.col.f32.bf16.bf16.f32 "
        "{%0,%1,%2,%3}, {%4,%5,%6,%7}, {%8,%9}, {%0,%1,%2,%3};"
        : "+f"(d[0]), "+f"(d[1]), "+f"(d[2]), "+f"(d[3])
        : "r"(a[0]), "r"(a[1]), "r"(a[2]), "r"(a[3]), "r"(b[0]), "r"(b[1]));
}
__device__ __forceinline__ void mma_f16(float* d, const uint32_t* a, const uint32_t* b) {
    asm volatile(
        "mma.sync.aligned.m16n8k16.row.col.f32.f16.f16.f32 "
        "{%0,%1,%2,%3}, {%4,%5,%6,%7}, {%8,%9}, {%0,%1,%2,%3};"
        : "+f"(d[0]), "+f"(d[1]), "+f"(d[2]), "+f"(d[3])
        : "r"(a[0]), "r"(a[1]), "r"(a[2]), "r"(a[3]), "r"(b[0]), "r"(b[1]));
}
__device__ __forceinline__ uint32_t pack2(float a, float b) {
    __nv_bfloat162 p = __floats2bfloat162_rn(a, b);
    return *(uint32_t*)&p;
}
// 16-byte vector fp16 reduction (sm_90+): 8 halves per op
__device__ __forceinline__ void red_add_v4h2(__half* p, uint4 v) {
    asm volatile("red.global.add.noftz.v4.f16x2 [%0], {%1, %2, %3, %4};"
                 :: "l"(p), "r"(v.x), "r"(v.y), "r"(v.z), "r"(v.w) : "memory");
}
// relu(bf16x2(p) + bf16x2(q)) in fp32, repacked bf16x2 (b1 pre-folded into P)
__device__ __forceinline__ uint32_t addrelu2(uint32_t p, uint32_t q) {
    float2 fp = __bfloat1622float2(*(__nv_bfloat162*)&p);
    float2 fq = __bfloat1622float2(*(__nv_bfloat162*)&q);
    return pack2(fmaxf(fp.x + fq.x, 0.f), fmaxf(fp.y + fq.y, 0.f));
}

#define WPITCH 272   // b16 tile pitch for 128-col matrices
#define BPITCH 528   // b16 tile pitch for 256-col matrices

// Warp-tile GEMM (ACCUMULATES into d; caller zeroes). WP = weight pitch.
template <int NK, int AP, int WP, int F16>
__device__ __forceinline__ void gemm_tile(uint32_t abase, uint32_t wbase,
                                          int wr, int wc, int lane,
                                          float d[2][4][4]) {
    const int l15 = lane & 15;
    const int kh  = (lane >> 4) << 3;
#pragma unroll
    for (int ks = 0; ks < NK; ks++) {
        uint32_t a[2][4], b[4][2];
#pragma unroll
        for (int mi = 0; mi < 2; mi++) {
            uint32_t addr = abase + (uint32_t)((wr * 32 + mi * 16 + l15) * AP +
                                               (ks * 16 + kh) * 2);
            ldsm_x4(a[mi], addr);
        }
#pragma unroll
        for (int nj = 0; nj < 2; nj++) {
            uint32_t addr = wbase + (uint32_t)((ks * 16 + l15) * WP +
                                               (wc * 32 + nj * 16 + kh) * 2);
            uint32_t t[4];
            ldsm_x4_t(t, addr);
            b[2 * nj][0] = t[0]; b[2 * nj][1] = t[1];
            b[2 * nj + 1][0] = t[2]; b[2 * nj + 1][1] = t[3];
        }
#pragma unroll
        for (int mi = 0; mi < 2; mi++)
#pragma unroll
            for (int ni = 0; ni < 4; ni++) {
                if (F16) mma_f16(d[mi][ni], a[mi], b[ni]);
                else     mma_bf16(d[mi][ni], a[mi], b[ni]);
            }
    }
}
// Fused two-B-matrix GEMM: A-fragments loaded once, both B matrices streamed.
template <int NK, int AP, int WP, int F16>
__device__ __forceinline__ void gemm_tile2(uint32_t abase, uint32_t wbase0,
                                           uint32_t wbase1,
                                           int wr, int wc, int lane,
                                           float d[2][4][4]) {
    const int l15 = lane & 15;
    const int kh  = (lane >> 4) << 3;
#pragma unroll
    for (int ks = 0; ks < NK; ks++) {
        uint32_t a[2][4], b[4][2];
#pragma unroll
        for (int mi = 0; mi < 2; mi++) {
            uint32_t addr = abase + (uint32_t)((wr * 32 + mi * 16 + l15) * AP +
                                               (ks * 16 + kh) * 2);
            ldsm_x4(a[mi], addr);
        }
#pragma unroll
        for (int w2 = 0; w2 < 2; w2++) {
            uint32_t wb = w2 ? wbase1 : wbase0;
#pragma unroll
            for (int nj = 0; nj < 2; nj++) {
                uint32_t addr = wb + (uint32_t)((ks * 16 + l15) * WP +
                                                (wc * 32 + nj * 16 + kh) * 2);
                uint32_t t[4];
                ldsm_x4_t(t, addr);
                b[2 * nj][0] = t[0]; b[2 * nj][1] = t[1];
                b[2 * nj + 1][0] = t[2]; b[2 * nj + 1][1] = t[3];
            }
#pragma unroll
            for (int mi = 0; mi < 2; mi++)
#pragma unroll
                for (int ni = 0; ni < 4; ni++) {
                    if (F16) mma_f16(d[mi][ni], a[mi], b[ni]);
                    else     mma_bf16(d[mi][ni], a[mi], b[ni]);
                }
        }
    }
}
__device__ __forceinline__ void zero_d(float d[2][4][4]) {
#pragma unroll
    for (int mi = 0; mi < 2; mi++)
#pragma unroll
        for (int ni = 0; ni < 4; ni++)
#pragma unroll
            for (int x = 0; x < 4; x++) d[mi][ni][x] = 0.f;
}

// ---------------------------------------------------------------------------
// k_prep (setup absorbed): per-block prologue zeroes a slice of g_S/g_deg;
// blocks 0-31 also compute W3n = W3@Wn1_bot (+bn3 on block 0). Then the
// main persistent loop computes per 128-row tile:
//   PQ = h@[W1_top | W1_bot] + [b1 | 0]  (bf16 hi, ONE pass) -> g_PQ
//   R  = h@Wn1_top 3-term split (HH a-frags shared WH+WL)    -> g_R
// k_edge (consumer of S/deg/PQ) launches strictly after k_prep completes.
// ---------------------------------------------------------------------------
#define P_W1  0        // 128 x 528 = 67584 (bf16, 256 cols)
#define P_WH  67584
#define P_WL  102400
#define P_HH  137216
#define P_HL  172032
#define SM_PREP_TOTAL 206848

__global__ __launch_bounds__(512, 1) void k_prep(
    const float* __restrict__ h, const float* __restrict__ W1,
    const float* __restrict__ Wn1, const float* __restrict__ b1,
    const float* __restrict__ W3, const float* __restrict__ b3)
{
    extern __shared__ __align__(16) char sm[];
    const uint32_t sbase = smem_u32(sm);
    const int tid = threadIdx.x, wid = tid >> 5, lane = tid & 31;
    const int wr = wid & 3, wc = wid >> 2;   // 4x4 warp grid
    const int l15 = lane & 15, kh = (lane >> 4) << 3;
    const int g = lane >> 2, q = lane & 3;

    // --- absorbed setup: zero S/deg slices (all blocks) ---
    {
        const uint4 z = make_uint4(0, 0, 0, 0);
        const int nS = V_N * 128 / 8;
        const int stride = gridDim.x * 512;
        for (int i = blockIdx.x * 512 + tid; i < nS; i += stride)
            ((uint4*)g_S)[i] = z;
        const int nD = V_N / 4;
        for (int i = blockIdx.x * 512 + tid; i < nD; i += stride)
            ((uint4*)g_deg)[i] = z;
    }
    // --- absorbed setup: W3n (blocks 0-31, 4 rows each) + bn3 (block 0) ---
    if (blockIdx.x < 32) {
        const int k = blockIdx.x * 4 + (tid >> 7), n = tid & 127;
        float s = 0.f;
        for (int j = 0; j < 128; j++)
            s += W3[k * 128 + j] * Wn1[(128 + j) * 128 + n];
        g_W3n[k * 128 + n] = __float2half(s);
        if (blockIdx.x == 0 && tid < 128) {
            float s2 = 0.f;
            for (int j = 0; j < 128; j++)
                s2 += b3[j] * Wn1[(128 + j) * 128 + n];
            g_bn3[n] = s2;
        }
    }

    // --- weight staging ---
    for (int i = tid; i < 128 * 256; i += 512) {
        int k = i >> 8, n = i & 255;
        float w = (n < 128) ? W1[k * 128 + n] : W1[(128 + k) * 128 + (n - 128)];
        *(__nv_bfloat16*)(sm + P_W1 + k * BPITCH + n * 2) = __float2bfloat16(w);
    }
    for (int i = tid; i < 128 * 128; i += 512) {
        int k = i >> 7, n = i & 127;
        float w = Wn1[k * 128 + n];
        __nv_bfloat16 whi = __float2bfloat16(w);
        *(__nv_bfloat16*)(sm + P_WH + k * WPITCH + n * 2) = whi;
        *(__nv_bfloat16*)(sm + P_WL + k * WPITCH + n * 2) =
            __float2bfloat16(w - __bfloat162float(whi));
    }
    __syncthreads();

    const float4* h4 = (const float4*)h;
    const int numTiles = (V_N + 127) / 128;   // 391

    for (int tile = blockIdx.x; tile < numTiles; tile += gridDim.x) {
        const int n0 = tile * 128;
        __syncthreads();
        for (int i = tid; i < 128 * 32; i += 512) {
            int r = i >> 5, j = i & 31;
            int node = n0 + r;
            float4 v = (node < V_N) ? h4[(size_t)node * 32 + j]
                                    : make_float4(0.f, 0.f, 0.f, 0.f);
            __nv_bfloat16 h0 = __float2bfloat16(v.x), h1 = __float2bfloat16(v.y);
            __nv_bfloat16 h2 = __float2bfloat16(v.z), h3 = __float2bfloat16(v.w);
            uint2 uh, ul;
            uh.x = pack2(__bfloat162float(h0), __bfloat162float(h1));
            uh.y = pack2(__bfloat162float(h2), __bfloat162float(h3));
            ul.x = pack2(v.x - __bfloat162float(h0), v.y - __bfloat162float(h1));
            ul.y = pack2(v.z - __bfloat162float(h2), v.w - __bfloat162float(h3));
            *(uint2*)(sm + P_HH + r * WPITCH + j * 8) = uh;
            *(uint2*)(sm + P_HL + r * WPITCH + j * 8) = ul;
        }
        __syncthreads();

        // ---- PQ: single pass, warp tile 32 rows x 64 cols; +b1 on P half ----
        {
            float dq[2][8][4];
#pragma unroll
            for (int mi = 0; mi < 2; mi++)
#pragma unroll
                for (int ni = 0; ni < 8; ni++)
#pragma unroll
                    for (int x = 0; x < 4; x++) dq[mi][ni][x] = 0.f;

#pragma unroll
            for (int ks = 0; ks < 8; ks++) {
                uint32_t a[2][4], b[8][2];
#pragma unroll
                for (int mi = 0; mi < 2; mi++) {
                    uint32_t addr = sbase + P_HH +
                        (uint32_t)((wr * 32 + mi * 16 + l15) * WPITCH +
                                   (ks * 16 + kh) * 2);
                    ldsm_x4(a[mi], addr);
                }
#pragma unroll
                for (int nj = 0; nj < 4; nj++) {
                    uint32_t addr = sbase + P_W1 +
                        (uint32_t)((ks * 16 + l15) * BPITCH +
                                   (wc * 64 + nj * 16 + kh) * 2);
                    uint32_t t[4];
                    ldsm_x4_t(t, addr);
                    b[2 * nj][0] = t[0]; b[2 * nj][1] = t[1];
                    b[2 * nj + 1][0] = t[2]; b[2 * nj + 1][1] = t[3];
                }
#pragma unroll
                for (int mi = 0; mi < 2; mi++)
#pragma unroll
                    for (int ni = 0; ni < 8; ni++)
                        mma_bf16(dq[mi][ni], a[mi], b[ni]);
            }

            const bool isP = (wc < 2);   // cols < 128 -> P half
#pragma unroll
            for (int mi = 0; mi < 2; mi++) {
                const int rA = wr * 32 + mi * 16 + g;
                const int nodeA = n0 + rA, nodeB = nodeA + 8;
#pragma unroll
                for (int ni = 0; ni < 8; ni++) {
                    const int c = wc * 64 + ni * 8 + 2 * q;
                    float bx = 0.f, by = 0.f;
                    if (isP) { float2 bv = *(const float2*)&b1[c]; bx = bv.x; by = bv.y; }
                    if (nodeA < V_N)
                        *(uint32_t*)&g_PQ[(size_t)nodeA * 256 + c] =
                            pack2(dq[mi][ni][0] + bx, dq[mi][ni][1] + by);
                    if (nodeB < V_N)
                        *(uint32_t*)&g_PQ[(size_t)nodeB * 256 + c] =
                            pack2(dq[mi][ni][2] + bx, dq[mi][ni][3] + by);
                }
            }
        }

        // ---- R: 3-term split; HH a-frags shared between WH and WL ----
        {
            float d[2][4][4];
            zero_d(d);
            gemm_tile2<8, WPITCH, WPITCH, 0>(sbase + P_HH, sbase + P_WH,
                                             sbase + P_WL, wr, wc, lane, d);
            gemm_tile<8, WPITCH, WPITCH, 0>(sbase + P_HL, sbase + P_WH,
                                            wr, wc, lane, d);

#pragma unroll
            for (int mi = 0; mi < 2; mi++) {
                const int rA = wr * 32 + mi * 16 + g;
                const int nodeA = n0 + rA, nodeB = nodeA + 8;
#pragma unroll
                for (int ni = 0; ni < 4; ni++) {
                    const int c = wc * 32 + ni * 8 + 2 * q;
                    if (nodeA < V_N)
                        *(float2*)&g_R[(size_t)nodeA * 128 + c] =
                            make_float2(d[mi][ni][0], d[mi][ni][1]);
                    if (nodeB < V_N)
                        *(float2*)&g_R[(size_t)nodeB * 128 + c] =
                            make_float2(d[mi][ni][2], d[mi][ni][3]);
                }
            }
        }
    }
}

// ---------------------------------------------------------------------------
// k_edge: 64-edge tiles, 256 threads, TWO CTAs per SM.
//   A2 = relu(P'[src]+Q[dst]);  S[dst] += relu(A2@W2+b2);  deg[dst] += 1
// W2 columns stored PERMUTED (tau) -> one red.v4.f16x2 (16B) per row per mi.
// ---------------------------------------------------------------------------
#define SM_B2S  0        // 128 f32 = 512B (logical order)
#define SM_W2   512      // 128 x 272 = 34816 (permuted cols)
#define SM_A2A  35328    // 64 x 272 = 17408
#define SM_A2B  52736    // 17408
#define SM_EDGE_TOTAL 70144

__global__ __launch_bounds__(256, 2) void k_edge(
    const int* __restrict__ ei,
    const float* __restrict__ W2, const float* __restrict__ b2)
{
    extern __shared__ __align__(16) char sm[];
    float* b2s = (float*)(sm + SM_B2S);
    const uint32_t sbase = smem_u32(sm);
    const uint32_t sW2 = sbase + SM_W2;

    const int tid = threadIdx.x, wid = tid >> 5, lane = tid & 31;
    const int wr = wid & 1, wc = wid >> 1;   // 2x4 warp grid
    const int g = lane >> 2, q = lane & 3;

    // Stage W2 with column permutation tau
    for (int i = tid; i < 128 * 128; i += 256) {
        int k = i >> 7, n = i & 127;
        int t = n & 31, base = n & ~31;
        int q2 = t >> 3, rem = t & 7, ni2 = rem >> 1, jj = rem & 1;
        int tcol = base + ni2 * 8 + 2 * q2 + jj;   // stored position of logical n
        *(__nv_bfloat16*)(sm + SM_W2 + k * WPITCH + tcol * 2) = __float2bfloat16(W2[i]);
    }
    if (tid < 128) b2s[tid] = b2[tid];   // logical order
    __syncthreads();

    const int jg = tid & 15;                  // gather: 16B col group
    const int r0 = tid >> 4;                  // gather: base row (0..15)
    const int cb = wc * 32 + 8 * q;           // scatter: logical col base (8 cols)

    const int numTiles = E_N / 64;   // 12500
    float d[2][4][4];
    int buf = 0;

    // Prologue: gather first tile into buffer A
    int tile = blockIdx.x;
    if (tile < numTiles) {
        const int e0 = tile * 64;
        char* a2p = sm + SM_A2A;
#pragma unroll
        for (int k = 0; k < 4; k++) {
            int r = r0 + 16 * k;
            int s = ei[e0 + r], t = ei[E_N + e0 + r];
            uint4 P = *(const uint4*)&g_PQ[(size_t)s * 256 + jg * 8];
            uint4 Q = *(const uint4*)&g_PQ[(size_t)t * 256 + 128 + jg * 8];
            uint4 o;
            o.x = addrelu2(P.x, Q.x);
            o.y = addrelu2(P.y, Q.y);
            o.z = addrelu2(P.z, Q.z);
            o.w = addrelu2(P.w, Q.w);
            *(uint4*)(a2p + r * WPITCH + jg * 16) = o;
        }
    }

    for (; tile < numTiles; tile += gridDim.x) {
        const int e0 = tile * 64;
        const int rA = wr * 32 + g;

        // Prefetch scatter destinations (hide LDG latency behind GEMM2)
        int pd0 = ei[E_N + e0 + rA];
        int pd1 = ei[E_N + e0 + rA + 8];
        int pd2 = ei[E_N + e0 + rA + 16];
        int pd3 = ei[E_N + e0 + rA + 24];

        __syncthreads();   // A2[buf] ready; other buffer free

        // ---- GEMM2 on A2[buf] (output cols permuted) ----
        zero_d(d);
        gemm_tile<8, WPITCH, WPITCH, 0>(sbase + (buf ? SM_A2B : SM_A2A), sW2,
                                        wr, wc, lane, d);

        // ---- scatter: one 16B red per row per mi (+deg from col-group 0) ----
        {
            float2 bb0 = *(const float2*)&b2s[cb + 0];
            float2 bb1 = *(const float2*)&b2s[cb + 2];
            float2 bb2 = *(const float2*)&b2s[cb + 4];
            float2 bb3 = *(const float2*)&b2s[cb + 6];
#pragma unroll
            for (int mi = 0; mi < 2; mi++) {
                const int d0 = mi ? pd2 : pd0, d1 = mi ? pd3 : pd1;
                __half2 a0 = __floats2half2_rn(fmaxf(d[mi][0][0] + bb0.x, 0.f),
                                               fmaxf(d[mi][0][1] + bb0.y, 0.f));
                __half2 a1 = __floats2half2_rn(fmaxf(d[mi][1][0] + bb1.x, 0.f),
                                               fmaxf(d[mi][1][1] + bb1.y, 0.f));
                __half2 a2 = __floats2half2_rn(fmaxf(d[mi][2][0] + bb2.x, 0.f),
                                               fmaxf(d[mi][2][1] + bb2.y, 0.f));
                __half2 a3 = __floats2half2_rn(fmaxf(d[mi][3][0] + bb3.x, 0.f),
                                               fmaxf(d[mi][3][1] + bb3.y, 0.f));
                uint4 v0 = make_uint4(*(uint32_t*)&a0, *(uint32_t*)&a1,
                                      *(uint32_t*)&a2, *(uint32_t*)&a3);
                red_add_v4h2(&g_S[(size_t)d0 * 128 + cb], v0);

                __half2 c0 = __floats2half2_rn(fmaxf(d[mi][0][2] + bb0.x, 0.f),
                                               fmaxf(d[mi][0][3] + bb0.y, 0.f));
                __half2 c1 = __floats2half2_rn(fmaxf(d[mi][1][2] + bb1.x, 0.f),
                                               fmaxf(d[mi][1][3] + bb1.y, 0.f));
                __half2 c2 = __floats2half2_rn(fmaxf(d[mi][2][2] + bb2.x, 0.f),
                                               fmaxf(d[mi][2][3] + bb2.y, 0.f));
                __half2 c3 = __floats2half2_rn(fmaxf(d[mi][3][2] + bb3.x, 0.f),
                                               fmaxf(d[mi][3][3] + bb3.y, 0.f));
                uint4 v1 = make_uint4(*(uint32_t*)&c0, *(uint32_t*)&c1,
                                      *(uint32_t*)&c2, *(uint32_t*)&c3);
                red_add_v4h2(&g_S[(size_t)d1 * 128 + cb], v1);
            }
            if (wc == 0 && q == 0) {
                atomicAdd(&g_deg[pd0], 1);
                atomicAdd(&g_deg[pd1], 1);
                atomicAdd(&g_deg[pd2], 1);
                atomicAdd(&g_deg[pd3], 1);
            }
        }

        // ---- gather next tile into the other buffer ----
        const int nt = tile + gridDim.x;
        if (nt < numTiles) {
            const int ne0 = nt * 64;
            char* a2p = sm + (buf ? SM_A2A : SM_A2B);
#pragma unroll
            for (int k = 0; k < 4; k++) {
                int r = r0 + 16 * k;
                int s = ei[ne0 + r], t = ei[E_N + ne0 + r];
                uint4 P = *(const uint4*)&g_PQ[(size_t)s * 256 + jg * 8];
                uint4 Q = *(const uint4*)&g_PQ[(size_t)t * 256 + 128 + jg * 8];
                uint4 o;
                o.x = addrelu2(P.x, Q.x);
                o.y = addrelu2(P.y, Q.y);
                o.z = addrelu2(P.z, Q.z);
                o.w = addrelu2(P.w, Q.w);
                *(uint4*)(a2p + r * WPITCH + jg * 16) = o;
            }
        }
        buf ^= 1;
    }
}

// ---------------------------------------------------------------------------
// k_node: T = relu(R + S@W3n + deg*bn3 + bn1); out = T@Wn2 (3-term split,
// Thi a-frags shared across W2H/W2L).
// ---------------------------------------------------------------------------
#define N_B1  0         // bn1 512B
#define N_B2  512       // bn2 512B
#define N_B3  1024      // bn3 512B
#define N_W3N 1536      // fp16 W3n, 128 x 272 = 34816
#define N_W2H 36352
#define N_W2L 71168
#define N_XS  105984    // S staged fp16, 128 x 272
#define N_THI 140800
#define N_TLO 175616
#define SM_NODE_TOTAL 210432

__global__ __launch_bounds__(512, 1) void k_node(
    const float* __restrict__ bn1,
    const float* __restrict__ Wn2, const float* __restrict__ bn2,
    float* __restrict__ out)
{
    extern __shared__ __align__(16) char sm[];
    float* bn1s = (float*)(sm + N_B1);
    float* bn2s = (float*)(sm + N_B2);
    float* bn3s = (float*)(sm + N_B3);
    const uint32_t sbase = smem_u32(sm);
    const int tid = threadIdx.x, wid = tid >> 5, lane = tid & 31;
    const int wr = wid & 3, wc = wid >> 2;
    const int g = lane >> 2, q = lane & 3;

    for (int i = tid; i < 128 * 128; i += 512) {
        int k = i >> 7, n = i & 127;
        *(__half*)(sm + N_W3N + k * WPITCH + n * 2) = g_W3n[i];
        float w2 = Wn2[i];
        __nv_bfloat16 whi = __float2bfloat16(w2);
        *(__nv_bfloat16*)(sm + N_W2H + k * WPITCH + n * 2) = whi;
        *(__nv_bfloat16*)(sm + N_W2L + k * WPITCH + n * 2) =
            __float2bfloat16(w2 - __bfloat162float(whi));
    }
    if (tid < 128) { bn1s[tid] = bn1[tid]; bn2s[tid] = bn2[tid]; bn3s[tid] = g_bn3[tid]; }
    __syncthreads();

    float d[2][4][4];
    const int numTiles = (V_N + 127) / 128;   // 391

    for (int tile = blockIdx.x; tile < numTiles; tile += gridDim.x) {
        const int n0 = tile * 128;
        __syncthreads();
        for (int i = tid; i < 128 * 16; i += 512) {
            int r = i >> 4, j = i & 15;
            int node = n0 + r;
            uint4 v = (node < V_N) ? *(const uint4*)&g_S[(size_t)node * 128 + j * 8]
                                   : make_uint4(0, 0, 0, 0);
            *(uint4*)(sm + N_XS + r * WPITCH + j * 16) = v;
        }
        __syncthreads();

        // GEMM A: S @ W3n (fp16)
        zero_d(d);
        gemm_tile<8, WPITCH, WPITCH, 1>(sbase + N_XS, sbase + N_W3N, wr, wc, lane, d);

        // T = relu(d + R + deg*bn3 + bn1), split -> Thi/Tlo
#pragma unroll
        for (int mi = 0; mi < 2; mi++) {
            const int rA = wr * 32 + mi * 16 + g;
            const int nodeA = n0 + rA, nodeB = nodeA + 8;
            const float degA = (nodeA < V_N) ? (float)g_deg[nodeA] : 0.f;
            const float degB = (nodeB < V_N) ? (float)g_deg[nodeB] : 0.f;
#pragma unroll
            for (int ni = 0; ni < 4; ni++) {
                const int c = wc * 32 + ni * 8 + 2 * q;
                float2 bb = *(const float2*)&bn1s[c];
                float2 b3v = *(const float2*)&bn3s[c];
                float2 r0 = (nodeA < V_N) ? *(const float2*)&g_R[(size_t)nodeA * 128 + c]
                                          : make_float2(0.f, 0.f);
                float2 r1 = (nodeB < V_N) ? *(const float2*)&g_R[(size_t)nodeB * 128 + c]
                                          : make_float2(0.f, 0.f);
                float t0 = fmaxf(d[mi][ni][0] + r0.x + degA * b3v.x + bb.x, 0.f);
                float t1 = fmaxf(d[mi][ni][1] + r0.y + degA * b3v.y + bb.y, 0.f);
                float t2 = fmaxf(d[mi][ni][2] + r1.x + degB * b3v.x + bb.x, 0.f);
                float t3 = fmaxf(d[mi][ni][3] + r1.y + degB * b3v.y + bb.y, 0.f);
                __nv_bfloat16 h0 = __float2bfloat16(t0), h1 = __float2bfloat16(t1);
                __nv_bfloat16 h2 = __float2bfloat16(t2), h3 = __float2bfloat16(t3);
                *(uint32_t*)(sm + N_THI + rA * WPITCH + c * 2) =
                    pack2(__bfloat162float(h0), __bfloat162float(h1));
                *(uint32_t*)(sm + N_THI + (rA + 8) * WPITCH + c * 2) =
                    pack2(__bfloat162float(h2), __bfloat162float(h3));
                *(uint32_t*)(sm + N_TLO + rA * WPITCH + c * 2) =
                    pack2(t0 - __bfloat162float(h0), t1 - __bfloat162float(h1));
                *(uint32_t*)(sm + N_TLO + (rA + 8) * WPITCH + c * 2) =
                    pack2(t2 - __bfloat162float(h2), t3 - __bfloat162float(h3));
            }
        }
        __syncthreads();

        // GEMM B: out = Thi@(W2hi+W2lo) + Tlo@W2hi + bn2 (Thi a-frags shared)
        zero_d(d);
        gemm_tile2<8, WPITCH, WPITCH, 0>(sbase + N_THI, sbase + N_W2H,
                                         sbase + N_W2L, wr, wc, lane, d);
        gemm_tile<8, WPITCH, WPITCH, 0>(sbase + N_TLO, sbase + N_W2H, wr, wc, lane, d);

#pragma unroll
        for (int mi = 0; mi < 2; mi++) {
            const int rA = wr * 32 + mi * 16 + g;
            const int nodeA = n0 + rA, nodeB = nodeA + 8;
#pragma unroll
            for (int ni = 0; ni < 4; ni++) {
                const int c = wc * 32 + ni * 8 + 2 * q;
                float2 bb = *(const float2*)&bn2s[c];
                if (nodeA < V_N)
                    *(float2*)&out[(size_t)nodeA * 128 + c] =
                        make_float2(d[mi][ni][0] + bb.x, d[mi][ni][1] + bb.y);
                if (nodeB < V_N)
                    *(float2*)&out[(size_t)nodeB * 128 + c] =
                        make_float2(d[mi][ni][2] + bb.x, d[mi][ni][3] + bb.y);
            }
        }
    }
}

// ---------------------------------------------------------------------------
extern "C" void kernel_launch(void* const* d_in, const int* in_sizes, int n_in,
                              void* d_out, int out_size) {
    const float* h   = (const float*)d_in[0];
    const int*   ei  = (const int*)d_in[1];   // int32 (JAX x64 disabled)
    const float* W1  = (const float*)d_in[2];
    const float* b1  = (const float*)d_in[3];
    const float* W2  = (const float*)d_in[4];
    const float* b2  = (const float*)d_in[5];
    const float* W3  = (const float*)d_in[6];
    const float* b3  = (const float*)d_in[7];
    const float* Wn1 = (const float*)d_in[8];
    const float* bn1 = (const float*)d_in[9];
    const float* Wn2 = (const float*)d_in[10];
    const float* bn2 = (const float*)d_in[11];
    float*       out = (float*)d_out;

    cudaFuncSetAttribute(k_prep, cudaFuncAttributeMaxDynamicSharedMemorySize, SM_PREP_TOTAL);
    cudaFuncSetAttribute(k_edge, cudaFuncAttributeMaxDynamicSharedMemorySize, SM_EDGE_TOTAL);
    cudaFuncSetAttribute(k_node, cudaFuncAttributeMaxDynamicSharedMemorySize, SM_NODE_TOTAL);

    k_prep<<<148, 512, SM_PREP_TOTAL>>>(h, W1, Wn1, b1, W3, b3);
    k_edge<<<296, 256, SM_EDGE_TOTAL>>>(ei, W2, b2);
    k_node<<<148, 512, SM_NODE_TOTAL>>>(bn1, Wn2, bn2, out);
}

// round 17
// speedup vs baseline: 1.5165x; 1.0426x over previous
#include <cuda_runtime.h>
#include <cuda_bf16.h>
#include <cuda_fp16.h>
#include <cstdint>

// Problem constants (fixed shapes)
#define V_N 50000
#define E_N 800000

// Scratch (static device arrays — no runtime allocation)
__device__ __half g_S[(size_t)V_N * 128];           // Σ relu(A2@W2+b2) per node, fp16
__device__ int    g_deg[V_N];                       // in-degree
__device__ __nv_bfloat16 g_PQ[(size_t)V_N * 256];   // [P+b1 | Q], bf16, sigma-permuted cols
__device__ float  g_R[(size_t)V_N * 128];           // h @ Wn1_top, rho-permuted cols
__device__ __half g_W3n[128 * 128];                 // W3 @ Wn1_bot, fp16
__device__ float  g_bn3[128];                       // b3 @ Wn1_bot

// ============================================================================
// Warp-level MMA helpers (base PTX: ldmatrix sm_75+, mma.sync sm_80+)
// ============================================================================
__device__ __forceinline__ uint32_t smem_u32(const void* p) {
    uint32_t a;
    asm("{ .reg .u64 t; cvta.to.shared.u64 t, %1; cvt.u32.u64 %0, t; }"
        : "=r"(a) : "l"(p));
    return a;
}
__device__ __forceinline__ void ldsm_x4(uint32_t* r, uint32_t addr) {
    asm volatile("ldmatrix.sync.aligned.m8n8.x4.shared.b16 {%0,%1,%2,%3}, [%4];"
                 : "=r"(r[0]), "=r"(r[1]), "=r"(r[2]), "=r"(r[3]) : "r"(addr));
}
__device__ __forceinline__ void ldsm_x4_t(uint32_t* r, uint32_t addr) {
    asm volatile("ldmatrix.sync.aligned.m8n8.x4.trans.shared.b16 {%0,%1,%2,%3}, [%4];"
                 : "=r"(r[0]), "=r"(r[1]), "=r"(r[2]), "=r"(r[3]) : "r"(addr));
}
__device__ __forceinline__ void mma_bf16(float* d, const uint32_t* a, const uint32_t* b) {
    asm volatile(
        "mma.sync.aligned.m16n8k16.row.col.f32.bf16.bf16.f32 "
        "{%0,%1,%2,%3}, {%4,%5,%6,%7}, {%8,%9}, {%0,%1,%2,%3};"
        : "+f"(d[0]), "+f"(d[1]), "+f"(d[2]), "+f"(d[3])
        : "r"(a[0]), "r"(a[1]), "r"(a[2]), "r"(a[3]), "r"(b[0]), "r"(b[1]));
}
__device__ __forceinline__ void mma_f16(float* d, const uint32_t* a, const uint32_t* b) {
    asm volatile(
        "mma.sync.aligned.m16n8k16.row.col.f32.f16.f16.f32 "
        "{%0,%1,%2,%3}, {%4,%5,%6,%7}, {%8,%9}, {%0,%1,%2,%3};"
        : "+f"(d[0]), "+f"(d[1]), "+f"(d[2]), "+f"(d[3])
        : "r"(a[0]), "r"(a[1]), "r"(a[2]), "r"(a[3]), "r"(b[0]), "r"(b[1]));
}
__device__ __forceinline__ uint32_t pack2(float a, float b) {
    __nv_bfloat162 p = __floats2bfloat162_rn(a, b);
    return *(uint32_t*)&p;
}
// 16-byte vector fp16 reduction (sm_90+): 8 halves per op
__device__ __forceinline__ void red_add_v4h2(__half* p, uint4 v) {
    asm volatile("red.global.add.noftz.v4.f16x2 [%0], {%1, %2, %3, %4};"
                 :: "l"(p), "r"(v.x), "r"(v.y), "r"(v.z), "r"(v.w) : "memory");
}
// relu(p + q) in native bf16x2 (numerically identical to f32 path: fp32 add of
// two bf16 is exact, so both compute round(P+Q); relu exact).
__device__ __forceinline__ uint32_t addrelu2(uint32_t p, uint32_t q) {
    __nv_bfloat162 s = __hadd2(*(__nv_bfloat162*)&p, *(__nv_bfloat162*)&q);
    __nv_bfloat162 z = __floats2bfloat162_rn(0.f, 0.f);
    s = __hmax2(s, z);
    return *(uint32_t*)&s;
}
// sigma: within each 64-col group, logical (ni*8 + 2q + j) -> 16q + 2ni + j
__device__ __forceinline__ int sigma_col(int c) {
    return (c & ~63) + (((c >> 1) & 3) << 4) + (((c >> 3) & 7) << 1) + (c & 1);
}

#define WPITCH 272   // b16 tile pitch for 128-col matrices
#define BPITCH 528   // b16 tile pitch for 256-col matrices

// Warp-tile GEMM (ACCUMULATES into d; caller zeroes). WP = weight pitch.
template <int NK, int AP, int WP, int F16>
__device__ __forceinline__ void gemm_tile(uint32_t abase, uint32_t wbase,
                                          int wr, int wc, int lane,
                                          float d[2][4][4]) {
    const int l15 = lane & 15;
    const int kh  = (lane >> 4) << 3;
#pragma unroll
    for (int ks = 0; ks < NK; ks++) {
        uint32_t a[2][4], b[4][2];
#pragma unroll
        for (int mi = 0; mi < 2; mi++) {
            uint32_t addr = abase + (uint32_t)((wr * 32 + mi * 16 + l15) * AP +
                                               (ks * 16 + kh) * 2);
            ldsm_x4(a[mi], addr);
        }
#pragma unroll
        for (int nj = 0; nj < 2; nj++) {
            uint32_t addr = wbase + (uint32_t)((ks * 16 + l15) * WP +
                                               (wc * 32 + nj * 16 + kh) * 2);
            uint32_t t[4];
            ldsm_x4_t(t, addr);
            b[2 * nj][0] = t[0]; b[2 * nj][1] = t[1];
            b[2 * nj + 1][0] = t[2]; b[2 * nj + 1][1] = t[3];
        }
#pragma unroll
        for (int mi = 0; mi < 2; mi++)
#pragma unroll
            for (int ni = 0; ni < 4; ni++) {
                if (F16) mma_f16(d[mi][ni], a[mi], b[ni]);
                else     mma_bf16(d[mi][ni], a[mi], b[ni]);
            }
    }
}
// Fused two-B-matrix GEMM: A-fragments loaded once, both B matrices streamed.
template <int NK, int AP, int WP, int F16>
__device__ __forceinline__ void gemm_tile2(uint32_t abase, uint32_t wbase0,
                                           uint32_t wbase1,
                                           int wr, int wc, int lane,
                                           float d[2][4][4]) {
    const int l15 = lane & 15;
    const int kh  = (lane >> 4) << 3;
#pragma unroll
    for (int ks = 0; ks < NK; ks++) {
        uint32_t a[2][4], b[4][2];
#pragma unroll
        for (int mi = 0; mi < 2; mi++) {
            uint32_t addr = abase + (uint32_t)((wr * 32 + mi * 16 + l15) * AP +
                                               (ks * 16 + kh) * 2);
            ldsm_x4(a[mi], addr);
        }
#pragma unroll
        for (int w2 = 0; w2 < 2; w2++) {
            uint32_t wb = w2 ? wbase1 : wbase0;
#pragma unroll
            for (int nj = 0; nj < 2; nj++) {
                uint32_t addr = wb + (uint32_t)((ks * 16 + l15) * WP +
                                                (wc * 32 + nj * 16 + kh) * 2);
                uint32_t t[4];
                ldsm_x4_t(t, addr);
                b[2 * nj][0] = t[0]; b[2 * nj][1] = t[1];
                b[2 * nj + 1][0] = t[2]; b[2 * nj + 1][1] = t[3];
            }
#pragma unroll
            for (int mi = 0; mi < 2; mi++)
#pragma unroll
                for (int ni = 0; ni < 4; ni++) {
                    if (F16) mma_f16(d[mi][ni], a[mi], b[ni]);
                    else     mma_bf16(d[mi][ni], a[mi], b[ni]);
                }
        }
    }
}
__device__ __forceinline__ void zero_d(float d[2][4][4]) {
#pragma unroll
    for (int mi = 0; mi < 2; mi++)
#pragma unroll
        for (int ni = 0; ni < 4; ni++)
#pragma unroll
            for (int x = 0; x < 4; x++) d[mi][ni][x] = 0.f;
}

// ---------------------------------------------------------------------------
// k_prep (setup absorbed): zero S/deg slices; blocks 0-31 compute W3n (+bn3).
// Main loop per 128-row tile:
//   PQ = h@[W1_top | W1_bot] + [b1 | 0]  (bf16 hi, ONE pass) -> g_PQ (sigma)
//   R  = h@Wn1_top 3-term split                               -> g_R (rho)
// ---------------------------------------------------------------------------
#define P_W1  0        // 128 x 528 = 67584 (bf16, 256 cols)
#define P_WH  67584
#define P_WL  102400
#define P_HH  137216
#define P_HL  172032
#define SM_PREP_TOTAL 206848

__global__ __launch_bounds__(512, 1) void k_prep(
    const float* __restrict__ h, const float* __restrict__ W1,
    const float* __restrict__ Wn1, const float* __restrict__ b1,
    const float* __restrict__ W3, const float* __restrict__ b3)
{
    extern __shared__ __align__(16) char sm[];
    const uint32_t sbase = smem_u32(sm);
    const int tid = threadIdx.x, wid = tid >> 5, lane = tid & 31;
    const int wr = wid & 3, wc = wid >> 2;   // 4x4 warp grid
    const int l15 = lane & 15, kh = (lane >> 4) << 3;
    const int g = lane >> 2, q = lane & 3;

    // --- absorbed setup: zero S/deg slices (all blocks) ---
    {
        const uint4 z = make_uint4(0, 0, 0, 0);
        const int nS = V_N * 128 / 8;
        const int stride = gridDim.x * 512;
        for (int i = blockIdx.x * 512 + tid; i < nS; i += stride)
            ((uint4*)g_S)[i] = z;
        const int nD = V_N / 4;
        for (int i = blockIdx.x * 512 + tid; i < nD; i += stride)
            ((uint4*)g_deg)[i] = z;
    }
    // --- absorbed setup: W3n (blocks 0-31) + bn3 (block 0) ---
    if (blockIdx.x < 32) {
        const int k = blockIdx.x * 4 + (tid >> 7), n = tid & 127;
        float s = 0.f;
        for (int j = 0; j < 128; j++)
            s += W3[k * 128 + j] * Wn1[(128 + j) * 128 + n];
        g_W3n[k * 128 + n] = __float2half(s);
        if (blockIdx.x == 0 && tid < 128) {
            float s2 = 0.f;
            for (int j = 0; j < 128; j++)
                s2 += b3[j] * Wn1[(128 + j) * 128 + n];
            g_bn3[n] = s2;
        }
    }

    // --- weight staging ---
    for (int i = tid; i < 128 * 256; i += 512) {
        int k = i >> 8, n = i & 255;
        float w = (n < 128) ? W1[k * 128 + n] : W1[(128 + k) * 128 + (n - 128)];
        *(__nv_bfloat16*)(sm + P_W1 + k * BPITCH + n * 2) = __float2bfloat16(w);
    }
    for (int i = tid; i < 128 * 128; i += 512) {
        int k = i >> 7, n = i & 127;
        float w = Wn1[k * 128 + n];
        __nv_bfloat16 whi = __float2bfloat16(w);
        *(__nv_bfloat16*)(sm + P_WH + k * WPITCH + n * 2) = whi;
        *(__nv_bfloat16*)(sm + P_WL + k * WPITCH + n * 2) =
            __float2bfloat16(w - __bfloat162float(whi));
    }
    __syncthreads();

    const float4* h4 = (const float4*)h;
    const int numTiles = (V_N + 127) / 128;   // 391

    for (int tile = blockIdx.x; tile < numTiles; tile += gridDim.x) {
        const int n0 = tile * 128;
        __syncthreads();
        for (int i = tid; i < 128 * 32; i += 512) {
            int r = i >> 5, j = i & 31;
            int node = n0 + r;
            float4 v = (node < V_N) ? h4[(size_t)node * 32 + j]
                                    : make_float4(0.f, 0.f, 0.f, 0.f);
            __nv_bfloat16 h0 = __float2bfloat16(v.x), h1 = __float2bfloat16(v.y);
            __nv_bfloat16 h2 = __float2bfloat16(v.z), h3 = __float2bfloat16(v.w);
            uint2 uh, ul;
            uh.x = pack2(__bfloat162float(h0), __bfloat162float(h1));
            uh.y = pack2(__bfloat162float(h2), __bfloat162float(h3));
            ul.x = pack2(v.x - __bfloat162float(h0), v.y - __bfloat162float(h1));
            ul.y = pack2(v.z - __bfloat162float(h2), v.w - __bfloat162float(h3));
            *(uint2*)(sm + P_HH + r * WPITCH + j * 8) = uh;
            *(uint2*)(sm + P_HL + r * WPITCH + j * 8) = ul;
        }
        __syncthreads();

        // ---- PQ: single pass, warp tile 32 rows x 64 cols; +b1 on P half ----
        {
            float dq[2][8][4];
#pragma unroll
            for (int mi = 0; mi < 2; mi++)
#pragma unroll
                for (int ni = 0; ni < 8; ni++)
#pragma unroll
                    for (int x = 0; x < 4; x++) dq[mi][ni][x] = 0.f;

#pragma unroll
            for (int ks = 0; ks < 8; ks++) {
                uint32_t a[2][4], b[8][2];
#pragma unroll
                for (int mi = 0; mi < 2; mi++) {
                    uint32_t addr = sbase + P_HH +
                        (uint32_t)((wr * 32 + mi * 16 + l15) * WPITCH +
                                   (ks * 16 + kh) * 2);
                    ldsm_x4(a[mi], addr);
                }
#pragma unroll
                for (int nj = 0; nj < 4; nj++) {
                    uint32_t addr = sbase + P_W1 +
                        (uint32_t)((ks * 16 + l15) * BPITCH +
                                   (wc * 64 + nj * 16 + kh) * 2);
                    uint32_t t[4];
                    ldsm_x4_t(t, addr);
                    b[2 * nj][0] = t[0]; b[2 * nj][1] = t[1];
                    b[2 * nj + 1][0] = t[2]; b[2 * nj + 1][1] = t[3];
                }
#pragma unroll
                for (int mi = 0; mi < 2; mi++)
#pragma unroll
                    for (int ni = 0; ni < 8; ni++)
                        mma_bf16(dq[mi][ni], a[mi], b[ni]);
            }

            // Epilogue: sigma-permuted -> thread's 16 values are contiguous.
            // Stored at g_PQ[node*256 + wc*64 + 16q .. +16).
            const bool isP = (wc < 2);   // cols < 128 -> P half
#pragma unroll
            for (int mi = 0; mi < 2; mi++) {
                const int rA = wr * 32 + mi * 16 + g;
                const int nodeA = n0 + rA, nodeB = nodeA + 8;
                uint4 uA0, uA1, uB0, uB1;
                uint32_t* uA = (uint32_t*)&uA0;   // uA0,uA1 contiguous? build safely:
                uint32_t wordsA[8], wordsB[8];
#pragma unroll
                for (int ni = 0; ni < 8; ni++) {
                    const int c = wc * 64 + ni * 8 + 2 * q;   // logical col
                    float bx = 0.f, by = 0.f;
                    if (isP) { float2 bv = *(const float2*)&b1[c]; bx = bv.x; by = bv.y; }
                    wordsA[ni] = pack2(dq[mi][ni][0] + bx, dq[mi][ni][1] + by);
                    wordsB[ni] = pack2(dq[mi][ni][2] + bx, dq[mi][ni][3] + by);
                }
                uA0 = make_uint4(wordsA[0], wordsA[1], wordsA[2], wordsA[3]);
                uA1 = make_uint4(wordsA[4], wordsA[5], wordsA[6], wordsA[7]);
                uB0 = make_uint4(wordsB[0], wordsB[1], wordsB[2], wordsB[3]);
                uB1 = make_uint4(wordsB[4], wordsB[5], wordsB[6], wordsB[7]);
                (void)uA;
                const int base = wc * 64 + 16 * q;
                if (nodeA < V_N) {
                    *(uint4*)&g_PQ[(size_t)nodeA * 256 + base]     = uA0;
                    *(uint4*)&g_PQ[(size_t)nodeA * 256 + base + 8] = uA1;
                }
                if (nodeB < V_N) {
                    *(uint4*)&g_PQ[(size_t)nodeB * 256 + base]     = uB0;
                    *(uint4*)&g_PQ[(size_t)nodeB * 256 + base + 8] = uB1;
                }
            }
        }

        // ---- R: 3-term split; HH a-frags shared between WH and WL ----
        {
            float d[2][4][4];
            zero_d(d);
            gemm_tile2<8, WPITCH, WPITCH, 0>(sbase + P_HH, sbase + P_WH,
                                             sbase + P_WL, wr, wc, lane, d);
            gemm_tile<8, WPITCH, WPITCH, 0>(sbase + P_HL, sbase + P_WH,
                                            wr, wc, lane, d);

            // rho-permuted store: 8 contiguous floats at wc*32 + 8q.
#pragma unroll
            for (int mi = 0; mi < 2; mi++) {
                const int rA = wr * 32 + mi * 16 + g;
                const int nodeA = n0 + rA, nodeB = nodeA + 8;
                const int base = wc * 32 + 8 * q;
                if (nodeA < V_N) {
                    *(float4*)&g_R[(size_t)nodeA * 128 + base] =
                        make_float4(d[mi][0][0], d[mi][0][1], d[mi][1][0], d[mi][1][1]);
                    *(float4*)&g_R[(size_t)nodeA * 128 + base + 4] =
                        make_float4(d[mi][2][0], d[mi][2][1], d[mi][3][0], d[mi][3][1]);
                }
                if (nodeB < V_N) {
                    *(float4*)&g_R[(size_t)nodeB * 128 + base] =
                        make_float4(d[mi][0][2], d[mi][0][3], d[mi][1][2], d[mi][1][3]);
                    *(float4*)&g_R[(size_t)nodeB * 128 + base + 4] =
                        make_float4(d[mi][2][2], d[mi][2][3], d[mi][3][2], d[mi][3][3]);
                }
            }
        }
    }
}

// ---------------------------------------------------------------------------
// k_edge: 64-edge tiles, 256 threads, TWO CTAs per SM.
//   A2 = relu(P'[src]+Q[dst]);  S[dst] += relu(A2@W2+b2);  deg[dst] += 1
// W2 rows sigma-permuted (to match PQ column order) AND columns tau-permuted
// (so fragment scatter is one red.v4.f16x2 per row per mi).
// ---------------------------------------------------------------------------
#define SM_B2S  0        // 128 f32 = 512B (logical order)
#define SM_W2   512      // 128 x 272 = 34816 (perm rows+cols)
#define SM_A2A  35328    // 64 x 272 = 17408
#define SM_A2B  52736    // 17408
#define SM_EDGE_TOTAL 70144

__global__ __launch_bounds__(256, 2) void k_edge(
    const int* __restrict__ ei,
    const float* __restrict__ W2, const float* __restrict__ b2)
{
    extern __shared__ __align__(16) char sm[];
    float* b2s = (float*)(sm + SM_B2S);
    const uint32_t sbase = smem_u32(sm);
    const uint32_t sW2 = sbase + SM_W2;

    const int tid = threadIdx.x, wid = tid >> 5, lane = tid & 31;
    const int wr = wid & 1, wc = wid >> 1;   // 2x4 warp grid
    const int g = lane >> 2, q = lane & 3;

    // Stage W2: row position = sigma(k) (matches PQ/A2 K order),
    // col position = tau(n) (fragment-contiguous scatter).
    for (int i = tid; i < 128 * 128; i += 256) {
        int k = i >> 7, n = i & 127;
        int krow = sigma_col(k);
        int t = n & 31, base = n & ~31;
        int q2 = t >> 3, rem = t & 7, ni2 = rem >> 1, jj = rem & 1;
        int tcol = base + ni2 * 8 + 2 * q2 + jj;
        *(__nv_bfloat16*)(sm + SM_W2 + krow * WPITCH + tcol * 2) =
            __float2bfloat16(W2[i]);
    }
    if (tid < 128) b2s[tid] = b2[tid];   // logical order
    __syncthreads();

    const int jg = tid & 15;                  // gather: 16B col group
    const int r0 = tid >> 4;                  // gather: base row (0..15)
    const int cb = wc * 32 + 8 * q;           // scatter: logical col base (8 cols)

    const int numTiles = E_N / 64;   // 12500
    float d[2][4][4];
    int buf = 0;

    // Prologue: gather first tile into buffer A
    int tile = blockIdx.x;
    if (tile < numTiles) {
        const int e0 = tile * 64;
        char* a2p = sm + SM_A2A;
#pragma unroll
        for (int k = 0; k < 4; k++) {
            int r = r0 + 16 * k;
            int s = ei[e0 + r], t = ei[E_N + e0 + r];
            uint4 P = *(const uint4*)&g_PQ[(size_t)s * 256 + jg * 8];
            uint4 Q = *(const uint4*)&g_PQ[(size_t)t * 256 + 128 + jg * 8];
            uint4 o;
            o.x = addrelu2(P.x, Q.x);
            o.y = addrelu2(P.y, Q.y);
            o.z = addrelu2(P.z, Q.z);
            o.w = addrelu2(P.w, Q.w);
            *(uint4*)(a2p + r * WPITCH + jg * 16) = o;
        }
    }

    for (; tile < numTiles; tile += gridDim.x) {
        const int e0 = tile * 64;
        const int rA = wr * 32 + g;

        // Prefetch scatter destinations (hide LDG latency behind GEMM2)
        int pd0 = ei[E_N + e0 + rA];
        int pd1 = ei[E_N + e0 + rA + 8];
        int pd2 = ei[E_N + e0 + rA + 16];
        int pd3 = ei[E_N + e0 + rA + 24];

        __syncthreads();   // A2[buf] ready; other buffer free

        // ---- GEMM2 on A2[buf] (output cols tau-permuted) ----
        zero_d(d);
        gemm_tile<8, WPITCH, WPITCH, 0>(sbase + (buf ? SM_A2B : SM_A2A), sW2,
                                        wr, wc, lane, d);

        // ---- scatter: one 16B red per row per mi (+deg from col-group 0) ----
        {
            float2 bb0 = *(const float2*)&b2s[cb + 0];
            float2 bb1 = *(const float2*)&b2s[cb + 2];
            float2 bb2 = *(const float2*)&b2s[cb + 4];
            float2 bb3 = *(const float2*)&b2s[cb + 6];
#pragma unroll
            for (int mi = 0; mi < 2; mi++) {
                const int d0 = mi ? pd2 : pd0, d1 = mi ? pd3 : pd1;
                __half2 a0 = __floats2half2_rn(fmaxf(d[mi][0][0] + bb0.x, 0.f),
                                               fmaxf(d[mi][0][1] + bb0.y, 0.f));
                __half2 a1 = __floats2half2_rn(fmaxf(d[mi][1][0] + bb1.x, 0.f),
                                               fmaxf(d[mi][1][1] + bb1.y, 0.f));
                __half2 a2 = __floats2half2_rn(fmaxf(d[mi][2][0] + bb2.x, 0.f),
                                               fmaxf(d[mi][2][1] + bb2.y, 0.f));
                __half2 a3 = __floats2half2_rn(fmaxf(d[mi][3][0] + bb3.x, 0.f),
                                               fmaxf(d[mi][3][1] + bb3.y, 0.f));
                uint4 v0 = make_uint4(*(uint32_t*)&a0, *(uint32_t*)&a1,
                                      *(uint32_t*)&a2, *(uint32_t*)&a3);
                red_add_v4h2(&g_S[(size_t)d0 * 128 + cb], v0);

                __half2 c0 = __floats2half2_rn(fmaxf(d[mi][0][2] + bb0.x, 0.f),
                                               fmaxf(d[mi][0][3] + bb0.y, 0.f));
                __half2 c1 = __floats2half2_rn(fmaxf(d[mi][1][2] + bb1.x, 0.f),
                                               fmaxf(d[mi][1][3] + bb1.y, 0.f));
                __half2 c2 = __floats2half2_rn(fmaxf(d[mi][2][2] + bb2.x, 0.f),
                                               fmaxf(d[mi][2][3] + bb2.y, 0.f));
                __half2 c3 = __floats2half2_rn(fmaxf(d[mi][3][2] + bb3.x, 0.f),
                                               fmaxf(d[mi][3][3] + bb3.y, 0.f));
                uint4 v1 = make_uint4(*(uint32_t*)&c0, *(uint32_t*)&c1,
                                      *(uint32_t*)&c2, *(uint32_t*)&c3);
                red_add_v4h2(&g_S[(size_t)d1 * 128 + cb], v1);
            }
            if (wc == 0 && q == 0) {
                atomicAdd(&g_deg[pd0], 1);
                atomicAdd(&g_deg[pd1], 1);
                atomicAdd(&g_deg[pd2], 1);
                atomicAdd(&g_deg[pd3], 1);
            }
        }

        // ---- gather next tile into the other buffer ----
        const int nt = tile + gridDim.x;
        if (nt < numTiles) {
            const int ne0 = nt * 64;
            char* a2p = sm + (buf ? SM_A2A : SM_A2B);
#pragma unroll
            for (int k = 0; k < 4; k++) {
                int r = r0 + 16 * k;
                int s = ei[ne0 + r], t = ei[E_N + ne0 + r];
                uint4 P = *(const uint4*)&g_PQ[(size_t)s * 256 + jg * 8];
                uint4 Q = *(const uint4*)&g_PQ[(size_t)t * 256 + 128 + jg * 8];
                uint4 o;
                o.x = addrelu2(P.x, Q.x);
                o.y = addrelu2(P.y, Q.y);
                o.z = addrelu2(P.z, Q.z);
                o.w = addrelu2(P.w, Q.w);
                *(uint4*)(a2p + r * WPITCH + jg * 16) = o;
            }
        }
        buf ^= 1;
    }
}

// ---------------------------------------------------------------------------
// k_node: T = relu(R + S@W3n + deg*bn3 + bn1); out = T@Wn2 (3-term split,
// Thi a-frags shared). R read as 2x float4 (rho-permuted layout).
// ---------------------------------------------------------------------------
#define N_B1  0         // bn1 512B
#define N_B2  512       // bn2 512B
#define N_B3  1024      // bn3 512B
#define N_W3N 1536      // fp16 W3n, 128 x 272 = 34816
#define N_W2H 36352
#define N_W2L 71168
#define N_XS  105984    // S staged fp16, 128 x 272
#define N_THI 140800
#define N_TLO 175616
#define SM_NODE_TOTAL 210432

__global__ __launch_bounds__(512, 1) void k_node(
    const float* __restrict__ bn1,
    const float* __restrict__ Wn2, const float* __restrict__ bn2,
    float* __restrict__ out)
{
    extern __shared__ __align__(16) char sm[];
    float* bn1s = (float*)(sm + N_B1);
    float* bn2s = (float*)(sm + N_B2);
    float* bn3s = (float*)(sm + N_B3);
    const uint32_t sbase = smem_u32(sm);
    const int tid = threadIdx.x, wid = tid >> 5, lane = tid & 31;
    const int wr = wid & 3, wc = wid >> 2;
    const int g = lane >> 2, q = lane & 3;

    for (int i = tid; i < 128 * 128; i += 512) {
        int k = i >> 7, n = i & 127;
        *(__half*)(sm + N_W3N + k * WPITCH + n * 2) = g_W3n[i];
        float w2 = Wn2[i];
        __nv_bfloat16 whi = __float2bfloat16(w2);
        *(__nv_bfloat16*)(sm + N_W2H + k * WPITCH + n * 2) = whi;
        *(__nv_bfloat16*)(sm + N_W2L + k * WPITCH + n * 2) =
            __float2bfloat16(w2 - __bfloat162float(whi));
    }
    if (tid < 128) { bn1s[tid] = bn1[tid]; bn2s[tid] = bn2[tid]; bn3s[tid] = g_bn3[tid]; }
    __syncthreads();

    float d[2][4][4];
    const int numTiles = (V_N + 127) / 128;   // 391

    for (int tile = blockIdx.x; tile < numTiles; tile += gridDim.x) {
        const int n0 = tile * 128;
        __syncthreads();
        for (int i = tid; i < 128 * 16; i += 512) {
            int r = i >> 4, j = i & 15;
            int node = n0 + r;
            uint4 v = (node < V_N) ? *(const uint4*)&g_S[(size_t)node * 128 + j * 8]
                                   : make_uint4(0, 0, 0, 0);
            *(uint4*)(sm + N_XS + r * WPITCH + j * 16) = v;
        }
        __syncthreads();

        // GEMM A: S @ W3n (fp16)
        zero_d(d);
        gemm_tile<8, WPITCH, WPITCH, 1>(sbase + N_XS, sbase + N_W3N, wr, wc, lane, d);

        // T = relu(d + R + deg*bn3 + bn1), split -> Thi/Tlo
        const float4 z4 = make_float4(0.f, 0.f, 0.f, 0.f);
#pragma unroll
        for (int mi = 0; mi < 2; mi++) {
            const int rA = wr * 32 + mi * 16 + g;
            const int nodeA = n0 + rA, nodeB = nodeA + 8;
            const float degA = (nodeA < V_N) ? (float)g_deg[nodeA] : 0.f;
            const float degB = (nodeB < V_N) ? (float)g_deg[nodeB] : 0.f;
            const int rbase = wc * 32 + 8 * q;
            float4 rAv0 = z4, rAv1 = z4, rBv0 = z4, rBv1 = z4;
            if (nodeA < V_N) {
                rAv0 = *(const float4*)&g_R[(size_t)nodeA * 128 + rbase];
                rAv1 = *(const float4*)&g_R[(size_t)nodeA * 128 + rbase + 4];
            }
            if (nodeB < V_N) {
                rBv0 = *(const float4*)&g_R[(size_t)nodeB * 128 + rbase];
                rBv1 = *(const float4*)&g_R[(size_t)nodeB * 128 + rbase + 4];
            }
            const float rAx[4] = {rAv0.x, rAv0.z, rAv1.x, rAv1.z};
            const float rAy[4] = {rAv0.y, rAv0.w, rAv1.y, rAv1.w};
            const float rBx[4] = {rBv0.x, rBv0.z, rBv1.x, rBv1.z};
            const float rBy[4] = {rBv0.y, rBv0.w, rBv1.y, rBv1.w};
#pragma unroll
            for (int ni = 0; ni < 4; ni++) {
                const int c = wc * 32 + ni * 8 + 2 * q;
                float2 bb = *(const float2*)&bn1s[c];
                float2 b3v = *(const float2*)&bn3s[c];
                float t0 = fmaxf(d[mi][ni][0] + rAx[ni] + degA * b3v.x + bb.x, 0.f);
                float t1 = fmaxf(d[mi][ni][1] + rAy[ni] + degA * b3v.y + bb.y, 0.f);
                float t2 = fmaxf(d[mi][ni][2] + rBx[ni] + degB * b3v.x + bb.x, 0.f);
                float t3 = fmaxf(d[mi][ni][3] + rBy[ni] + degB * b3v.y + bb.y, 0.f);
                __nv_bfloat16 h0 = __float2bfloat16(t0), h1 = __float2bfloat16(t1);
                __nv_bfloat16 h2 = __float2bfloat16(t2), h3 = __float2bfloat16(t3);
                *(uint32_t*)(sm + N_THI + rA * WPITCH + c * 2) =
                    pack2(__bfloat162float(h0), __bfloat162float(h1));
                *(uint32_t*)(sm + N_THI + (rA + 8) * WPITCH + c * 2) =
                    pack2(__bfloat162float(h2), __bfloat162float(h3));
                *(uint32_t*)(sm + N_TLO + rA * WPITCH + c * 2) =
                    pack2(t0 - __bfloat162float(h0), t1 - __bfloat162float(h1));
                *(uint32_t*)(sm + N_TLO + (rA + 8) * WPITCH + c * 2) =
                    pack2(t2 - __bfloat162float(h2), t3 - __bfloat162float(h3));
            }
        }
        __syncthreads();

        // GEMM B: out = Thi@(W2hi+W2lo) + Tlo@W2hi + bn2 (Thi a-frags shared)
        zero_d(d);
        gemm_tile2<8, WPITCH, WPITCH, 0>(sbase + N_THI, sbase + N_W2H,
                                         sbase + N_W2L, wr, wc, lane, d);
        gemm_tile<8, WPITCH, WPITCH, 0>(sbase + N_TLO, sbase + N_W2H, wr, wc, lane, d);

#pragma unroll
        for (int mi = 0; mi < 2; mi++) {
            const int rA = wr * 32 + mi * 16 + g;
            const int nodeA = n0 + rA, nodeB = nodeA + 8;
#pragma unroll
            for (int ni = 0; ni < 4; ni++) {
                const int c = wc * 32 + ni * 8 + 2 * q;
                float2 bb = *(const float2*)&bn2s[c];
                if (nodeA < V_N)
                    *(float2*)&out[(size_t)nodeA * 128 + c] =
                        make_float2(d[mi][ni][0] + bb.x, d[mi][ni][1] + bb.y);
                if (nodeB < V_N)
                    *(float2*)&out[(size_t)nodeB * 128 + c] =
                        make_float2(d[mi][ni][2] + bb.x, d[mi][ni][3] + bb.y);
            }
        }
    }
}

// ---------------------------------------------------------------------------
extern "C" void kernel_launch(void* const* d_in, const int* in_sizes, int n_in,
                              void* d_out, int out_size) {
    const float* h   = (const float*)d_in[0];
    const int*   ei  = (const int*)d_in[1];   // int32 (JAX x64 disabled)
    const float* W1  = (const float*)d_in[2];
    const float* b1  = (const float*)d_in[3];
    const float* W2  = (const float*)d_in[4];
    const float* b2  = (const float*)d_in[5];
    const float* W3  = (const float*)d_in[6];
    const float* b3  = (const float*)d_in[7];
    const float* Wn1 = (const float*)d_in[8];
    const float* bn1 = (const float*)d_in[9];
    const float* Wn2 = (const float*)d_in[10];
    const float* bn2 = (const float*)d_in[11];
    float*       out = (float*)d_out;

    cudaFuncSetAttribute(k_prep, cudaFuncAttributeMaxDynamicSharedMemorySize, SM_PREP_TOTAL);
    cudaFuncSetAttribute(k_edge, cudaFuncAttributeMaxDynamicSharedMemorySize, SM_EDGE_TOTAL);
    cudaFuncSetAttribute(k_node, cudaFuncAttributeMaxDynamicSharedMemorySize, SM_NODE_TOTAL);

    k_prep<<<148, 512, SM_PREP_TOTAL>>>(h, W1, Wn1, b1, W3, b3);
    k_edge<<<296, 256, SM_EDGE_TOTAL>>>(ei, W2, b2);
    k_node<<<148, 512, SM_NODE_TOTAL>>>(bn1, Wn2, bn2, out);
}